// round 1
// baseline (speedup 1.0000x reference)
#include <cuda_runtime.h>
#include <math.h>

// Problem dims
#define BB   4
#define TT   2048
#define MT   8192      // B*T
#define CDIM 1024
#define HH   16
#define DH   64
#define FF   4096

// ---------------- scratch (no allocation allowed; device globals) -----------
__device__ float g_h   [MT * CDIM];   // LN output (reused for LN1 and LN2)
__device__ float g_q   [MT * CDIM];
__device__ float g_k   [MT * CDIM];
__device__ float g_v   [MT * CDIM];
__device__ float g_attn[MT * CDIM];
__device__ float g_x1  [MT * CDIM];
__device__ float g_mlp [MT * FF];

// ---------------- LayerNorm: one block per row, 256 threads -----------------
__global__ __launch_bounds__(256) void ln_kernel(
    const float4* __restrict__ x, const float4* __restrict__ g,
    const float4* __restrict__ be, float4* __restrict__ out)
{
    const int r = blockIdx.x;
    const int t = threadIdx.x;                 // 256 threads * float4 = 1024
    const float4 v = x[(size_t)r * (CDIM / 4) + t];
    float s  = v.x + v.y + v.z + v.w;
    float ss = v.x * v.x + v.y * v.y + v.z * v.z + v.w * v.w;
    #pragma unroll
    for (int o = 16; o > 0; o >>= 1) {
        s  += __shfl_down_sync(0xffffffffu, s,  o);
        ss += __shfl_down_sync(0xffffffffu, ss, o);
    }
    __shared__ float rs[8], rss[8];
    __shared__ float smu, sinv;
    const int w = t >> 5, lane = t & 31;
    if (lane == 0) { rs[w] = s; rss[w] = ss; }
    __syncthreads();
    if (t == 0) {
        float S = 0.f, SS = 0.f;
        #pragma unroll
        for (int i = 0; i < 8; i++) { S += rs[i]; SS += rss[i]; }
        const float mu  = S * (1.0f / CDIM);
        const float var = SS * (1.0f / CDIM) - mu * mu;
        smu = mu; sinv = rsqrtf(var + 1e-5f);
    }
    __syncthreads();
    const float mu = smu, inv = sinv;
    const float4 gv = g[t], bv = be[t];
    float4 o4;
    o4.x = (v.x - mu) * inv * gv.x + bv.x;
    o4.y = (v.y - mu) * inv * gv.y + bv.y;
    o4.z = (v.z - mu) * inv * gv.z + bv.z;
    o4.w = (v.w - mu) * inv * gv.w + bv.w;
    out[(size_t)r * (CDIM / 4) + t] = o4;
}

// ---------------- SGEMM: 128x128x8 tiles, 8x8 microtile, 256 threads --------
// EPI bit0: +bias (per output column)   bit2: relu   bit1: +residual (per elem)
// order: acc -> +bias -> relu -> +residual (matches the two fused epilogues)
template <int EPI>
__global__ __launch_bounds__(256) void sgemm_k(
    const float* __restrict__ A, const float* __restrict__ Bw,
    const float* __restrict__ bias, const float* __restrict__ res,
    float* __restrict__ C, int M, int N, int K)
{
    __shared__ float As[8][128];
    __shared__ float Bs[8][128];
    const int tid = threadIdx.x;
    const int bx = blockIdx.x, by = blockIdx.y;
    const int arow = tid >> 1,  acol = (tid & 1) << 2;   // A tile 128x8
    const int brow = tid >> 5,  bcol = (tid & 31) << 2;  // B tile 8x128
    const float* Ap = A  + (size_t)(by * 128 + arow) * K + acol;
    const float* Bp = Bw + (size_t)brow * N + bx * 128 + bcol;
    const int tx = tid & 15, ty = tid >> 4;

    float acc[8][8];
    #pragma unroll
    for (int i = 0; i < 8; i++)
        #pragma unroll
        for (int j = 0; j < 8; j++) acc[i][j] = 0.f;

    float4 a_reg = *(const float4*)Ap;
    float4 b_reg = *(const float4*)Bp;

    for (int k0 = 0; k0 < K; k0 += 8) {
        As[acol + 0][arow] = a_reg.x;
        As[acol + 1][arow] = a_reg.y;
        As[acol + 2][arow] = a_reg.z;
        As[acol + 3][arow] = a_reg.w;
        *(float4*)&Bs[brow][bcol] = b_reg;
        __syncthreads();
        if (k0 + 8 < K) {                       // register prefetch next tile
            a_reg = *(const float4*)(Ap + k0 + 8);
            b_reg = *(const float4*)(Bp + (size_t)(k0 + 8) * N);
        }
        #pragma unroll
        for (int kk = 0; kk < 8; kk++) {
            float af[8], bf[8];
            *(float4*)&af[0] = *(const float4*)&As[kk][ty * 8];
            *(float4*)&af[4] = *(const float4*)&As[kk][ty * 8 + 4];
            *(float4*)&bf[0] = *(const float4*)&Bs[kk][tx * 8];
            *(float4*)&bf[4] = *(const float4*)&Bs[kk][tx * 8 + 4];
            #pragma unroll
            for (int i = 0; i < 8; i++)
                #pragma unroll
                for (int j = 0; j < 8; j++)
                    acc[i][j] += af[i] * bf[j];
        }
        __syncthreads();
    }

    const int crow = by * 128 + ty * 8;
    const int ccol = bx * 128 + tx * 8;
    #pragma unroll
    for (int i = 0; i < 8; i++) {
        #pragma unroll
        for (int j = 0; j < 8; j += 4) {
            float4 v;
            v.x = acc[i][j + 0]; v.y = acc[i][j + 1];
            v.z = acc[i][j + 2]; v.w = acc[i][j + 3];
            const size_t idx = (size_t)(crow + i) * N + ccol + j;
            if (EPI & 1) {
                const float4 b4 = *(const float4*)(bias + ccol + j);
                v.x += b4.x; v.y += b4.y; v.z += b4.z; v.w += b4.w;
            }
            if (EPI & 4) {
                v.x = fmaxf(v.x, 0.f); v.y = fmaxf(v.y, 0.f);
                v.z = fmaxf(v.z, 0.f); v.w = fmaxf(v.w, 0.f);
            }
            if (EPI & 2) {
                const float4 r4 = *(const float4*)(res + idx);
                v.x += r4.x; v.y += r4.y; v.z += r4.z; v.w += r4.w;
            }
            *(float4*)(C + idx) = v;
        }
    }
}

// ---------------- Flash attention (causal), one thread per query row --------
// grid (T/64, H, B), 64 threads. q,o,s-chunk in registers; K/V tiles in smem.
__global__ __launch_bounds__(64) void flash_kernel(
    const float* __restrict__ Q, const float* __restrict__ K,
    const float* __restrict__ V, float* __restrict__ O)
{
    __shared__ float Ks[64][64];
    __shared__ float Vs[64][64];
    const int qt = blockIdx.x, h = blockIdx.y, b = blockIdx.z;
    const int t = threadIdx.x;
    const int row = qt * 64 + t;
    const float* qp = Q + ((size_t)(b * TT + row)) * CDIM + h * DH;

    float q[64];
    #pragma unroll
    for (int d = 0; d < 64; d += 4) {
        const float4 v4 = *(const float4*)(qp + d);
        q[d + 0] = v4.x * 0.125f;    // Dh^-0.5
        q[d + 1] = v4.y * 0.125f;
        q[d + 2] = v4.z * 0.125f;
        q[d + 3] = v4.w * 0.125f;
    }
    float o[64];
    #pragma unroll
    for (int d = 0; d < 64; d++) o[d] = 0.f;
    float m = -1e30f, l = 0.f;

    // coalesced K/V tile load mapping: 16 lanes cover one row, 4 rows per pass
    const int dcol = (t & 15) * 4;
    const int r0   = t >> 4;

    for (int kt = 0; kt <= qt; kt++) {
        const float* kbase = K + ((size_t)(b * TT + kt * 64)) * CDIM + h * DH;
        const float* vbase = V + ((size_t)(b * TT + kt * 64)) * CDIM + h * DH;
        #pragma unroll
        for (int rr = r0; rr < 64; rr += 4) {
            *(float4*)&Ks[rr][dcol] = *(const float4*)(kbase + (size_t)rr * CDIM + dcol);
            *(float4*)&Vs[rr][dcol] = *(const float4*)(vbase + (size_t)rr * CDIM + dcol);
        }
        __syncthreads();

        const int jmax = (kt == qt) ? (t + 1) : 64;   // causal: valid j count
        #pragma unroll
        for (int c = 0; c < 4; c++) {
            float s[16];
            float cm = -1e30f;
            #pragma unroll
            for (int jj = 0; jj < 16; jj++) {
                const int j = c * 16 + jj;
                const float4* kr = (const float4*)Ks[j];
                float acc = 0.f;
                #pragma unroll
                for (int d4 = 0; d4 < 16; d4++) {
                    const float4 kv = kr[d4];   // smem broadcast: conflict-free
                    acc += q[d4 * 4 + 0] * kv.x + q[d4 * 4 + 1] * kv.y
                         + q[d4 * 4 + 2] * kv.z + q[d4 * 4 + 3] * kv.w;
                }
                if (j >= jmax) acc = -1e30f;
                s[jj] = acc;
                cm = fmaxf(cm, acc);
            }
            if (cm > -1e29f) {                  // skip fully-masked chunks
                const float mnew = fmaxf(m, cm);
                const float corr = __expf(m - mnew);
                l *= corr;
                #pragma unroll
                for (int d = 0; d < 64; d++) o[d] *= corr;
                #pragma unroll
                for (int jj = 0; jj < 16; jj++) {
                    const float p = __expf(s[jj] - mnew);   // masked -> 0
                    l += p;
                    const float4* vr = (const float4*)Vs[c * 16 + jj];
                    #pragma unroll
                    for (int d4 = 0; d4 < 16; d4++) {
                        const float4 vv = vr[d4];
                        o[d4 * 4 + 0] += p * vv.x;
                        o[d4 * 4 + 1] += p * vv.y;
                        o[d4 * 4 + 2] += p * vv.z;
                        o[d4 * 4 + 3] += p * vv.w;
                    }
                }
                m = mnew;
            }
        }
        __syncthreads();
    }

    const float inv = 1.f / l;
    float* op = O + ((size_t)(b * TT + row)) * CDIM + h * DH;
    #pragma unroll
    for (int d = 0; d < 64; d += 4) {
        float4 v4;
        v4.x = o[d + 0] * inv; v4.y = o[d + 1] * inv;
        v4.z = o[d + 2] * inv; v4.w = o[d + 3] * inv;
        *(float4*)(op + d) = v4;
    }
}

// ---------------- launch --------------------------------------------------
extern "C" void kernel_launch(void* const* d_in, const int* in_sizes, int n_in,
                              void* d_out, int out_size)
{
    const float* x   = (const float*)d_in[0];
    const float* Wq  = (const float*)d_in[1];
    const float* Wk  = (const float*)d_in[2];
    const float* Wv  = (const float*)d_in[3];
    const float* Wo  = (const float*)d_in[4];
    const float* bo  = (const float*)d_in[5];
    const float* W1  = (const float*)d_in[6];
    const float* b1  = (const float*)d_in[7];
    const float* W2  = (const float*)d_in[8];
    const float* b2  = (const float*)d_in[9];
    const float* g1  = (const float*)d_in[10];
    const float* be1 = (const float*)d_in[11];
    const float* g2  = (const float*)d_in[12];
    const float* be2 = (const float*)d_in[13];
    float* out = (float*)d_out;

    float *h, *q, *k, *v, *attn, *x1, *mlp;
    cudaGetSymbolAddress((void**)&h,    g_h);
    cudaGetSymbolAddress((void**)&q,    g_q);
    cudaGetSymbolAddress((void**)&k,    g_k);
    cudaGetSymbolAddress((void**)&v,    g_v);
    cudaGetSymbolAddress((void**)&attn, g_attn);
    cudaGetSymbolAddress((void**)&x1,   g_x1);
    cudaGetSymbolAddress((void**)&mlp,  g_mlp);

    const dim3 gC(CDIM / 128, MT / 128);   // (8, 64)
    const dim3 gF(FF / 128,   MT / 128);   // (32, 64)

    // LN1
    ln_kernel<<<MT, 256>>>((const float4*)x, (const float4*)g1,
                           (const float4*)be1, (float4*)h);
    // QKV projections
    sgemm_k<0><<<gC, 256>>>(h, Wq, nullptr, nullptr, q, MT, CDIM, CDIM);
    sgemm_k<0><<<gC, 256>>>(h, Wk, nullptr, nullptr, k, MT, CDIM, CDIM);
    sgemm_k<0><<<gC, 256>>>(h, Wv, nullptr, nullptr, v, MT, CDIM, CDIM);
    // causal flash attention
    flash_kernel<<<dim3(TT / 64, HH, BB), 64>>>(q, k, v, attn);
    // x1 = x + attn @ Wo + bo
    sgemm_k<3><<<gC, 256>>>(attn, Wo, bo, x, x1, MT, CDIM, CDIM);
    // LN2
    ln_kernel<<<MT, 256>>>((const float4*)x1, (const float4*)g2,
                           (const float4*)be2, (float4*)h);
    // mlp = relu(h @ W1 + b1)
    sgemm_k<5><<<gF, 256>>>(h, W1, b1, nullptr, mlp, MT, FF, CDIM);
    // out = x1 + mlp @ W2 + b2
    sgemm_k<3><<<gC, 256>>>(mlp, W2, b2, x1, out, MT, CDIM, FF);
}

// round 5
// speedup vs baseline: 1.3819x; 1.3819x over previous
#include <cuda_runtime.h>
#include <cuda_bf16.h>
#include <cstdint>
#include <math.h>

// Problem dims
#define BB   4
#define TT   2048
#define MT   8192      // B*T
#define CDIM 1024
#define HH   16
#define DH   64
#define FF   4096

// ---------------- scratch (no allocation allowed; device globals) -----------
__device__ float g_h   [MT * CDIM];
__device__ float g_q   [MT * CDIM];
__device__ float g_k   [MT * CDIM];
__device__ float g_v   [MT * CDIM];
__device__ float g_attn[MT * CDIM];
__device__ float g_x1  [MT * CDIM];
__device__ float g_mlp [MT * FF];

// ---------------- LayerNorm: one block per row, 256 threads -----------------
__global__ __launch_bounds__(256) void ln_kernel(
    const float4* __restrict__ x, const float4* __restrict__ g,
    const float4* __restrict__ be, float4* __restrict__ out)
{
    const int r = blockIdx.x;
    const int t = threadIdx.x;
    const float4 v = x[(size_t)r * (CDIM / 4) + t];
    float s  = v.x + v.y + v.z + v.w;
    float ss = v.x * v.x + v.y * v.y + v.z * v.z + v.w * v.w;
    #pragma unroll
    for (int o = 16; o > 0; o >>= 1) {
        s  += __shfl_down_sync(0xffffffffu, s,  o);
        ss += __shfl_down_sync(0xffffffffu, ss, o);
    }
    __shared__ float rs[8], rss[8];
    __shared__ float smu, sinv;
    const int w = t >> 5, lane = t & 31;
    if (lane == 0) { rs[w] = s; rss[w] = ss; }
    __syncthreads();
    if (t == 0) {
        float S = 0.f, SS = 0.f;
        #pragma unroll
        for (int i = 0; i < 8; i++) { S += rs[i]; SS += rss[i]; }
        const float mu  = S * (1.0f / CDIM);
        const float var = SS * (1.0f / CDIM) - mu * mu;
        smu = mu; sinv = rsqrtf(var + 1e-5f);
    }
    __syncthreads();
    const float mu = smu, inv = sinv;
    const float4 gv = g[t], bv = be[t];
    float4 o4;
    o4.x = (v.x - mu) * inv * gv.x + bv.x;
    o4.y = (v.y - mu) * inv * gv.y + bv.y;
    o4.z = (v.z - mu) * inv * gv.z + bv.z;
    o4.w = (v.w - mu) * inv * gv.w + bv.w;
    out[(size_t)r * (CDIM / 4) + t] = o4;
}

// ---------------- bf16x3 tensor-core GEMM ----------------------------------
// C = A(fp32) @ B(fp32) with A,B split into bf16 hi+lo; products hi*hi +
// hi*lo + lo*hi accumulated in fp32 -> ~2^-17 operand error (rel_err ~1e-5).
// Block tile 128x128x32, 8 warps, warp tile 64x32, mma.sync m16n8k16 bf16.
// EPI bit0: +bias(col)  bit2: relu  bit1: +residual(elem); order bias->relu->res

#define LDMAT_X4(R0,R1,R2,R3,addr) \
    asm volatile("ldmatrix.sync.aligned.m8n8.x4.shared.b16 {%0,%1,%2,%3}, [%4];" \
        : "=r"(R0), "=r"(R1), "=r"(R2), "=r"(R3) : "r"(addr))

#define LDMAT_X4_T(R0,R1,R2,R3,addr) \
    asm volatile("ldmatrix.sync.aligned.m8n8.x4.trans.shared.b16 {%0,%1,%2,%3}, [%4];" \
        : "=r"(R0), "=r"(R1), "=r"(R2), "=r"(R3) : "r"(addr))

#define MMA16816(C, A0,A1,A2,A3, B0,B1) \
    asm volatile("mma.sync.aligned.m16n8k16.row.col.f32.bf16.bf16.f32 " \
        "{%0,%1,%2,%3},{%4,%5,%6,%7},{%8,%9},{%0,%1,%2,%3};" \
        : "+f"(C[0]), "+f"(C[1]), "+f"(C[2]), "+f"(C[3]) \
        : "r"(A0), "r"(A1), "r"(A2), "r"(A3), "r"(B0), "r"(B1))

__device__ __forceinline__ uint32_t smem_addr32(const void* p) {
    return (uint32_t)__cvta_generic_to_shared(p);
}

template <int EPI>
__global__ __launch_bounds__(256, 1) void mma_gemm(
    const float* __restrict__ A, const float* __restrict__ Bw,
    const float* __restrict__ bias, const float* __restrict__ res,
    float* __restrict__ C, int M, int N, int K)
{
    // A stored [m][k]: 128 rows, stride 40 bf16 (80B) -> ldmatrix conflict-free
    // B stored [k][n]:  32 rows, stride 136 bf16 (272B) -> conflict-free
    __shared__ __nv_bfloat16 As_hi[128][40];
    __shared__ __nv_bfloat16 As_lo[128][40];
    __shared__ __nv_bfloat16 Bs_hi[32][136];
    __shared__ __nv_bfloat16 Bs_lo[32][136];

    const int tid  = threadIdx.x;
    const int warp = tid >> 5, lane = tid & 31;
    const int wm = (warp & 1) * 64;      // warp m-offset: 2 warps along m
    const int wn = (warp >> 1) * 32;     // warp n-offset: 4 warps along n
    const int bm = blockIdx.y * 128, bn = blockIdx.x * 128;

    float c[4][4][4];                    // [mt][nt][frag]
    #pragma unroll
    for (int i = 0; i < 4; i++)
        #pragma unroll
        for (int j = 0; j < 4; j++)
            #pragma unroll
            for (int q = 0; q < 4; q++) c[i][j][q] = 0.f;

    // global tile load mapping
    const int ar  = tid >> 3;            // A: 32 rows/pass, 4 passes
    const int ak  = (tid & 7) * 4;       //    8 lanes cover 32 k floats
    const int br  = tid >> 5;            // B: 8 k-rows/pass, 4 passes
    const int bn4 = (tid & 31) * 4;      //    32 lanes cover 128 n floats

    for (int k0 = 0; k0 < K; k0 += 32) {
        // ---- load + split A tile [128 x 32] ----
        #pragma unroll
        for (int p = 0; p < 4; p++) {
            const int row = p * 32 + ar;
            const float4 v = *(const float4*)(A + (size_t)(bm + row) * K + k0 + ak);
            __nv_bfloat162 h0, h1, l0, l1;
            h0.x = __float2bfloat16_rn(v.x);
            h0.y = __float2bfloat16_rn(v.y);
            h1.x = __float2bfloat16_rn(v.z);
            h1.y = __float2bfloat16_rn(v.w);
            l0.x = __float2bfloat16_rn(v.x - __bfloat162float(h0.x));
            l0.y = __float2bfloat16_rn(v.y - __bfloat162float(h0.y));
            l1.x = __float2bfloat16_rn(v.z - __bfloat162float(h1.x));
            l1.y = __float2bfloat16_rn(v.w - __bfloat162float(h1.y));
            *(__nv_bfloat162*)&As_hi[row][ak]     = h0;
            *(__nv_bfloat162*)&As_hi[row][ak + 2] = h1;
            *(__nv_bfloat162*)&As_lo[row][ak]     = l0;
            *(__nv_bfloat162*)&As_lo[row][ak + 2] = l1;
        }
        // ---- load + split B tile [32 x 128] ----
        #pragma unroll
        for (int p = 0; p < 4; p++) {
            const int kr = p * 8 + br;
            const float4 v = *(const float4*)(Bw + (size_t)(k0 + kr) * N + bn + bn4);
            __nv_bfloat162 h0, h1, l0, l1;
            h0.x = __float2bfloat16_rn(v.x);
            h0.y = __float2bfloat16_rn(v.y);
            h1.x = __float2bfloat16_rn(v.z);
            h1.y = __float2bfloat16_rn(v.w);
            l0.x = __float2bfloat16_rn(v.x - __bfloat162float(h0.x));
            l0.y = __float2bfloat16_rn(v.y - __bfloat162float(h0.y));
            l1.x = __float2bfloat16_rn(v.z - __bfloat162float(h1.x));
            l1.y = __float2bfloat16_rn(v.w - __bfloat162float(h1.y));
            *(__nv_bfloat162*)&Bs_hi[kr][bn4]     = h0;
            *(__nv_bfloat162*)&Bs_hi[kr][bn4 + 2] = h1;
            *(__nv_bfloat162*)&Bs_lo[kr][bn4]     = l0;
            *(__nv_bfloat162*)&Bs_lo[kr][bn4 + 2] = l1;
        }
        __syncthreads();

        #pragma unroll
        for (int ks = 0; ks < 32; ks += 16) {
            uint32_t ah[4][4], al[4][4], bh[2][4], bl[2][4];
            // A fragments: 4 m16 tiles (non-trans ldmatrix)
            #pragma unroll
            for (int mt = 0; mt < 4; mt++) {
                const int r  = wm + mt * 16 + (lane & 15);
                const int cc = ks + 8 * (lane >> 4);
                LDMAT_X4(ah[mt][0], ah[mt][1], ah[mt][2], ah[mt][3],
                         smem_addr32(&As_hi[r][cc]));
                LDMAT_X4(al[mt][0], al[mt][1], al[mt][2], al[mt][3],
                         smem_addr32(&As_lo[r][cc]));
            }
            // B fragments: 2 n16 groups (trans ldmatrix)
            #pragma unroll
            for (int ng = 0; ng < 2; ng++) {
                const int r  = ks + (lane & 15);
                const int cc = wn + ng * 16 + 8 * (lane >> 4);
                LDMAT_X4_T(bh[ng][0], bh[ng][1], bh[ng][2], bh[ng][3],
                           smem_addr32(&Bs_hi[r][cc]));
                LDMAT_X4_T(bl[ng][0], bl[ng][1], bl[ng][2], bl[ng][3],
                           smem_addr32(&Bs_lo[r][cc]));
            }
            // mma: hi*hi + lo*hi + hi*lo
            #pragma unroll
            for (int mt = 0; mt < 4; mt++) {
                #pragma unroll
                for (int nt = 0; nt < 4; nt++) {
                    const int ng = nt >> 1, hf = (nt & 1) * 2;
                    const uint32_t b0h = bh[ng][hf], b1h = bh[ng][hf + 1];
                    const uint32_t b0l = bl[ng][hf], b1l = bl[ng][hf + 1];
                    MMA16816(c[mt][nt], ah[mt][0], ah[mt][1], ah[mt][2], ah[mt][3], b0h, b1h);
                    MMA16816(c[mt][nt], al[mt][0], al[mt][1], al[mt][2], al[mt][3], b0h, b1h);
                    MMA16816(c[mt][nt], ah[mt][0], ah[mt][1], ah[mt][2], ah[mt][3], b0l, b1l);
                }
            }
        }
        __syncthreads();
    }

    // ---- epilogue ----
    const int g  = lane >> 2;
    const int qq = (lane & 3) * 2;
    #pragma unroll
    for (int mt = 0; mt < 4; mt++) {
        #pragma unroll
        for (int nt = 0; nt < 4; nt++) {
            const int col = bn + wn + nt * 8 + qq;
            #pragma unroll
            for (int hrow = 0; hrow < 2; hrow++) {
                const int row = bm + wm + mt * 16 + g + hrow * 8;
                float2 v;
                v.x = c[mt][nt][hrow * 2 + 0];
                v.y = c[mt][nt][hrow * 2 + 1];
                const size_t idx = (size_t)row * N + col;
                if (EPI & 1) {
                    const float2 b2 = *(const float2*)(bias + col);
                    v.x += b2.x; v.y += b2.y;
                }
                if (EPI & 4) { v.x = fmaxf(v.x, 0.f); v.y = fmaxf(v.y, 0.f); }
                if (EPI & 2) {
                    const float2 r2 = *(const float2*)(res + idx);
                    v.x += r2.x; v.y += r2.y;
                }
                *(float2*)(C + idx) = v;
            }
        }
    }
}

// ---------------- Flash attention (causal), one thread per query row --------
__global__ __launch_bounds__(64) void flash_kernel(
    const float* __restrict__ Q, const float* __restrict__ K,
    const float* __restrict__ V, float* __restrict__ O)
{
    __shared__ float Ks[64][64];
    __shared__ float Vs[64][64];
    const int qt = blockIdx.x, h = blockIdx.y, b = blockIdx.z;
    const int t = threadIdx.x;
    const int row = qt * 64 + t;
    const float* qp = Q + ((size_t)(b * TT + row)) * CDIM + h * DH;

    float q[64];
    #pragma unroll
    for (int d = 0; d < 64; d += 4) {
        const float4 v4 = *(const float4*)(qp + d);
        q[d + 0] = v4.x * 0.125f;
        q[d + 1] = v4.y * 0.125f;
        q[d + 2] = v4.z * 0.125f;
        q[d + 3] = v4.w * 0.125f;
    }
    float o[64];
    #pragma unroll
    for (int d = 0; d < 64; d++) o[d] = 0.f;
    float m = -1e30f, l = 0.f;

    const int dcol = (t & 15) * 4;
    const int r0   = t >> 4;

    for (int kt = 0; kt <= qt; kt++) {
        const float* kbase = K + ((size_t)(b * TT + kt * 64)) * CDIM + h * DH;
        const float* vbase = V + ((size_t)(b * TT + kt * 64)) * CDIM + h * DH;
        #pragma unroll
        for (int rr = r0; rr < 64; rr += 4) {
            *(float4*)&Ks[rr][dcol] = *(const float4*)(kbase + (size_t)rr * CDIM + dcol);
            *(float4*)&Vs[rr][dcol] = *(const float4*)(vbase + (size_t)rr * CDIM + dcol);
        }
        __syncthreads();

        const int jmax = (kt == qt) ? (t + 1) : 64;
        #pragma unroll
        for (int ci = 0; ci < 4; ci++) {
            float s[16];
            float cm = -1e30f;
            #pragma unroll
            for (int jj = 0; jj < 16; jj++) {
                const int j = ci * 16 + jj;
                const float4* kr = (const float4*)Ks[j];
                float acc = 0.f;
                #pragma unroll
                for (int d4 = 0; d4 < 16; d4++) {
                    const float4 kv = kr[d4];
                    acc += q[d4 * 4 + 0] * kv.x + q[d4 * 4 + 1] * kv.y
                         + q[d4 * 4 + 2] * kv.z + q[d4 * 4 + 3] * kv.w;
                }
                if (j >= jmax) acc = -1e30f;
                s[jj] = acc;
                cm = fmaxf(cm, acc);
            }
            if (cm > -1e29f) {
                const float mnew = fmaxf(m, cm);
                const float corr = __expf(m - mnew);
                l *= corr;
                #pragma unroll
                for (int d = 0; d < 64; d++) o[d] *= corr;
                #pragma unroll
                for (int jj = 0; jj < 16; jj++) {
                    const float p = __expf(s[jj] - mnew);
                    l += p;
                    const float4* vr = (const float4*)Vs[ci * 16 + jj];
                    #pragma unroll
                    for (int d4 = 0; d4 < 16; d4++) {
                        const float4 vv = vr[d4];
                        o[d4 * 4 + 0] += p * vv.x;
                        o[d4 * 4 + 1] += p * vv.y;
                        o[d4 * 4 + 2] += p * vv.z;
                        o[d4 * 4 + 3] += p * vv.w;
                    }
                }
                m = mnew;
            }
        }
        __syncthreads();
    }

    const float inv = 1.f / l;
    float* op = O + ((size_t)(b * TT + row)) * CDIM + h * DH;
    #pragma unroll
    for (int d = 0; d < 64; d += 4) {
        float4 v4;
        v4.x = o[d + 0] * inv; v4.y = o[d + 1] * inv;
        v4.z = o[d + 2] * inv; v4.w = o[d + 3] * inv;
        *(float4*)(op + d) = v4;
    }
}

// ---------------- launch --------------------------------------------------
extern "C" void kernel_launch(void* const* d_in, const int* in_sizes, int n_in,
                              void* d_out, int out_size)
{
    const float* x   = (const float*)d_in[0];
    const float* Wq  = (const float*)d_in[1];
    const float* Wk  = (const float*)d_in[2];
    const float* Wv  = (const float*)d_in[3];
    const float* Wo  = (const float*)d_in[4];
    const float* bo  = (const float*)d_in[5];
    const float* W1  = (const float*)d_in[6];
    const float* b1  = (const float*)d_in[7];
    const float* W2  = (const float*)d_in[8];
    const float* b2  = (const float*)d_in[9];
    const float* g1  = (const float*)d_in[10];
    const float* be1 = (const float*)d_in[11];
    const float* g2  = (const float*)d_in[12];
    const float* be2 = (const float*)d_in[13];
    float* out = (float*)d_out;

    float *h, *q, *k, *v, *attn, *x1, *mlp;
    cudaGetSymbolAddress((void**)&h,    g_h);
    cudaGetSymbolAddress((void**)&q,    g_q);
    cudaGetSymbolAddress((void**)&k,    g_k);
    cudaGetSymbolAddress((void**)&v,    g_v);
    cudaGetSymbolAddress((void**)&attn, g_attn);
    cudaGetSymbolAddress((void**)&x1,   g_x1);
    cudaGetSymbolAddress((void**)&mlp,  g_mlp);

    const dim3 gC(CDIM / 128, MT / 128);   // (8, 64)
    const dim3 gF(FF / 128,   MT / 128);   // (32, 64)

    // LN1
    ln_kernel<<<MT, 256>>>((const float4*)x, (const float4*)g1,
                           (const float4*)be1, (float4*)h);
    // QKV projections
    mma_gemm<0><<<gC, 256>>>(h, Wq, nullptr, nullptr, q, MT, CDIM, CDIM);
    mma_gemm<0><<<gC, 256>>>(h, Wk, nullptr, nullptr, k, MT, CDIM, CDIM);
    mma_gemm<0><<<gC, 256>>>(h, Wv, nullptr, nullptr, v, MT, CDIM, CDIM);
    // causal flash attention
    flash_kernel<<<dim3(TT / 64, HH, BB), 64>>>(q, k, v, attn);
    // x1 = x + attn @ Wo + bo
    mma_gemm<3><<<gC, 256>>>(attn, Wo, bo, x, x1, MT, CDIM, CDIM);
    // LN2
    ln_kernel<<<MT, 256>>>((const float4*)x1, (const float4*)g2,
                           (const float4*)be2, (float4*)h);
    // mlp = relu(h @ W1 + b1)
    mma_gemm<5><<<gF, 256>>>(h, W1, b1, nullptr, mlp, MT, FF, CDIM);
    // out = x1 + mlp @ W2 + b2
    mma_gemm<3><<<gC, 256>>>(mlp, W2, b2, x1, out, MT, CDIM, FF);
}

// round 7
// speedup vs baseline: 1.5346x; 1.1105x over previous
#include <cuda_runtime.h>
#include <cuda_bf16.h>
#include <cstdint>
#include <math.h>

// Problem dims
#define BB   4
#define TT   2048
#define MT   8192      // B*T
#define CDIM 1024
#define HH   16
#define DH   64
#define FF   4096
#define QKVN 3072

// ---------------- scratch (device globals; no allocation allowed) ----------
__device__ __nv_bfloat16 g_h_hi [MT * CDIM];
__device__ __nv_bfloat16 g_h_lo [MT * CDIM];
__device__ float         g_qkv  [(size_t)MT * QKVN];
__device__ __nv_bfloat16 g_at_hi[MT * CDIM];
__device__ __nv_bfloat16 g_at_lo[MT * CDIM];
__device__ float         g_x1   [MT * CDIM];
__device__ __nv_bfloat16 g_ml_hi[(size_t)MT * FF];
__device__ __nv_bfloat16 g_ml_lo[(size_t)MT * FF];
// pre-split weights
__device__ __nv_bfloat16 g_wqkv_hi[CDIM * QKVN];
__device__ __nv_bfloat16 g_wqkv_lo[CDIM * QKVN];
__device__ __nv_bfloat16 g_wo_hi [CDIM * CDIM];
__device__ __nv_bfloat16 g_wo_lo [CDIM * CDIM];
__device__ __nv_bfloat16 g_w1_hi [CDIM * FF];
__device__ __nv_bfloat16 g_w1_lo [CDIM * FF];
__device__ __nv_bfloat16 g_w2_hi [FF * CDIM];
__device__ __nv_bfloat16 g_w2_lo [FF * CDIM];

// ---------------- helpers ---------------------------------------------------
__device__ __forceinline__ uint32_t smem_addr32(const void* p) {
    return (uint32_t)__cvta_generic_to_shared(p);
}
__device__ __forceinline__ void cp16(void* smem, const void* g) {
    uint32_t s = smem_addr32(smem);
    asm volatile("cp.async.cg.shared.global [%0], [%1], 16;" :: "r"(s), "l"(g));
}
#define CP_COMMIT() asm volatile("cp.async.commit_group;")
#define CP_WAIT(n)  asm volatile("cp.async.wait_group %0;" :: "n"(n))

__device__ __forceinline__ void split2(float a, float b,
    __nv_bfloat162& hi, __nv_bfloat162& lo)
{
    hi.x = __float2bfloat16_rn(a);
    hi.y = __float2bfloat16_rn(b);
    lo.x = __float2bfloat16_rn(a - __bfloat162float(hi.x));
    lo.y = __float2bfloat16_rn(b - __bfloat162float(hi.y));
}

// ---------------- split kernels --------------------------------------------
// contiguous: in [n] fp32 -> hi/lo bf16
__global__ __launch_bounds__(256) void split_kernel(
    const float4* __restrict__ in, __nv_bfloat162* __restrict__ hi,
    __nv_bfloat162* __restrict__ lo, int n4)
{
    const int i = blockIdx.x * 256 + threadIdx.x;
    if (i >= n4) return;
    const float4 v = in[i];
    __nv_bfloat162 h0, h1, l0, l1;
    split2(v.x, v.y, h0, l0);
    split2(v.z, v.w, h1, l1);
    hi[i * 2]     = h0; hi[i * 2 + 1] = h1;
    lo[i * 2]     = l0; lo[i * 2 + 1] = l1;
}

// pack Wq/Wk/Wv [1024][1024] into wqkv [1024][3072] at column offset
__global__ __launch_bounds__(256) void split_pack_kernel(
    const float4* __restrict__ in, __nv_bfloat16* __restrict__ hi,
    __nv_bfloat16* __restrict__ lo, int coloff)
{
    const int i = blockIdx.x * 256 + threadIdx.x;   // over CDIM*CDIM/4
    if (i >= CDIM * CDIM / 4) return;
    const int r = i >> 8;            // row (1024 cols / 4 = 256 float4 per row)
    const int c = (i & 255) * 4;
    const float4 v = in[i];
    __nv_bfloat162 h0, h1, l0, l1;
    split2(v.x, v.y, h0, l0);
    split2(v.z, v.w, h1, l1);
    const size_t o = (size_t)r * QKVN + coloff + c;
    *(__nv_bfloat162*)(hi + o)     = h0;
    *(__nv_bfloat162*)(hi + o + 2) = h1;
    *(__nv_bfloat162*)(lo + o)     = l0;
    *(__nv_bfloat162*)(lo + o + 2) = l1;
}

// ---------------- LayerNorm: emits bf16 hi/lo -------------------------------
__global__ __launch_bounds__(256) void ln_kernel(
    const float4* __restrict__ x, const float4* __restrict__ g,
    const float4* __restrict__ be,
    __nv_bfloat16* __restrict__ hi, __nv_bfloat16* __restrict__ lo)
{
    const int r = blockIdx.x;
    const int t = threadIdx.x;
    const float4 v = x[(size_t)r * (CDIM / 4) + t];
    float s  = v.x + v.y + v.z + v.w;
    float ss = v.x * v.x + v.y * v.y + v.z * v.z + v.w * v.w;
    #pragma unroll
    for (int o = 16; o > 0; o >>= 1) {
        s  += __shfl_down_sync(0xffffffffu, s,  o);
        ss += __shfl_down_sync(0xffffffffu, ss, o);
    }
    __shared__ float rs[8], rss[8];
    __shared__ float smu, sinv;
    const int w = t >> 5, lane = t & 31;
    if (lane == 0) { rs[w] = s; rss[w] = ss; }
    __syncthreads();
    if (t == 0) {
        float S = 0.f, SS = 0.f;
        #pragma unroll
        for (int i = 0; i < 8; i++) { S += rs[i]; SS += rss[i]; }
        const float mu  = S * (1.0f / CDIM);
        const float var = SS * (1.0f / CDIM) - mu * mu;
        smu = mu; sinv = rsqrtf(var + 1e-5f);
    }
    __syncthreads();
    const float mu = smu, inv = sinv;
    const float4 gv = g[t], bv = be[t];
    float a0 = (v.x - mu) * inv * gv.x + bv.x;
    float a1 = (v.y - mu) * inv * gv.y + bv.y;
    float a2 = (v.z - mu) * inv * gv.z + bv.z;
    float a3 = (v.w - mu) * inv * gv.w + bv.w;
    __nv_bfloat162 h0, h1, l0, l1;
    split2(a0, a1, h0, l0);
    split2(a2, a3, h1, l1);
    const size_t o = (size_t)r * CDIM + t * 4;
    *(__nv_bfloat162*)(hi + o)     = h0;
    *(__nv_bfloat162*)(hi + o + 2) = h1;
    *(__nv_bfloat162*)(lo + o)     = l0;
    *(__nv_bfloat162*)(lo + o + 2) = l1;
}

// ---------------- pipelined bf16x3 tensor-core GEMM -------------------------
// Inputs pre-split bf16 hi/lo. Block tile 128x128x32, double-buffered cp.async.
// EPI bit0:+bias  bit1:+residual  bit2:relu  bit3:split-bf16 output
// order: bias -> relu -> residual

#define LDMAT_X4(R0,R1,R2,R3,addr) \
    asm volatile("ldmatrix.sync.aligned.m8n8.x4.shared.b16 {%0,%1,%2,%3}, [%4];" \
        : "=r"(R0), "=r"(R1), "=r"(R2), "=r"(R3) : "r"(addr))
#define LDMAT_X4_T(R0,R1,R2,R3,addr) \
    asm volatile("ldmatrix.sync.aligned.m8n8.x4.trans.shared.b16 {%0,%1,%2,%3}, [%4];" \
        : "=r"(R0), "=r"(R1), "=r"(R2), "=r"(R3) : "r"(addr))
#define MMA16816(C, A0,A1,A2,A3, B0,B1) \
    asm volatile("mma.sync.aligned.m16n8k16.row.col.f32.bf16.bf16.f32 " \
        "{%0,%1,%2,%3},{%4,%5,%6,%7},{%8,%9},{%0,%1,%2,%3};" \
        : "+f"(C[0]), "+f"(C[1]), "+f"(C[2]), "+f"(C[3]) \
        : "r"(A0), "r"(A1), "r"(A2), "r"(A3), "r"(B0), "r"(B1))

#define A_ST 5120   // elements per A stage: 128*40
#define B_ST 4352   // elements per B stage: 32*136
#define GEMM_SMEM ((4 * A_ST + 4 * B_ST) * 2)   // 75776 bytes

template <int EPI>
__global__ __launch_bounds__(256, 1) void mma_gemm(
    const __nv_bfloat16* __restrict__ Ah, const __nv_bfloat16* __restrict__ Al,
    const __nv_bfloat16* __restrict__ Bh, const __nv_bfloat16* __restrict__ Bl,
    const float* __restrict__ bias, const float* __restrict__ res,
    float* __restrict__ C, __nv_bfloat16* __restrict__ Ch,
    __nv_bfloat16* __restrict__ Cl, int M, int N, int K)
{
    extern __shared__ char dynsmem[];
    __nv_bfloat16* as_hi = (__nv_bfloat16*)dynsmem;          // [2][128][40]
    __nv_bfloat16* as_lo = as_hi + 2 * A_ST;
    __nv_bfloat16* bs_hi = as_hi + 4 * A_ST;                 // [2][32][136]
    __nv_bfloat16* bs_lo = bs_hi + 2 * B_ST;

    const int tid  = threadIdx.x;
    const int warp = tid >> 5, lane = tid & 31;
    const int wm = (warp & 1) * 64;
    const int wn = (warp >> 1) * 32;
    const int bm = blockIdx.y * 128, bn = blockIdx.x * 128;

    float c[4][4][4];
    #pragma unroll
    for (int i = 0; i < 4; i++)
        #pragma unroll
        for (int j = 0; j < 4; j++)
            #pragma unroll
            for (int q = 0; q < 4; q++) c[i][j][q] = 0.f;

    // cp.async load mappings
    const int a_r = tid >> 2, a_c = (tid & 3) * 8;    // 64 rows/pass, 2 passes
    const int b_r = tid >> 4, b_c = (tid & 15) * 8;   // 16 rows/pass, 2 passes

    auto load_stage = [&](int s, int k0) {
        #pragma unroll
        for (int p = 0; p < 2; p++) {
            const int row = p * 64 + a_r;
            const size_t go = (size_t)(bm + row) * K + k0 + a_c;
            const int so = s * A_ST + row * 40 + a_c;
            cp16(as_hi + so, Ah + go);
            cp16(as_lo + so, Al + go);
        }
        #pragma unroll
        for (int p = 0; p < 2; p++) {
            const int row = p * 16 + b_r;
            const size_t go = (size_t)(k0 + row) * N + bn + b_c;
            const int so = s * B_ST + row * 136 + b_c;
            cp16(bs_hi + so, Bh + go);
            cp16(bs_lo + so, Bl + go);
        }
    };

    const int nk = K / 32;
    load_stage(0, 0);
    CP_COMMIT();

    for (int ki = 0; ki < nk; ki++) {
        const int s = ki & 1;
        if (ki + 1 < nk) {
            load_stage(s ^ 1, (ki + 1) * 32);
            CP_COMMIT();
            CP_WAIT(1);
        } else {
            CP_WAIT(0);
        }
        __syncthreads();

        const uint32_t ah_b = smem_addr32(as_hi + s * A_ST);
        const uint32_t al_b = smem_addr32(as_lo + s * A_ST);
        const uint32_t bh_b = smem_addr32(bs_hi + s * B_ST);
        const uint32_t bl_b = smem_addr32(bs_lo + s * B_ST);

        #pragma unroll
        for (int ks = 0; ks < 32; ks += 16) {
            uint32_t ah[4][4], al[4][4], bh[2][4], bl[2][4];
            #pragma unroll
            for (int mt = 0; mt < 4; mt++) {
                const int r  = wm + mt * 16 + (lane & 15);
                const int cc = ks + 8 * (lane >> 4);
                const uint32_t off = (uint32_t)(r * 40 + cc) * 2;
                LDMAT_X4(ah[mt][0], ah[mt][1], ah[mt][2], ah[mt][3], ah_b + off);
                LDMAT_X4(al[mt][0], al[mt][1], al[mt][2], al[mt][3], al_b + off);
            }
            #pragma unroll
            for (int ng = 0; ng < 2; ng++) {
                const int r  = ks + (lane & 15);
                const int cc = wn + ng * 16 + 8 * (lane >> 4);
                const uint32_t off = (uint32_t)(r * 136 + cc) * 2;
                LDMAT_X4_T(bh[ng][0], bh[ng][1], bh[ng][2], bh[ng][3], bh_b + off);
                LDMAT_X4_T(bl[ng][0], bl[ng][1], bl[ng][2], bl[ng][3], bl_b + off);
            }
            #pragma unroll
            for (int mt = 0; mt < 4; mt++) {
                #pragma unroll
                for (int nt = 0; nt < 4; nt++) {
                    const int ng = nt >> 1, hf = (nt & 1) * 2;
                    const uint32_t b0h = bh[ng][hf], b1h = bh[ng][hf + 1];
                    const uint32_t b0l = bl[ng][hf], b1l = bl[ng][hf + 1];
                    MMA16816(c[mt][nt], ah[mt][0], ah[mt][1], ah[mt][2], ah[mt][3], b0h, b1h);
                    MMA16816(c[mt][nt], al[mt][0], al[mt][1], al[mt][2], al[mt][3], b0h, b1h);
                    MMA16816(c[mt][nt], ah[mt][0], ah[mt][1], ah[mt][2], ah[mt][3], b0l, b1l);
                }
            }
        }
        __syncthreads();
    }

    // ---- epilogue ----
    const int gg = lane >> 2;
    const int qq = (lane & 3) * 2;
    #pragma unroll
    for (int mt = 0; mt < 4; mt++) {
        #pragma unroll
        for (int nt = 0; nt < 4; nt++) {
            const int col = bn + wn + nt * 8 + qq;
            #pragma unroll
            for (int hrow = 0; hrow < 2; hrow++) {
                const int row = bm + wm + mt * 16 + gg + hrow * 8;
                float2 v;
                v.x = c[mt][nt][hrow * 2 + 0];
                v.y = c[mt][nt][hrow * 2 + 1];
                const size_t idx = (size_t)row * N + col;
                if (EPI & 1) {
                    const float2 b2 = *(const float2*)(bias + col);
                    v.x += b2.x; v.y += b2.y;
                }
                if (EPI & 4) { v.x = fmaxf(v.x, 0.f); v.y = fmaxf(v.y, 0.f); }
                if (EPI & 2) {
                    const float2 r2 = *(const float2*)(res + idx);
                    v.x += r2.x; v.y += r2.y;
                }
                if (EPI & 8) {
                    __nv_bfloat162 h2, l2;
                    split2(v.x, v.y, h2, l2);
                    *(__nv_bfloat162*)(Ch + idx) = h2;
                    *(__nv_bfloat162*)(Cl + idx) = l2;
                } else {
                    *(float2*)(C + idx) = v;
                }
            }
        }
    }
}

// ---------------- Flash attention (causal), one thread per query row --------
// reads packed qkv [MT][3072] (q|k|v), writes attn as bf16 hi/lo
__global__ __launch_bounds__(64) void flash_kernel(
    const float* __restrict__ QKV,
    __nv_bfloat16* __restrict__ Ohi, __nv_bfloat16* __restrict__ Olo)
{
    __shared__ float Ks[64][64];
    __shared__ float Vs[64][64];
    const int qt = blockIdx.x, h = blockIdx.y, bz = blockIdx.z;
    const int t = threadIdx.x;
    const int row = qt * 64 + t;
    const float* qp = QKV + (size_t)(bz * TT + row) * QKVN + h * DH;

    float q[64];
    #pragma unroll
    for (int d = 0; d < 64; d += 4) {
        const float4 v4 = *(const float4*)(qp + d);
        q[d + 0] = v4.x * 0.125f;
        q[d + 1] = v4.y * 0.125f;
        q[d + 2] = v4.z * 0.125f;
        q[d + 3] = v4.w * 0.125f;
    }
    float o[64];
    #pragma unroll
    for (int d = 0; d < 64; d++) o[d] = 0.f;
    float m = -1e30f, l = 0.f;

    const int dcol = (t & 15) * 4;
    const int r0   = t >> 4;

    for (int kt = 0; kt <= qt; kt++) {
        const float* kbase = QKV + (size_t)(bz * TT + kt * 64) * QKVN + CDIM + h * DH;
        const float* vbase = kbase + CDIM;
        #pragma unroll
        for (int rr = r0; rr < 64; rr += 4) {
            *(float4*)&Ks[rr][dcol] = *(const float4*)(kbase + (size_t)rr * QKVN + dcol);
            *(float4*)&Vs[rr][dcol] = *(const float4*)(vbase + (size_t)rr * QKVN + dcol);
        }
        __syncthreads();

        const int jmax = (kt == qt) ? (t + 1) : 64;
        #pragma unroll
        for (int ci = 0; ci < 4; ci++) {
            float s[16];
            float cm = -1e30f;
            #pragma unroll
            for (int jj = 0; jj < 16; jj++) {
                const int j = ci * 16 + jj;
                const float4* kr = (const float4*)Ks[j];
                float acc = 0.f;
                #pragma unroll
                for (int d4 = 0; d4 < 16; d4++) {
                    const float4 kv = kr[d4];
                    acc += q[d4 * 4 + 0] * kv.x + q[d4 * 4 + 1] * kv.y
                         + q[d4 * 4 + 2] * kv.z + q[d4 * 4 + 3] * kv.w;
                }
                if (j >= jmax) acc = -1e30f;
                s[jj] = acc;
                cm = fmaxf(cm, acc);
            }
            if (cm > -1e29f) {
                const float mnew = fmaxf(m, cm);
                const float corr = __expf(m - mnew);
                l *= corr;
                #pragma unroll
                for (int d = 0; d < 64; d++) o[d] *= corr;
                #pragma unroll
                for (int jj = 0; jj < 16; jj++) {
                    const float p = __expf(s[jj] - mnew);
                    l += p;
                    const float4* vr = (const float4*)Vs[ci * 16 + jj];
                    #pragma unroll
                    for (int d4 = 0; d4 < 16; d4++) {
                        const float4 vv = vr[d4];
                        o[d4 * 4 + 0] += p * vv.x;
                        o[d4 * 4 + 1] += p * vv.y;
                        o[d4 * 4 + 2] += p * vv.z;
                        o[d4 * 4 + 3] += p * vv.w;
                    }
                }
                m = mnew;
            }
        }
        __syncthreads();
    }

    const float inv = 1.f / l;
    const size_t obase = (size_t)(bz * TT + row) * CDIM + h * DH;
    #pragma unroll
    for (int d = 0; d < 64; d += 2) {
        __nv_bfloat162 h2, l2;
        split2(o[d] * inv, o[d + 1] * inv, h2, l2);
        *(__nv_bfloat162*)(Ohi + obase + d) = h2;
        *(__nv_bfloat162*)(Olo + obase + d) = l2;
    }
}

// ---------------- launch ----------------------------------------------------
extern "C" void kernel_launch(void* const* d_in, const int* in_sizes, int n_in,
                              void* d_out, int out_size)
{
    const float* x   = (const float*)d_in[0];
    const float* Wq  = (const float*)d_in[1];
    const float* Wk  = (const float*)d_in[2];
    const float* Wv  = (const float*)d_in[3];
    const float* Wo  = (const float*)d_in[4];
    const float* bo  = (const float*)d_in[5];
    const float* W1  = (const float*)d_in[6];
    const float* b1  = (const float*)d_in[7];
    const float* W2  = (const float*)d_in[8];
    const float* b2  = (const float*)d_in[9];
    const float* g1  = (const float*)d_in[10];
    const float* be1 = (const float*)d_in[11];
    const float* g2  = (const float*)d_in[12];
    const float* be2 = (const float*)d_in[13];
    float* out = (float*)d_out;

    __nv_bfloat16 *h_hi, *h_lo, *at_hi, *at_lo, *ml_hi, *ml_lo;
    __nv_bfloat16 *wqkv_hi, *wqkv_lo, *wo_hi, *wo_lo, *w1_hi, *w1_lo, *w2_hi, *w2_lo;
    float *qkv, *x1;
    cudaGetSymbolAddress((void**)&h_hi,  g_h_hi);
    cudaGetSymbolAddress((void**)&h_lo,  g_h_lo);
    cudaGetSymbolAddress((void**)&qkv,   g_qkv);
    cudaGetSymbolAddress((void**)&at_hi, g_at_hi);
    cudaGetSymbolAddress((void**)&at_lo, g_at_lo);
    cudaGetSymbolAddress((void**)&x1,    g_x1);
    cudaGetSymbolAddress((void**)&ml_hi, g_ml_hi);
    cudaGetSymbolAddress((void**)&ml_lo, g_ml_lo);
    cudaGetSymbolAddress((void**)&wqkv_hi, g_wqkv_hi);
    cudaGetSymbolAddress((void**)&wqkv_lo, g_wqkv_lo);
    cudaGetSymbolAddress((void**)&wo_hi, g_wo_hi);
    cudaGetSymbolAddress((void**)&wo_lo, g_wo_lo);
    cudaGetSymbolAddress((void**)&w1_hi, g_w1_hi);
    cudaGetSymbolAddress((void**)&w1_lo, g_w1_lo);
    cudaGetSymbolAddress((void**)&w2_hi, g_w2_hi);
    cudaGetSymbolAddress((void**)&w2_lo, g_w2_lo);

    cudaFuncSetAttribute(mma_gemm<0>,  cudaFuncAttributeMaxDynamicSharedMemorySize, GEMM_SMEM);
    cudaFuncSetAttribute(mma_gemm<3>,  cudaFuncAttributeMaxDynamicSharedMemorySize, GEMM_SMEM);
    cudaFuncSetAttribute(mma_gemm<13>, cudaFuncAttributeMaxDynamicSharedMemorySize, GEMM_SMEM);

    // ---- pre-split weights ----
    const int nW = CDIM * CDIM / 4;       // 262144
    split_pack_kernel<<<(nW + 255) / 256, 256>>>((const float4*)Wq, wqkv_hi, wqkv_lo, 0);
    split_pack_kernel<<<(nW + 255) / 256, 256>>>((const float4*)Wk, wqkv_hi, wqkv_lo, 1024);
    split_pack_kernel<<<(nW + 255) / 256, 256>>>((const float4*)Wv, wqkv_hi, wqkv_lo, 2048);
    split_kernel<<<(nW + 255) / 256, 256>>>((const float4*)Wo,
        (__nv_bfloat162*)wo_hi, (__nv_bfloat162*)wo_lo, nW);
    const int nW1 = CDIM * FF / 4;
    split_kernel<<<(nW1 + 255) / 256, 256>>>((const float4*)W1,
        (__nv_bfloat162*)w1_hi, (__nv_bfloat162*)w1_lo, nW1);
    split_kernel<<<(nW1 + 255) / 256, 256>>>((const float4*)W2,
        (__nv_bfloat162*)w2_hi, (__nv_bfloat162*)w2_lo, nW1);

    const dim3 gQKV(QKVN / 128, MT / 128);   // (24, 64)
    const dim3 gC(CDIM / 128, MT / 128);     // (8, 64)
    const dim3 gF(FF / 128, MT / 128);       // (32, 64)

    // LN1 -> split h
    ln_kernel<<<MT, 256>>>((const float4*)x, (const float4*)g1,
                           (const float4*)be1, h_hi, h_lo);
    // fused QKV projection
    mma_gemm<0><<<gQKV, 256, GEMM_SMEM>>>(h_hi, h_lo, wqkv_hi, wqkv_lo,
        nullptr, nullptr, qkv, nullptr, nullptr, MT, QKVN, CDIM);
    // causal flash attention -> split attn
    flash_kernel<<<dim3(TT / 64, HH, BB), 64>>>(qkv, at_hi, at_lo);
    // x1 = x + attn @ Wo + bo
    mma_gemm<3><<<gC, 256, GEMM_SMEM>>>(at_hi, at_lo, wo_hi, wo_lo,
        bo, x, x1, nullptr, nullptr, MT, CDIM, CDIM);
    // LN2 -> split h
    ln_kernel<<<MT, 256>>>((const float4*)x1, (const float4*)g2,
                           (const float4*)be2, h_hi, h_lo);
    // mlp = relu(h @ W1 + b1) -> split
    mma_gemm<13><<<gF, 256, GEMM_SMEM>>>(h_hi, h_lo, w1_hi, w1_lo,
        b1, nullptr, nullptr, ml_hi, ml_lo, MT, FF, CDIM);
    // out = x1 + mlp @ W2 + b2
    mma_gemm<3><<<gC, 256, GEMM_SMEM>>>(ml_hi, ml_lo, w2_hi, w2_lo,
        b2, x1, out, nullptr, nullptr, MT, CDIM, FF);
}

// round 8
// speedup vs baseline: 2.9813x; 1.9426x over previous
#include <cuda_runtime.h>
#include <cuda_bf16.h>
#include <cstdint>
#include <math.h>

// Problem dims
#define BB   4
#define TT   2048
#define MT   8192      // B*T
#define CDIM 1024
#define HH   16
#define DH   64
#define FF   4096
#define QKVN 3072

// ---------------- scratch (device globals; no allocation allowed) ----------
__device__ __nv_bfloat16 g_h_hi [MT * CDIM];
__device__ __nv_bfloat16 g_h_lo [MT * CDIM];
__device__ __nv_bfloat16 g_qkv_hi[(size_t)MT * QKVN];
__device__ __nv_bfloat16 g_qkv_lo[(size_t)MT * QKVN];
__device__ __nv_bfloat16 g_at_hi[MT * CDIM];
__device__ __nv_bfloat16 g_at_lo[MT * CDIM];
__device__ float         g_x1   [MT * CDIM];
__device__ __nv_bfloat16 g_ml_hi[(size_t)MT * FF];
__device__ __nv_bfloat16 g_ml_lo[(size_t)MT * FF];
// pre-split weights
__device__ __nv_bfloat16 g_wqkv_hi[CDIM * QKVN];
__device__ __nv_bfloat16 g_wqkv_lo[CDIM * QKVN];
__device__ __nv_bfloat16 g_wo_hi [CDIM * CDIM];
__device__ __nv_bfloat16 g_wo_lo [CDIM * CDIM];
__device__ __nv_bfloat16 g_w1_hi [CDIM * FF];
__device__ __nv_bfloat16 g_w1_lo [CDIM * FF];
__device__ __nv_bfloat16 g_w2_hi [FF * CDIM];
__device__ __nv_bfloat16 g_w2_lo [FF * CDIM];

// ---------------- helpers ---------------------------------------------------
__device__ __forceinline__ uint32_t smem_addr32(const void* p) {
    return (uint32_t)__cvta_generic_to_shared(p);
}
__device__ __forceinline__ void cp16(void* smem, const void* g) {
    uint32_t s = smem_addr32(smem);
    asm volatile("cp.async.cg.shared.global [%0], [%1], 16;" :: "r"(s), "l"(g));
}
#define CP_COMMIT() asm volatile("cp.async.commit_group;")
#define CP_WAIT(n)  asm volatile("cp.async.wait_group %0;" :: "n"(n))

__device__ __forceinline__ void split2(float a, float b,
    __nv_bfloat162& hi, __nv_bfloat162& lo)
{
    hi.x = __float2bfloat16_rn(a);
    hi.y = __float2bfloat16_rn(b);
    lo.x = __float2bfloat16_rn(a - __bfloat162float(hi.x));
    lo.y = __float2bfloat16_rn(b - __bfloat162float(hi.y));
}
__device__ __forceinline__ float fexp2(float x) {
    float y;
    asm("ex2.approx.f32 %0, %1;" : "=f"(y) : "f"(x));
    return y;
}

// ---------------- split kernels --------------------------------------------
__global__ __launch_bounds__(256) void split_kernel(
    const float4* __restrict__ in, __nv_bfloat162* __restrict__ hi,
    __nv_bfloat162* __restrict__ lo, int n4)
{
    const int i = blockIdx.x * 256 + threadIdx.x;
    if (i >= n4) return;
    const float4 v = in[i];
    __nv_bfloat162 h0, h1, l0, l1;
    split2(v.x, v.y, h0, l0);
    split2(v.z, v.w, h1, l1);
    hi[i * 2]     = h0; hi[i * 2 + 1] = h1;
    lo[i * 2]     = l0; lo[i * 2 + 1] = l1;
}

__global__ __launch_bounds__(256) void split_pack_kernel(
    const float4* __restrict__ in, __nv_bfloat16* __restrict__ hi,
    __nv_bfloat16* __restrict__ lo, int coloff)
{
    const int i = blockIdx.x * 256 + threadIdx.x;
    if (i >= CDIM * CDIM / 4) return;
    const int r = i >> 8;
    const int c = (i & 255) * 4;
    const float4 v = in[i];
    __nv_bfloat162 h0, h1, l0, l1;
    split2(v.x, v.y, h0, l0);
    split2(v.z, v.w, h1, l1);
    const size_t o = (size_t)r * QKVN + coloff + c;
    *(__nv_bfloat162*)(hi + o)     = h0;
    *(__nv_bfloat162*)(hi + o + 2) = h1;
    *(__nv_bfloat162*)(lo + o)     = l0;
    *(__nv_bfloat162*)(lo + o + 2) = l1;
}

// ---------------- LayerNorm: emits bf16 hi/lo -------------------------------
__global__ __launch_bounds__(256) void ln_kernel(
    const float4* __restrict__ x, const float4* __restrict__ g,
    const float4* __restrict__ be,
    __nv_bfloat16* __restrict__ hi, __nv_bfloat16* __restrict__ lo)
{
    const int r = blockIdx.x;
    const int t = threadIdx.x;
    const float4 v = x[(size_t)r * (CDIM / 4) + t];
    float s  = v.x + v.y + v.z + v.w;
    float ss = v.x * v.x + v.y * v.y + v.z * v.z + v.w * v.w;
    #pragma unroll
    for (int o = 16; o > 0; o >>= 1) {
        s  += __shfl_down_sync(0xffffffffu, s,  o);
        ss += __shfl_down_sync(0xffffffffu, ss, o);
    }
    __shared__ float rs[8], rss[8];
    __shared__ float smu, sinv;
    const int w = t >> 5, lane = t & 31;
    if (lane == 0) { rs[w] = s; rss[w] = ss; }
    __syncthreads();
    if (t == 0) {
        float S = 0.f, SS = 0.f;
        #pragma unroll
        for (int i = 0; i < 8; i++) { S += rs[i]; SS += rss[i]; }
        const float mu  = S * (1.0f / CDIM);
        const float var = SS * (1.0f / CDIM) - mu * mu;
        smu = mu; sinv = rsqrtf(var + 1e-5f);
    }
    __syncthreads();
    const float mu = smu, inv = sinv;
    const float4 gv = g[t], bv = be[t];
    float a0 = (v.x - mu) * inv * gv.x + bv.x;
    float a1 = (v.y - mu) * inv * gv.y + bv.y;
    float a2 = (v.z - mu) * inv * gv.z + bv.z;
    float a3 = (v.w - mu) * inv * gv.w + bv.w;
    __nv_bfloat162 h0, h1, l0, l1;
    split2(a0, a1, h0, l0);
    split2(a2, a3, h1, l1);
    const size_t o = (size_t)r * CDIM + t * 4;
    *(__nv_bfloat162*)(hi + o)     = h0;
    *(__nv_bfloat162*)(hi + o + 2) = h1;
    *(__nv_bfloat162*)(lo + o)     = l0;
    *(__nv_bfloat162*)(lo + o + 2) = l1;
}

// ---------------- MMA macros ------------------------------------------------
#define LDMAT_X4(R0,R1,R2,R3,addr) \
    asm volatile("ldmatrix.sync.aligned.m8n8.x4.shared.b16 {%0,%1,%2,%3}, [%4];" \
        : "=r"(R0), "=r"(R1), "=r"(R2), "=r"(R3) : "r"(addr))
#define LDMAT_X4_T(R0,R1,R2,R3,addr) \
    asm volatile("ldmatrix.sync.aligned.m8n8.x4.trans.shared.b16 {%0,%1,%2,%3}, [%4];" \
        : "=r"(R0), "=r"(R1), "=r"(R2), "=r"(R3) : "r"(addr))
#define MMA16816(C, A0,A1,A2,A3, B0,B1) \
    asm volatile("mma.sync.aligned.m16n8k16.row.col.f32.bf16.bf16.f32 " \
        "{%0,%1,%2,%3},{%4,%5,%6,%7},{%8,%9},{%0,%1,%2,%3};" \
        : "+f"(C[0]), "+f"(C[1]), "+f"(C[2]), "+f"(C[3]) \
        : "r"(A0), "r"(A1), "r"(A2), "r"(A3), "r"(B0), "r"(B1))

// ---------------- pipelined bf16x3 tensor-core GEMM -------------------------
#define A_ST 5120   // elements per A stage: 128*40
#define B_ST 4352   // elements per B stage: 32*136
#define GEMM_SMEM ((4 * A_ST + 4 * B_ST) * 2)   // 75776 bytes

template <int EPI>
__global__ __launch_bounds__(256, 1) void mma_gemm(
    const __nv_bfloat16* __restrict__ Ah, const __nv_bfloat16* __restrict__ Al,
    const __nv_bfloat16* __restrict__ Bh, const __nv_bfloat16* __restrict__ Bl,
    const float* __restrict__ bias, const float* __restrict__ res,
    float* __restrict__ C, __nv_bfloat16* __restrict__ Ch,
    __nv_bfloat16* __restrict__ Cl, int M, int N, int K)
{
    extern __shared__ char dynsmem[];
    __nv_bfloat16* as_hi = (__nv_bfloat16*)dynsmem;          // [2][128][40]
    __nv_bfloat16* as_lo = as_hi + 2 * A_ST;
    __nv_bfloat16* bs_hi = as_hi + 4 * A_ST;                 // [2][32][136]
    __nv_bfloat16* bs_lo = bs_hi + 2 * B_ST;

    const int tid  = threadIdx.x;
    const int warp = tid >> 5, lane = tid & 31;
    const int wm = (warp & 1) * 64;
    const int wn = (warp >> 1) * 32;
    const int bm = blockIdx.y * 128, bn = blockIdx.x * 128;

    float c[4][4][4];
    #pragma unroll
    for (int i = 0; i < 4; i++)
        #pragma unroll
        for (int j = 0; j < 4; j++)
            #pragma unroll
            for (int q = 0; q < 4; q++) c[i][j][q] = 0.f;

    const int a_r = tid >> 2, a_c = (tid & 3) * 8;
    const int b_r = tid >> 4, b_c = (tid & 15) * 8;

    auto load_stage = [&](int s, int k0) {
        #pragma unroll
        for (int p = 0; p < 2; p++) {
            const int row = p * 64 + a_r;
            const size_t go = (size_t)(bm + row) * K + k0 + a_c;
            const int so = s * A_ST + row * 40 + a_c;
            cp16(as_hi + so, Ah + go);
            cp16(as_lo + so, Al + go);
        }
        #pragma unroll
        for (int p = 0; p < 2; p++) {
            const int row = p * 16 + b_r;
            const size_t go = (size_t)(k0 + row) * N + bn + b_c;
            const int so = s * B_ST + row * 136 + b_c;
            cp16(bs_hi + so, Bh + go);
            cp16(bs_lo + so, Bl + go);
        }
    };

    const int nk = K / 32;
    load_stage(0, 0);
    CP_COMMIT();

    for (int ki = 0; ki < nk; ki++) {
        const int s = ki & 1;
        if (ki + 1 < nk) {
            load_stage(s ^ 1, (ki + 1) * 32);
            CP_COMMIT();
            CP_WAIT(1);
        } else {
            CP_WAIT(0);
        }
        __syncthreads();

        const uint32_t ah_b = smem_addr32(as_hi + s * A_ST);
        const uint32_t al_b = smem_addr32(as_lo + s * A_ST);
        const uint32_t bh_b = smem_addr32(bs_hi + s * B_ST);
        const uint32_t bl_b = smem_addr32(bs_lo + s * B_ST);

        #pragma unroll
        for (int ks = 0; ks < 32; ks += 16) {
            uint32_t ah[4][4], al[4][4], bh[2][4], bl[2][4];
            #pragma unroll
            for (int mt = 0; mt < 4; mt++) {
                const int r  = wm + mt * 16 + (lane & 15);
                const int cc = ks + 8 * (lane >> 4);
                const uint32_t off = (uint32_t)(r * 40 + cc) * 2;
                LDMAT_X4(ah[mt][0], ah[mt][1], ah[mt][2], ah[mt][3], ah_b + off);
                LDMAT_X4(al[mt][0], al[mt][1], al[mt][2], al[mt][3], al_b + off);
            }
            #pragma unroll
            for (int ng = 0; ng < 2; ng++) {
                const int r  = ks + (lane & 15);
                const int cc = wn + ng * 16 + 8 * (lane >> 4);
                const uint32_t off = (uint32_t)(r * 136 + cc) * 2;
                LDMAT_X4_T(bh[ng][0], bh[ng][1], bh[ng][2], bh[ng][3], bh_b + off);
                LDMAT_X4_T(bl[ng][0], bl[ng][1], bl[ng][2], bl[ng][3], bl_b + off);
            }
            #pragma unroll
            for (int mt = 0; mt < 4; mt++) {
                #pragma unroll
                for (int nt = 0; nt < 4; nt++) {
                    const int ng = nt >> 1, hf = (nt & 1) * 2;
                    const uint32_t b0h = bh[ng][hf], b1h = bh[ng][hf + 1];
                    const uint32_t b0l = bl[ng][hf], b1l = bl[ng][hf + 1];
                    MMA16816(c[mt][nt], ah[mt][0], ah[mt][1], ah[mt][2], ah[mt][3], b0h, b1h);
                    MMA16816(c[mt][nt], al[mt][0], al[mt][1], al[mt][2], al[mt][3], b0h, b1h);
                    MMA16816(c[mt][nt], ah[mt][0], ah[mt][1], ah[mt][2], ah[mt][3], b0l, b1l);
                }
            }
        }
        __syncthreads();
    }

    const int gg = lane >> 2;
    const int qq = (lane & 3) * 2;
    #pragma unroll
    for (int mt = 0; mt < 4; mt++) {
        #pragma unroll
        for (int nt = 0; nt < 4; nt++) {
            const int col = bn + wn + nt * 8 + qq;
            #pragma unroll
            for (int hrow = 0; hrow < 2; hrow++) {
                const int row = bm + wm + mt * 16 + gg + hrow * 8;
                float2 v;
                v.x = c[mt][nt][hrow * 2 + 0];
                v.y = c[mt][nt][hrow * 2 + 1];
                const size_t idx = (size_t)row * N + col;
                if (EPI & 1) {
                    const float2 b2 = *(const float2*)(bias + col);
                    v.x += b2.x; v.y += b2.y;
                }
                if (EPI & 4) { v.x = fmaxf(v.x, 0.f); v.y = fmaxf(v.y, 0.f); }
                if (EPI & 2) {
                    const float2 r2 = *(const float2*)(res + idx);
                    v.x += r2.x; v.y += r2.y;
                }
                if (EPI & 8) {
                    __nv_bfloat162 h2, l2;
                    split2(v.x, v.y, h2, l2);
                    *(__nv_bfloat162*)(Ch + idx) = h2;
                    *(__nv_bfloat162*)(Cl + idx) = l2;
                } else {
                    *(float2*)(C + idx) = v;
                }
            }
        }
    }
}

// ---------------- tensor-core flash attention (causal, bf16x3) --------------
// 128 threads = 4 warps; block = 64 q rows for one (b,h); 64-key tiles,
// double-buffered cp.async on pre-split qkv hi/lo.
#define FST   72                 // padded row stride (bf16 elems); 144B, conflict-free
#define FTILE (64 * FST)
#define FLASH_SMEM (2 * 4 * FTILE * 2)   // 73728 bytes

__global__ __launch_bounds__(128) void flash_mma(
    const __nv_bfloat16* __restrict__ Gh, const __nv_bfloat16* __restrict__ Gl,
    __nv_bfloat16* __restrict__ Ohi, __nv_bfloat16* __restrict__ Olo)
{
    extern __shared__ __nv_bfloat16 fsm[];   // [2 stages][4 arrays][FTILE]
    const int qt = 31 - blockIdx.x;          // heavy tiles first
    const int h = blockIdx.y, b = blockIdx.z;
    const int tid = threadIdx.x, warp = tid >> 5, lane = tid & 31;
    const size_t qrow0 = (size_t)(b * TT + qt * 64);
    const float SC = 0.180336880f;           // 0.125 * log2(e)

    const int lr = tid >> 1;                 // loader: row 0..63
    const int lc = (tid & 1) * 4;            // 4 chunks of 8 bf16
    auto load_one = [&](__nv_bfloat16* dst, const __nv_bfloat16* src) {
        #pragma unroll
        for (int i = 0; i < 4; i++)
            cp16(dst + lr * FST + (lc + i) * 8, src + (size_t)lr * QKVN + (lc + i) * 8);
    };
    auto load_kv = [&](int s, int kt) {
        const size_t krow = (size_t)(b * TT + kt * 64);
        load_one(fsm + (s * 4 + 0) * FTILE, Gh + krow * QKVN + CDIM + h * DH);
        load_one(fsm + (s * 4 + 1) * FTILE, Gl + krow * QKVN + CDIM + h * DH);
        load_one(fsm + (s * 4 + 2) * FTILE, Gh + krow * QKVN + 2 * CDIM + h * DH);
        load_one(fsm + (s * 4 + 3) * FTILE, Gl + krow * QKVN + 2 * CDIM + h * DH);
    };

    // ---- stage Q through stage-0 buffers, ldmatrix to registers ----
    load_one(fsm + 0 * FTILE, Gh + qrow0 * QKVN + h * DH);
    load_one(fsm + 1 * FTILE, Gl + qrow0 * QKVN + h * DH);
    CP_COMMIT(); CP_WAIT(0);
    __syncthreads();
    uint32_t Qh[4][4], Ql[4][4];
    #pragma unroll
    for (int t = 0; t < 4; t++) {
        const uint32_t off = (uint32_t)((warp * 16 + (lane & 15)) * FST
                                        + t * 16 + 8 * (lane >> 4)) * 2;
        LDMAT_X4(Qh[t][0], Qh[t][1], Qh[t][2], Qh[t][3], smem_addr32(fsm) + off);
        LDMAT_X4(Ql[t][0], Ql[t][1], Ql[t][2], Ql[t][3], smem_addr32(fsm + FTILE) + off);
    }
    __syncthreads();

    float O[8][4];
    #pragma unroll
    for (int i = 0; i < 8; i++)
        #pragma unroll
        for (int j = 0; j < 4; j++) O[i][j] = 0.f;
    float m0 = -1e30f, m1 = -1e30f, l0 = 0.f, l1 = 0.f;

    load_kv(0, 0);
    CP_COMMIT();

    for (int kt = 0; kt <= qt; kt++) {
        const int s = kt & 1;
        if (kt < qt) { load_kv(s ^ 1, kt + 1); CP_COMMIT(); CP_WAIT(1); }
        else         { CP_WAIT(0); }
        __syncthreads();

        const uint32_t kh_b = smem_addr32(fsm + (s * 4 + 0) * FTILE);
        const uint32_t kl_b = smem_addr32(fsm + (s * 4 + 1) * FTILE);
        const uint32_t vh_b = smem_addr32(fsm + (s * 4 + 2) * FTILE);
        const uint32_t vl_b = smem_addr32(fsm + (s * 4 + 3) * FTILE);

        // ---- S = Q K^T (bf16x3) ----
        float sv[8][4];
        #pragma unroll
        for (int i = 0; i < 8; i++)
            #pragma unroll
            for (int j = 0; j < 4; j++) sv[i][j] = 0.f;

        #pragma unroll
        for (int t = 0; t < 4; t++) {
            #pragma unroll
            for (int g4 = 0; g4 < 4; g4++) {
                uint32_t kh0, kh1, kh2, kh3, kl0, kl1, kl2, kl3;
                const uint32_t off = (uint32_t)((g4 * 16 + (lane & 15)) * FST
                                                + t * 16 + 8 * (lane >> 4)) * 2;
                LDMAT_X4(kh0, kh1, kh2, kh3, kh_b + off);
                LDMAT_X4(kl0, kl1, kl2, kl3, kl_b + off);
                // even local tile: R0(k0-7), R2(k8-15); odd: R1, R3
                MMA16816(sv[g4 * 2], Qh[t][0], Qh[t][1], Qh[t][2], Qh[t][3], kh0, kh2);
                MMA16816(sv[g4 * 2], Ql[t][0], Ql[t][1], Ql[t][2], Ql[t][3], kh0, kh2);
                MMA16816(sv[g4 * 2], Qh[t][0], Qh[t][1], Qh[t][2], Qh[t][3], kl0, kl2);
                MMA16816(sv[g4 * 2 + 1], Qh[t][0], Qh[t][1], Qh[t][2], Qh[t][3], kh1, kh3);
                MMA16816(sv[g4 * 2 + 1], Ql[t][0], Ql[t][1], Ql[t][2], Ql[t][3], kh1, kh3);
                MMA16816(sv[g4 * 2 + 1], Qh[t][0], Qh[t][1], Qh[t][2], Qh[t][3], kl1, kl3);
            }
        }

        // ---- causal mask on diagonal tile ----
        const int rl0 = warp * 16 + (lane >> 2);
        if (kt == qt) {
            #pragma unroll
            for (int nt = 0; nt < 8; nt++) {
                const int cl = nt * 8 + (lane & 3) * 2;
                if (cl     > rl0)     sv[nt][0] = -1e30f;
                if (cl + 1 > rl0)     sv[nt][1] = -1e30f;
                if (cl     > rl0 + 8) sv[nt][2] = -1e30f;
                if (cl + 1 > rl0 + 8) sv[nt][3] = -1e30f;
            }
        }

        // ---- online softmax (row stats via quad shfl) ----
        float mx0 = -1e30f, mx1 = -1e30f;
        #pragma unroll
        for (int nt = 0; nt < 8; nt++) {
            mx0 = fmaxf(mx0, fmaxf(sv[nt][0], sv[nt][1]));
            mx1 = fmaxf(mx1, fmaxf(sv[nt][2], sv[nt][3]));
        }
        mx0 = fmaxf(mx0, __shfl_xor_sync(0xffffffffu, mx0, 1));
        mx0 = fmaxf(mx0, __shfl_xor_sync(0xffffffffu, mx0, 2));
        mx1 = fmaxf(mx1, __shfl_xor_sync(0xffffffffu, mx1, 1));
        mx1 = fmaxf(mx1, __shfl_xor_sync(0xffffffffu, mx1, 2));
        const float mn0 = fmaxf(m0, mx0), mn1 = fmaxf(m1, mx1);
        const float corr0 = fexp2((m0 - mn0) * SC);
        const float corr1 = fexp2((m1 - mn1) * SC);

        uint32_t pAh[4][4], pAl[4][4];
        float ps0 = 0.f, ps1 = 0.f;
        #pragma unroll
        for (int nt = 0; nt < 8; nt++) {
            const float p0 = fexp2((sv[nt][0] - mn0) * SC);
            const float p1 = fexp2((sv[nt][1] - mn0) * SC);
            const float p2 = fexp2((sv[nt][2] - mn1) * SC);
            const float p3 = fexp2((sv[nt][3] - mn1) * SC);
            ps0 += p0 + p1; ps1 += p2 + p3;
            __nv_bfloat162 h01, l01, h23, l23;
            split2(p0, p1, h01, l01);
            split2(p2, p3, h23, l23);
            const int t = nt >> 1, o = (nt & 1) * 2;
            pAh[t][o]     = *(uint32_t*)&h01;
            pAh[t][o + 1] = *(uint32_t*)&h23;
            pAl[t][o]     = *(uint32_t*)&l01;
            pAl[t][o + 1] = *(uint32_t*)&l23;
        }
        ps0 += __shfl_xor_sync(0xffffffffu, ps0, 1);
        ps0 += __shfl_xor_sync(0xffffffffu, ps0, 2);
        ps1 += __shfl_xor_sync(0xffffffffu, ps1, 1);
        ps1 += __shfl_xor_sync(0xffffffffu, ps1, 2);
        l0 = l0 * corr0 + ps0;
        l1 = l1 * corr1 + ps1;
        m0 = mn0; m1 = mn1;

        #pragma unroll
        for (int dt = 0; dt < 8; dt++) {
            O[dt][0] *= corr0; O[dt][1] *= corr0;
            O[dt][2] *= corr1; O[dt][3] *= corr1;
        }

        // ---- O += P V (bf16x3) ----
        #pragma unroll
        for (int t = 0; t < 4; t++) {
            #pragma unroll
            for (int g4 = 0; g4 < 4; g4++) {
                uint32_t vh0, vh1, vh2, vh3, vl0, vl1, vl2, vl3;
                const uint32_t off = (uint32_t)((t * 16 + (lane & 15)) * FST
                                                + g4 * 16 + 8 * (lane >> 4)) * 2;
                LDMAT_X4_T(vh0, vh1, vh2, vh3, vh_b + off);
                LDMAT_X4_T(vl0, vl1, vl2, vl3, vl_b + off);
                MMA16816(O[g4 * 2], pAh[t][0], pAh[t][1], pAh[t][2], pAh[t][3], vh0, vh1);
                MMA16816(O[g4 * 2], pAl[t][0], pAl[t][1], pAl[t][2], pAl[t][3], vh0, vh1);
                MMA16816(O[g4 * 2], pAh[t][0], pAh[t][1], pAh[t][2], pAh[t][3], vl0, vl1);
                MMA16816(O[g4 * 2 + 1], pAh[t][0], pAh[t][1], pAh[t][2], pAh[t][3], vh2, vh3);
                MMA16816(O[g4 * 2 + 1], pAl[t][0], pAl[t][1], pAl[t][2], pAl[t][3], vh2, vh3);
                MMA16816(O[g4 * 2 + 1], pAh[t][0], pAh[t][1], pAh[t][2], pAh[t][3], vl2, vl3);
            }
        }
        __syncthreads();
    }

    // ---- normalize + split-write ----
    const float inv0 = 1.f / l0, inv1 = 1.f / l1;
    const int rl0 = warp * 16 + (lane >> 2);
    #pragma unroll
    for (int dt = 0; dt < 8; dt++) {
        const int d = h * DH + dt * 8 + (lane & 3) * 2;
        __nv_bfloat162 hh, ll;
        const size_t i0 = (qrow0 + rl0) * CDIM + d;
        split2(O[dt][0] * inv0, O[dt][1] * inv0, hh, ll);
        *(__nv_bfloat162*)(Ohi + i0) = hh;
        *(__nv_bfloat162*)(Olo + i0) = ll;
        const size_t i1 = (qrow0 + rl0 + 8) * CDIM + d;
        split2(O[dt][2] * inv1, O[dt][3] * inv1, hh, ll);
        *(__nv_bfloat162*)(Ohi + i1) = hh;
        *(__nv_bfloat162*)(Olo + i1) = ll;
    }
}

// ---------------- launch ----------------------------------------------------
extern "C" void kernel_launch(void* const* d_in, const int* in_sizes, int n_in,
                              void* d_out, int out_size)
{
    const float* x   = (const float*)d_in[0];
    const float* Wq  = (const float*)d_in[1];
    const float* Wk  = (const float*)d_in[2];
    const float* Wv  = (const float*)d_in[3];
    const float* Wo  = (const float*)d_in[4];
    const float* bo  = (const float*)d_in[5];
    const float* W1  = (const float*)d_in[6];
    const float* b1  = (const float*)d_in[7];
    const float* W2  = (const float*)d_in[8];
    const float* b2  = (const float*)d_in[9];
    const float* g1  = (const float*)d_in[10];
    const float* be1 = (const float*)d_in[11];
    const float* g2  = (const float*)d_in[12];
    const float* be2 = (const float*)d_in[13];
    float* out = (float*)d_out;

    __nv_bfloat16 *h_hi, *h_lo, *qkv_hi, *qkv_lo, *at_hi, *at_lo, *ml_hi, *ml_lo;
    __nv_bfloat16 *wqkv_hi, *wqkv_lo, *wo_hi, *wo_lo, *w1_hi, *w1_lo, *w2_hi, *w2_lo;
    float *x1;
    cudaGetSymbolAddress((void**)&h_hi,   g_h_hi);
    cudaGetSymbolAddress((void**)&h_lo,   g_h_lo);
    cudaGetSymbolAddress((void**)&qkv_hi, g_qkv_hi);
    cudaGetSymbolAddress((void**)&qkv_lo, g_qkv_lo);
    cudaGetSymbolAddress((void**)&at_hi,  g_at_hi);
    cudaGetSymbolAddress((void**)&at_lo,  g_at_lo);
    cudaGetSymbolAddress((void**)&x1,     g_x1);
    cudaGetSymbolAddress((void**)&ml_hi,  g_ml_hi);
    cudaGetSymbolAddress((void**)&ml_lo,  g_ml_lo);
    cudaGetSymbolAddress((void**)&wqkv_hi, g_wqkv_hi);
    cudaGetSymbolAddress((void**)&wqkv_lo, g_wqkv_lo);
    cudaGetSymbolAddress((void**)&wo_hi, g_wo_hi);
    cudaGetSymbolAddress((void**)&wo_lo, g_wo_lo);
    cudaGetSymbolAddress((void**)&w1_hi, g_w1_hi);
    cudaGetSymbolAddress((void**)&w1_lo, g_w1_lo);
    cudaGetSymbolAddress((void**)&w2_hi, g_w2_hi);
    cudaGetSymbolAddress((void**)&w2_lo, g_w2_lo);

    cudaFuncSetAttribute(mma_gemm<3>,  cudaFuncAttributeMaxDynamicSharedMemorySize, GEMM_SMEM);
    cudaFuncSetAttribute(mma_gemm<8>,  cudaFuncAttributeMaxDynamicSharedMemorySize, GEMM_SMEM);
    cudaFuncSetAttribute(mma_gemm<13>, cudaFuncAttributeMaxDynamicSharedMemorySize, GEMM_SMEM);
    cudaFuncSetAttribute(flash_mma,    cudaFuncAttributeMaxDynamicSharedMemorySize, FLASH_SMEM);

    // ---- pre-split weights ----
    const int nW = CDIM * CDIM / 4;
    split_pack_kernel<<<(nW + 255) / 256, 256>>>((const float4*)Wq, wqkv_hi, wqkv_lo, 0);
    split_pack_kernel<<<(nW + 255) / 256, 256>>>((const float4*)Wk, wqkv_hi, wqkv_lo, 1024);
    split_pack_kernel<<<(nW + 255) / 256, 256>>>((const float4*)Wv, wqkv_hi, wqkv_lo, 2048);
    split_kernel<<<(nW + 255) / 256, 256>>>((const float4*)Wo,
        (__nv_bfloat162*)wo_hi, (__nv_bfloat162*)wo_lo, nW);
    const int nW1 = CDIM * FF / 4;
    split_kernel<<<(nW1 + 255) / 256, 256>>>((const float4*)W1,
        (__nv_bfloat162*)w1_hi, (__nv_bfloat162*)w1_lo, nW1);
    split_kernel<<<(nW1 + 255) / 256, 256>>>((const float4*)W2,
        (__nv_bfloat162*)w2_hi, (__nv_bfloat162*)w2_lo, nW1);

    const dim3 gQKV(QKVN / 128, MT / 128);   // (24, 64)
    const dim3 gC(CDIM / 128, MT / 128);     // (8, 64)
    const dim3 gF(FF / 128, MT / 128);       // (32, 64)

    // LN1 -> split h
    ln_kernel<<<MT, 256>>>((const float4*)x, (const float4*)g1,
                           (const float4*)be1, h_hi, h_lo);
    // fused QKV projection -> split qkv
    mma_gemm<8><<<gQKV, 256, GEMM_SMEM>>>(h_hi, h_lo, wqkv_hi, wqkv_lo,
        nullptr, nullptr, nullptr, qkv_hi, qkv_lo, MT, QKVN, CDIM);
    // tensor-core causal flash attention -> split attn
    flash_mma<<<dim3(TT / 64, HH, BB), 128, FLASH_SMEM>>>(qkv_hi, qkv_lo, at_hi, at_lo);
    // x1 = x + attn @ Wo + bo
    mma_gemm<3><<<gC, 256, GEMM_SMEM>>>(at_hi, at_lo, wo_hi, wo_lo,
        bo, x, x1, nullptr, nullptr, MT, CDIM, CDIM);
    // LN2 -> split h
    ln_kernel<<<MT, 256>>>((const float4*)x1, (const float4*)g2,
                           (const float4*)be2, h_hi, h_lo);
    // mlp = relu(h @ W1 + b1) -> split
    mma_gemm<13><<<gF, 256, GEMM_SMEM>>>(h_hi, h_lo, w1_hi, w1_lo,
        b1, nullptr, nullptr, ml_hi, ml_lo, MT, FF, CDIM);
    // out = x1 + mlp @ W2 + b2
    mma_gemm<3><<<gC, 256, GEMM_SMEM>>>(ml_hi, ml_lo, w2_hi, w2_lo,
        b2, x1, out, nullptr, nullptr, MT, CDIM, FF);
}

// round 9
// speedup vs baseline: 3.0234x; 1.0141x over previous
#include <cuda_runtime.h>
#include <cuda_bf16.h>
#include <cstdint>
#include <math.h>

// Problem dims
#define BB   4
#define TT   2048
#define MT   8192      // B*T
#define CDIM 1024
#define HH   16
#define DH   64
#define FF   4096
#define QKVN 3072

// ---------------- scratch (device globals; no allocation allowed) ----------
__device__ __nv_bfloat16 g_h_hi [MT * CDIM];
__device__ __nv_bfloat16 g_h_lo [MT * CDIM];
__device__ __nv_bfloat16 g_qkv_hi[(size_t)MT * QKVN];
__device__ __nv_bfloat16 g_qkv_lo[(size_t)MT * QKVN];
__device__ __nv_bfloat16 g_at_hi[MT * CDIM];
__device__ __nv_bfloat16 g_at_lo[MT * CDIM];
__device__ float         g_x1   [MT * CDIM];
__device__ __nv_bfloat16 g_ml_hi[(size_t)MT * FF];
__device__ __nv_bfloat16 g_ml_lo[(size_t)MT * FF];
// pre-split weights
__device__ __nv_bfloat16 g_wqkv_hi[CDIM * QKVN];
__device__ __nv_bfloat16 g_wqkv_lo[CDIM * QKVN];
__device__ __nv_bfloat16 g_wo_hi [CDIM * CDIM];
__device__ __nv_bfloat16 g_wo_lo [CDIM * CDIM];
__device__ __nv_bfloat16 g_w1_hi [CDIM * FF];
__device__ __nv_bfloat16 g_w1_lo [CDIM * FF];
__device__ __nv_bfloat16 g_w2_hi [FF * CDIM];
__device__ __nv_bfloat16 g_w2_lo [FF * CDIM];

// ---------------- helpers ---------------------------------------------------
__device__ __forceinline__ uint32_t smem_addr32(const void* p) {
    return (uint32_t)__cvta_generic_to_shared(p);
}
__device__ __forceinline__ void cp16(void* smem, const void* g) {
    uint32_t s = smem_addr32(smem);
    asm volatile("cp.async.cg.shared.global [%0], [%1], 16;" :: "r"(s), "l"(g));
}
#define CP_COMMIT() asm volatile("cp.async.commit_group;")
#define CP_WAIT(n)  asm volatile("cp.async.wait_group %0;" :: "n"(n))

__device__ __forceinline__ void split2(float a, float b,
    __nv_bfloat162& hi, __nv_bfloat162& lo)
{
    hi.x = __float2bfloat16_rn(a);
    hi.y = __float2bfloat16_rn(b);
    lo.x = __float2bfloat16_rn(a - __bfloat162float(hi.x));
    lo.y = __float2bfloat16_rn(b - __bfloat162float(hi.y));
}
__device__ __forceinline__ float fexp2(float x) {
    float y;
    asm("ex2.approx.f32 %0, %1;" : "=f"(y) : "f"(x));
    return y;
}

// ---------------- split kernels --------------------------------------------
__global__ __launch_bounds__(256) void split_kernel(
    const float4* __restrict__ in, __nv_bfloat162* __restrict__ hi,
    __nv_bfloat162* __restrict__ lo, int n4)
{
    const int i = blockIdx.x * 256 + threadIdx.x;
    if (i >= n4) return;
    const float4 v = in[i];
    __nv_bfloat162 h0, h1, l0, l1;
    split2(v.x, v.y, h0, l0);
    split2(v.z, v.w, h1, l1);
    hi[i * 2]     = h0; hi[i * 2 + 1] = h1;
    lo[i * 2]     = l0; lo[i * 2 + 1] = l1;
}

__global__ __launch_bounds__(256) void split_pack_kernel(
    const float4* __restrict__ in, __nv_bfloat16* __restrict__ hi,
    __nv_bfloat16* __restrict__ lo, int coloff)
{
    const int i = blockIdx.x * 256 + threadIdx.x;
    if (i >= CDIM * CDIM / 4) return;
    const int r = i >> 8;
    const int c = (i & 255) * 4;
    const float4 v = in[i];
    __nv_bfloat162 h0, h1, l0, l1;
    split2(v.x, v.y, h0, l0);
    split2(v.z, v.w, h1, l1);
    const size_t o = (size_t)r * QKVN + coloff + c;
    *(__nv_bfloat162*)(hi + o)     = h0;
    *(__nv_bfloat162*)(hi + o + 2) = h1;
    *(__nv_bfloat162*)(lo + o)     = l0;
    *(__nv_bfloat162*)(lo + o + 2) = l1;
}

// ---------------- LayerNorm: emits bf16 hi/lo -------------------------------
__global__ __launch_bounds__(256) void ln_kernel(
    const float4* __restrict__ x, const float4* __restrict__ g,
    const float4* __restrict__ be,
    __nv_bfloat16* __restrict__ hi, __nv_bfloat16* __restrict__ lo)
{
    const int r = blockIdx.x;
    const int t = threadIdx.x;
    const float4 v = x[(size_t)r * (CDIM / 4) + t];
    float s  = v.x + v.y + v.z + v.w;
    float ss = v.x * v.x + v.y * v.y + v.z * v.z + v.w * v.w;
    #pragma unroll
    for (int o = 16; o > 0; o >>= 1) {
        s  += __shfl_down_sync(0xffffffffu, s,  o);
        ss += __shfl_down_sync(0xffffffffu, ss, o);
    }
    __shared__ float rs[8], rss[8];
    __shared__ float smu, sinv;
    const int w = t >> 5, lane = t & 31;
    if (lane == 0) { rs[w] = s; rss[w] = ss; }
    __syncthreads();
    if (t == 0) {
        float S = 0.f, SS = 0.f;
        #pragma unroll
        for (int i = 0; i < 8; i++) { S += rs[i]; SS += rss[i]; }
        const float mu  = S * (1.0f / CDIM);
        const float var = SS * (1.0f / CDIM) - mu * mu;
        smu = mu; sinv = rsqrtf(var + 1e-5f);
    }
    __syncthreads();
    const float mu = smu, inv = sinv;
    const float4 gv = g[t], bv = be[t];
    float a0 = (v.x - mu) * inv * gv.x + bv.x;
    float a1 = (v.y - mu) * inv * gv.y + bv.y;
    float a2 = (v.z - mu) * inv * gv.z + bv.z;
    float a3 = (v.w - mu) * inv * gv.w + bv.w;
    __nv_bfloat162 h0, h1, l0, l1;
    split2(a0, a1, h0, l0);
    split2(a2, a3, h1, l1);
    const size_t o = (size_t)r * CDIM + t * 4;
    *(__nv_bfloat162*)(hi + o)     = h0;
    *(__nv_bfloat162*)(hi + o + 2) = h1;
    *(__nv_bfloat162*)(lo + o)     = l0;
    *(__nv_bfloat162*)(lo + o + 2) = l1;
}

// ---------------- MMA macros ------------------------------------------------
#define LDMAT_X4(R0,R1,R2,R3,addr) \
    asm volatile("ldmatrix.sync.aligned.m8n8.x4.shared.b16 {%0,%1,%2,%3}, [%4];" \
        : "=r"(R0), "=r"(R1), "=r"(R2), "=r"(R3) : "r"(addr))
#define LDMAT_X4_T(R0,R1,R2,R3,addr) \
    asm volatile("ldmatrix.sync.aligned.m8n8.x4.trans.shared.b16 {%0,%1,%2,%3}, [%4];" \
        : "=r"(R0), "=r"(R1), "=r"(R2), "=r"(R3) : "r"(addr))
#define MMA16816(C, A0,A1,A2,A3, B0,B1) \
    asm volatile("mma.sync.aligned.m16n8k16.row.col.f32.bf16.bf16.f32 " \
        "{%0,%1,%2,%3},{%4,%5,%6,%7},{%8,%9},{%0,%1,%2,%3};" \
        : "+f"(C[0]), "+f"(C[1]), "+f"(C[2]), "+f"(C[3]) \
        : "r"(A0), "r"(A1), "r"(A2), "r"(A3), "r"(B0), "r"(B1))

// ---------------- pipelined bf16x3 tensor-core GEMM (3-stage) ---------------
#define A_ST 5120                         // elems per A array per stage: 128*40
#define B_ST 4352                         // elems per B array per stage: 32*136
#define STG_ELEMS (2 * A_ST + 2 * B_ST)   // 18944 elems per stage
#define GEMM_SMEM (3 * STG_ELEMS * 2)     // 113664 bytes

template <int EPI>
__global__ __launch_bounds__(256, 1) void mma_gemm(
    const __nv_bfloat16* __restrict__ Ah, const __nv_bfloat16* __restrict__ Al,
    const __nv_bfloat16* __restrict__ Bh, const __nv_bfloat16* __restrict__ Bl,
    const float* __restrict__ bias, const float* __restrict__ res,
    float* __restrict__ C, __nv_bfloat16* __restrict__ Ch,
    __nv_bfloat16* __restrict__ Cl, int M, int N, int K)
{
    extern __shared__ char dynsmem[];
    __nv_bfloat16* base = (__nv_bfloat16*)dynsmem;
    // per stage layout: [as_hi A_ST][as_lo A_ST][bs_hi B_ST][bs_lo B_ST]

    const int tid  = threadIdx.x;
    const int warp = tid >> 5, lane = tid & 31;
    const int wm = (warp & 1) * 64;
    const int wn = (warp >> 1) * 32;
    const int bm = blockIdx.y * 128, bn = blockIdx.x * 128;

    float c[4][4][4];
    #pragma unroll
    for (int i = 0; i < 4; i++)
        #pragma unroll
        for (int j = 0; j < 4; j++)
            #pragma unroll
            for (int q = 0; q < 4; q++) c[i][j][q] = 0.f;

    const int a_r = tid >> 2, a_c = (tid & 3) * 8;
    const int b_r = tid >> 4, b_c = (tid & 15) * 8;

    auto load_stage = [&](int s, int k0) {
        __nv_bfloat16* st = base + s * STG_ELEMS;
        #pragma unroll
        for (int p = 0; p < 2; p++) {
            const int row = p * 64 + a_r;
            const size_t go = (size_t)(bm + row) * K + k0 + a_c;
            const int so = row * 40 + a_c;
            cp16(st + so,        Ah + go);
            cp16(st + A_ST + so, Al + go);
        }
        #pragma unroll
        for (int p = 0; p < 2; p++) {
            const int row = p * 16 + b_r;
            const size_t go = (size_t)(k0 + row) * N + bn + b_c;
            const int so = 2 * A_ST + row * 136 + b_c;
            cp16(st + so,        Bh + go);
            cp16(st + B_ST + so, Bl + go);
        }
    };

    const int nk = K / 32;
    load_stage(0, 0);
    CP_COMMIT();
    if (nk > 1) load_stage(1, 32);
    CP_COMMIT();

    for (int ki = 0; ki < nk; ki++) {
        CP_WAIT(1);                    // stage ki resident
        __syncthreads();               // all warps done with stage (ki+2)%3 reads
        if (ki + 2 < nk) load_stage((ki + 2) % 3, (ki + 2) * 32);
        CP_COMMIT();                   // one group per iter keeps counts aligned

        const uint32_t st_b = smem_addr32(base + (ki % 3) * STG_ELEMS);
        const uint32_t ah_b = st_b;
        const uint32_t al_b = st_b + A_ST * 2;
        const uint32_t bh_b = st_b + 4 * A_ST;
        const uint32_t bl_b = bh_b + B_ST * 2;

        #pragma unroll
        for (int ks = 0; ks < 32; ks += 16) {
            uint32_t ah[4][4], al[4][4], bh[2][4], bl[2][4];
            #pragma unroll
            for (int mt = 0; mt < 4; mt++) {
                const int r  = wm + mt * 16 + (lane & 15);
                const int cc = ks + 8 * (lane >> 4);
                const uint32_t off = (uint32_t)(r * 40 + cc) * 2;
                LDMAT_X4(ah[mt][0], ah[mt][1], ah[mt][2], ah[mt][3], ah_b + off);
                LDMAT_X4(al[mt][0], al[mt][1], al[mt][2], al[mt][3], al_b + off);
            }
            #pragma unroll
            for (int ng = 0; ng < 2; ng++) {
                const int r  = ks + (lane & 15);
                const int cc = wn + ng * 16 + 8 * (lane >> 4);
                const uint32_t off = (uint32_t)(r * 136 + cc) * 2;
                LDMAT_X4_T(bh[ng][0], bh[ng][1], bh[ng][2], bh[ng][3], bh_b + off);
                LDMAT_X4_T(bl[ng][0], bl[ng][1], bl[ng][2], bl[ng][3], bl_b + off);
            }
            #pragma unroll
            for (int mt = 0; mt < 4; mt++) {
                #pragma unroll
                for (int nt = 0; nt < 4; nt++) {
                    const int ng = nt >> 1, hf = (nt & 1) * 2;
                    const uint32_t b0h = bh[ng][hf], b1h = bh[ng][hf + 1];
                    const uint32_t b0l = bl[ng][hf], b1l = bl[ng][hf + 1];
                    MMA16816(c[mt][nt], ah[mt][0], ah[mt][1], ah[mt][2], ah[mt][3], b0h, b1h);
                    MMA16816(c[mt][nt], al[mt][0], al[mt][1], al[mt][2], al[mt][3], b0h, b1h);
                    MMA16816(c[mt][nt], ah[mt][0], ah[mt][1], ah[mt][2], ah[mt][3], b0l, b1l);
                }
            }
        }
    }

    const int gg = lane >> 2;
    const int qq = (lane & 3) * 2;
    #pragma unroll
    for (int mt = 0; mt < 4; mt++) {
        #pragma unroll
        for (int nt = 0; nt < 4; nt++) {
            const int col = bn + wn + nt * 8 + qq;
            #pragma unroll
            for (int hrow = 0; hrow < 2; hrow++) {
                const int row = bm + wm + mt * 16 + gg + hrow * 8;
                float2 v;
                v.x = c[mt][nt][hrow * 2 + 0];
                v.y = c[mt][nt][hrow * 2 + 1];
                const size_t idx = (size_t)row * N + col;
                if (EPI & 1) {
                    const float2 b2 = *(const float2*)(bias + col);
                    v.x += b2.x; v.y += b2.y;
                }
                if (EPI & 4) { v.x = fmaxf(v.x, 0.f); v.y = fmaxf(v.y, 0.f); }
                if (EPI & 2) {
                    const float2 r2 = *(const float2*)(res + idx);
                    v.x += r2.x; v.y += r2.y;
                }
                if (EPI & 8) {
                    __nv_bfloat162 h2, l2;
                    split2(v.x, v.y, h2, l2);
                    *(__nv_bfloat162*)(Ch + idx) = h2;
                    *(__nv_bfloat162*)(Cl + idx) = l2;
                } else {
                    *(float2*)(C + idx) = v;
                }
            }
        }
    }
}

// ---------------- tensor-core flash attention (causal, bf16x3) --------------
// 128 threads = 4 warps; block = 64 q rows for one (b,h); 64-key tiles,
// double-buffered cp.async on pre-split qkv hi/lo.
#define FST   72                 // padded row stride (bf16 elems); 144B, conflict-free
#define FTILE (64 * FST)
#define FLASH_SMEM (2 * 4 * FTILE * 2)   // 73728 bytes

__global__ __launch_bounds__(128) void flash_mma(
    const __nv_bfloat16* __restrict__ Gh, const __nv_bfloat16* __restrict__ Gl,
    __nv_bfloat16* __restrict__ Ohi, __nv_bfloat16* __restrict__ Olo)
{
    extern __shared__ __nv_bfloat16 fsm[];   // [2 stages][4 arrays][FTILE]
    const int qt = 31 - blockIdx.x;          // heavy tiles first
    const int h = blockIdx.y, b = blockIdx.z;
    const int tid = threadIdx.x, warp = tid >> 5, lane = tid & 31;
    const size_t qrow0 = (size_t)(b * TT + qt * 64);
    const float SC = 0.180336880f;           // 0.125 * log2(e)

    const int lr = tid >> 1;
    const int lc = (tid & 1) * 4;
    auto load_one = [&](__nv_bfloat16* dst, const __nv_bfloat16* src) {
        #pragma unroll
        for (int i = 0; i < 4; i++)
            cp16(dst + lr * FST + (lc + i) * 8, src + (size_t)lr * QKVN + (lc + i) * 8);
    };
    auto load_kv = [&](int s, int kt) {
        const size_t krow = (size_t)(b * TT + kt * 64);
        load_one(fsm + (s * 4 + 0) * FTILE, Gh + krow * QKVN + CDIM + h * DH);
        load_one(fsm + (s * 4 + 1) * FTILE, Gl + krow * QKVN + CDIM + h * DH);
        load_one(fsm + (s * 4 + 2) * FTILE, Gh + krow * QKVN + 2 * CDIM + h * DH);
        load_one(fsm + (s * 4 + 3) * FTILE, Gl + krow * QKVN + 2 * CDIM + h * DH);
    };

    // ---- stage Q through stage-0 buffers, ldmatrix to registers ----
    load_one(fsm + 0 * FTILE, Gh + qrow0 * QKVN + h * DH);
    load_one(fsm + 1 * FTILE, Gl + qrow0 * QKVN + h * DH);
    CP_COMMIT(); CP_WAIT(0);
    __syncthreads();
    uint32_t Qh[4][4], Ql[4][4];
    #pragma unroll
    for (int t = 0; t < 4; t++) {
        const uint32_t off = (uint32_t)((warp * 16 + (lane & 15)) * FST
                                        + t * 16 + 8 * (lane >> 4)) * 2;
        LDMAT_X4(Qh[t][0], Qh[t][1], Qh[t][2], Qh[t][3], smem_addr32(fsm) + off);
        LDMAT_X4(Ql[t][0], Ql[t][1], Ql[t][2], Ql[t][3], smem_addr32(fsm + FTILE) + off);
    }
    __syncthreads();

    float O[8][4];
    #pragma unroll
    for (int i = 0; i < 8; i++)
        #pragma unroll
        for (int j = 0; j < 4; j++) O[i][j] = 0.f;
    float m0 = -1e30f, m1 = -1e30f, l0 = 0.f, l1 = 0.f;

    load_kv(0, 0);
    CP_COMMIT();

    for (int kt = 0; kt <= qt; kt++) {
        const int s = kt & 1;
        if (kt < qt) { load_kv(s ^ 1, kt + 1); CP_COMMIT(); CP_WAIT(1); }
        else         { CP_WAIT(0); }
        __syncthreads();

        const uint32_t kh_b = smem_addr32(fsm + (s * 4 + 0) * FTILE);
        const uint32_t kl_b = smem_addr32(fsm + (s * 4 + 1) * FTILE);
        const uint32_t vh_b = smem_addr32(fsm + (s * 4 + 2) * FTILE);
        const uint32_t vl_b = smem_addr32(fsm + (s * 4 + 3) * FTILE);

        // ---- S = Q K^T (bf16x3) ----
        float sv[8][4];
        #pragma unroll
        for (int i = 0; i < 8; i++)
            #pragma unroll
            for (int j = 0; j < 4; j++) sv[i][j] = 0.f;

        #pragma unroll
        for (int t = 0; t < 4; t++) {
            #pragma unroll
            for (int g4 = 0; g4 < 4; g4++) {
                uint32_t kh0, kh1, kh2, kh3, kl0, kl1, kl2, kl3;
                const uint32_t off = (uint32_t)((g4 * 16 + (lane & 15)) * FST
                                                + t * 16 + 8 * (lane >> 4)) * 2;
                LDMAT_X4(kh0, kh1, kh2, kh3, kh_b + off);
                LDMAT_X4(kl0, kl1, kl2, kl3, kl_b + off);
                MMA16816(sv[g4 * 2], Qh[t][0], Qh[t][1], Qh[t][2], Qh[t][3], kh0, kh2);
                MMA16816(sv[g4 * 2], Ql[t][0], Ql[t][1], Ql[t][2], Ql[t][3], kh0, kh2);
                MMA16816(sv[g4 * 2], Qh[t][0], Qh[t][1], Qh[t][2], Qh[t][3], kl0, kl2);
                MMA16816(sv[g4 * 2 + 1], Qh[t][0], Qh[t][1], Qh[t][2], Qh[t][3], kh1, kh3);
                MMA16816(sv[g4 * 2 + 1], Ql[t][0], Ql[t][1], Ql[t][2], Ql[t][3], kh1, kh3);
                MMA16816(sv[g4 * 2 + 1], Qh[t][0], Qh[t][1], Qh[t][2], Qh[t][3], kl1, kl3);
            }
        }

        // ---- causal mask on diagonal tile ----
        const int rl0 = warp * 16 + (lane >> 2);
        if (kt == qt) {
            #pragma unroll
            for (int nt = 0; nt < 8; nt++) {
                const int cl = nt * 8 + (lane & 3) * 2;
                if (cl     > rl0)     sv[nt][0] = -1e30f;
                if (cl + 1 > rl0)     sv[nt][1] = -1e30f;
                if (cl     > rl0 + 8) sv[nt][2] = -1e30f;
                if (cl + 1 > rl0 + 8) sv[nt][3] = -1e30f;
            }
        }

        // ---- online softmax (row stats via quad shfl) ----
        float mx0 = -1e30f, mx1 = -1e30f;
        #pragma unroll
        for (int nt = 0; nt < 8; nt++) {
            mx0 = fmaxf(mx0, fmaxf(sv[nt][0], sv[nt][1]));
            mx1 = fmaxf(mx1, fmaxf(sv[nt][2], sv[nt][3]));
        }
        mx0 = fmaxf(mx0, __shfl_xor_sync(0xffffffffu, mx0, 1));
        mx0 = fmaxf(mx0, __shfl_xor_sync(0xffffffffu, mx0, 2));
        mx1 = fmaxf(mx1, __shfl_xor_sync(0xffffffffu, mx1, 1));
        mx1 = fmaxf(mx1, __shfl_xor_sync(0xffffffffu, mx1, 2));
        const float mn0 = fmaxf(m0, mx0), mn1 = fmaxf(m1, mx1);
        const float corr0 = fexp2((m0 - mn0) * SC);
        const float corr1 = fexp2((m1 - mn1) * SC);

        uint32_t pAh[4][4], pAl[4][4];
        float ps0 = 0.f, ps1 = 0.f;
        #pragma unroll
        for (int nt = 0; nt < 8; nt++) {
            const float p0 = fexp2((sv[nt][0] - mn0) * SC);
            const float p1 = fexp2((sv[nt][1] - mn0) * SC);
            const float p2 = fexp2((sv[nt][2] - mn1) * SC);
            const float p3 = fexp2((sv[nt][3] - mn1) * SC);
            ps0 += p0 + p1; ps1 += p2 + p3;
            __nv_bfloat162 h01, l01, h23, l23;
            split2(p0, p1, h01, l01);
            split2(p2, p3, h23, l23);
            const int t = nt >> 1, o = (nt & 1) * 2;
            pAh[t][o]     = *(uint32_t*)&h01;
            pAh[t][o + 1] = *(uint32_t*)&h23;
            pAl[t][o]     = *(uint32_t*)&l01;
            pAl[t][o + 1] = *(uint32_t*)&l23;
        }
        ps0 += __shfl_xor_sync(0xffffffffu, ps0, 1);
        ps0 += __shfl_xor_sync(0xffffffffu, ps0, 2);
        ps1 += __shfl_xor_sync(0xffffffffu, ps1, 1);
        ps1 += __shfl_xor_sync(0xffffffffu, ps1, 2);
        l0 = l0 * corr0 + ps0;
        l1 = l1 * corr1 + ps1;
        m0 = mn0; m1 = mn1;

        #pragma unroll
        for (int dt = 0; dt < 8; dt++) {
            O[dt][0] *= corr0; O[dt][1] *= corr0;
            O[dt][2] *= corr1; O[dt][3] *= corr1;
        }

        // ---- O += P V (bf16x3) ----
        #pragma unroll
        for (int t = 0; t < 4; t++) {
            #pragma unroll
            for (int g4 = 0; g4 < 4; g4++) {
                uint32_t vh0, vh1, vh2, vh3, vl0, vl1, vl2, vl3;
                const uint32_t off = (uint32_t)((t * 16 + (lane & 15)) * FST
                                                + g4 * 16 + 8 * (lane >> 4)) * 2;
                LDMAT_X4_T(vh0, vh1, vh2, vh3, vh_b + off);
                LDMAT_X4_T(vl0, vl1, vl2, vl3, vl_b + off);
                MMA16816(O[g4 * 2], pAh[t][0], pAh[t][1], pAh[t][2], pAh[t][3], vh0, vh1);
                MMA16816(O[g4 * 2], pAl[t][0], pAl[t][1], pAl[t][2], pAl[t][3], vh0, vh1);
                MMA16816(O[g4 * 2], pAh[t][0], pAh[t][1], pAh[t][2], pAh[t][3], vl0, vl1);
                MMA16816(O[g4 * 2 + 1], pAh[t][0], pAh[t][1], pAh[t][2], pAh[t][3], vh2, vh3);
                MMA16816(O[g4 * 2 + 1], pAl[t][0], pAl[t][1], pAl[t][2], pAl[t][3], vh2, vh3);
                MMA16816(O[g4 * 2 + 1], pAh[t][0], pAh[t][1], pAh[t][2], pAh[t][3], vl2, vl3);
            }
        }
        __syncthreads();
    }

    // ---- normalize + split-write ----
    const float inv0 = 1.f / l0, inv1 = 1.f / l1;
    const int rl0 = warp * 16 + (lane >> 2);
    #pragma unroll
    for (int dt = 0; dt < 8; dt++) {
        const int d = h * DH + dt * 8 + (lane & 3) * 2;
        __nv_bfloat162 hh, ll;
        const size_t i0 = (qrow0 + rl0) * CDIM + d;
        split2(O[dt][0] * inv0, O[dt][1] * inv0, hh, ll);
        *(__nv_bfloat162*)(Ohi + i0) = hh;
        *(__nv_bfloat162*)(Olo + i0) = ll;
        const size_t i1 = (qrow0 + rl0 + 8) * CDIM + d;
        split2(O[dt][2] * inv1, O[dt][3] * inv1, hh, ll);
        *(__nv_bfloat162*)(Ohi + i1) = hh;
        *(__nv_bfloat162*)(Olo + i1) = ll;
    }
}

// ---------------- launch ----------------------------------------------------
extern "C" void kernel_launch(void* const* d_in, const int* in_sizes, int n_in,
                              void* d_out, int out_size)
{
    const float* x   = (const float*)d_in[0];
    const float* Wq  = (const float*)d_in[1];
    const float* Wk  = (const float*)d_in[2];
    const float* Wv  = (const float*)d_in[3];
    const float* Wo  = (const float*)d_in[4];
    const float* bo  = (const float*)d_in[5];
    const float* W1  = (const float*)d_in[6];
    const float* b1  = (const float*)d_in[7];
    const float* W2  = (const float*)d_in[8];
    const float* b2  = (const float*)d_in[9];
    const float* g1  = (const float*)d_in[10];
    const float* be1 = (const float*)d_in[11];
    const float* g2  = (const float*)d_in[12];
    const float* be2 = (const float*)d_in[13];
    float* out = (float*)d_out;

    __nv_bfloat16 *h_hi, *h_lo, *qkv_hi, *qkv_lo, *at_hi, *at_lo, *ml_hi, *ml_lo;
    __nv_bfloat16 *wqkv_hi, *wqkv_lo, *wo_hi, *wo_lo, *w1_hi, *w1_lo, *w2_hi, *w2_lo;
    float *x1;
    cudaGetSymbolAddress((void**)&h_hi,   g_h_hi);
    cudaGetSymbolAddress((void**)&h_lo,   g_h_lo);
    cudaGetSymbolAddress((void**)&qkv_hi, g_qkv_hi);
    cudaGetSymbolAddress((void**)&qkv_lo, g_qkv_lo);
    cudaGetSymbolAddress((void**)&at_hi,  g_at_hi);
    cudaGetSymbolAddress((void**)&at_lo,  g_at_lo);
    cudaGetSymbolAddress((void**)&x1,     g_x1);
    cudaGetSymbolAddress((void**)&ml_hi,  g_ml_hi);
    cudaGetSymbolAddress((void**)&ml_lo,  g_ml_lo);
    cudaGetSymbolAddress((void**)&wqkv_hi, g_wqkv_hi);
    cudaGetSymbolAddress((void**)&wqkv_lo, g_wqkv_lo);
    cudaGetSymbolAddress((void**)&wo_hi, g_wo_hi);
    cudaGetSymbolAddress((void**)&wo_lo, g_wo_lo);
    cudaGetSymbolAddress((void**)&w1_hi, g_w1_hi);
    cudaGetSymbolAddress((void**)&w1_lo, g_w1_lo);
    cudaGetSymbolAddress((void**)&w2_hi, g_w2_hi);
    cudaGetSymbolAddress((void**)&w2_lo, g_w2_lo);

    cudaFuncSetAttribute(mma_gemm<3>,  cudaFuncAttributeMaxDynamicSharedMemorySize, GEMM_SMEM);
    cudaFuncSetAttribute(mma_gemm<8>,  cudaFuncAttributeMaxDynamicSharedMemorySize, GEMM_SMEM);
    cudaFuncSetAttribute(mma_gemm<13>, cudaFuncAttributeMaxDynamicSharedMemorySize, GEMM_SMEM);
    cudaFuncSetAttribute(flash_mma,    cudaFuncAttributeMaxDynamicSharedMemorySize, FLASH_SMEM);

    // ---- pre-split weights ----
    const int nW = CDIM * CDIM / 4;
    split_pack_kernel<<<(nW + 255) / 256, 256>>>((const float4*)Wq, wqkv_hi, wqkv_lo, 0);
    split_pack_kernel<<<(nW + 255) / 256, 256>>>((const float4*)Wk, wqkv_hi, wqkv_lo, 1024);
    split_pack_kernel<<<(nW + 255) / 256, 256>>>((const float4*)Wv, wqkv_hi, wqkv_lo, 2048);
    split_kernel<<<(nW + 255) / 256, 256>>>((const float4*)Wo,
        (__nv_bfloat162*)wo_hi, (__nv_bfloat162*)wo_lo, nW);
    const int nW1 = CDIM * FF / 4;
    split_kernel<<<(nW1 + 255) / 256, 256>>>((const float4*)W1,
        (__nv_bfloat162*)w1_hi, (__nv_bfloat162*)w1_lo, nW1);
    split_kernel<<<(nW1 + 255) / 256, 256>>>((const float4*)W2,
        (__nv_bfloat162*)w2_hi, (__nv_bfloat162*)w2_lo, nW1);

    const dim3 gQKV(QKVN / 128, MT / 128);   // (24, 64)
    const dim3 gC(CDIM / 128, MT / 128);     // (8, 64)
    const dim3 gF(FF / 128, MT / 128);       // (32, 64)

    // LN1 -> split h
    ln_kernel<<<MT, 256>>>((const float4*)x, (const float4*)g1,
                           (const float4*)be1, h_hi, h_lo);
    // fused QKV projection -> split qkv
    mma_gemm<8><<<gQKV, 256, GEMM_SMEM>>>(h_hi, h_lo, wqkv_hi, wqkv_lo,
        nullptr, nullptr, nullptr, qkv_hi, qkv_lo, MT, QKVN, CDIM);
    // tensor-core causal flash attention -> split attn
    flash_mma<<<dim3(TT / 64, HH, BB), 128, FLASH_SMEM>>>(qkv_hi, qkv_lo, at_hi, at_lo);
    // x1 = x + attn @ Wo + bo
    mma_gemm<3><<<gC, 256, GEMM_SMEM>>>(at_hi, at_lo, wo_hi, wo_lo,
        bo, x, x1, nullptr, nullptr, MT, CDIM, CDIM);
    // LN2 -> split h
    ln_kernel<<<MT, 256>>>((const float4*)x1, (const float4*)g2,
                           (const float4*)be2, h_hi, h_lo);
    // mlp = relu(h @ W1 + b1) -> split
    mma_gemm<13><<<gF, 256, GEMM_SMEM>>>(h_hi, h_lo, w1_hi, w1_lo,
        b1, nullptr, nullptr, ml_hi, ml_lo, MT, FF, CDIM);
    // out = x1 + mlp @ W2 + b2
    mma_gemm<3><<<gC, 256, GEMM_SMEM>>>(ml_hi, ml_lo, w2_hi, w2_lo,
        b2, x1, out, nullptr, nullptr, MT, CDIM, FF);
}

// round 11
// speedup vs baseline: 3.0325x; 1.0030x over previous
#include <cuda_runtime.h>
#include <cuda_bf16.h>
#include <cstdint>
#include <math.h>

// Problem dims
#define BB   4
#define TT   2048
#define MT   8192      // B*T
#define CDIM 1024
#define HH   16
#define DH   64
#define FF   4096
#define QKVN 3072

// ---------------- scratch (device globals; no allocation allowed) ----------
__device__ __nv_bfloat16 g_h_hi [MT * CDIM];
__device__ __nv_bfloat16 g_h_lo [MT * CDIM];
__device__ __nv_bfloat16 g_qkv_hi[(size_t)MT * QKVN];
__device__ __nv_bfloat16 g_qkv_lo[(size_t)MT * QKVN];
__device__ __nv_bfloat16 g_at_hi[MT * CDIM];
__device__ __nv_bfloat16 g_at_lo[MT * CDIM];
__device__ float         g_x1   [MT * CDIM];
__device__ __nv_bfloat16 g_ml_hi[(size_t)MT * FF];
__device__ __nv_bfloat16 g_ml_lo[(size_t)MT * FF];
// pre-split weights [K][N]
__device__ __nv_bfloat16 g_wqkv_hi[CDIM * QKVN];
__device__ __nv_bfloat16 g_wqkv_lo[CDIM * QKVN];
__device__ __nv_bfloat16 g_wo_hi [CDIM * CDIM];
__device__ __nv_bfloat16 g_wo_lo [CDIM * CDIM];
__device__ __nv_bfloat16 g_w1_hi [CDIM * FF];
__device__ __nv_bfloat16 g_w1_lo [CDIM * FF];
__device__ __nv_bfloat16 g_w2_hi [FF * CDIM];
__device__ __nv_bfloat16 g_w2_lo [FF * CDIM];

// ---------------- helpers ---------------------------------------------------
__device__ __forceinline__ uint32_t smem_addr32(const void* p) {
    return (uint32_t)__cvta_generic_to_shared(p);
}
__device__ __forceinline__ void cp16(void* smem, const void* g) {
    uint32_t s = smem_addr32(smem);
    asm volatile("cp.async.cg.shared.global [%0], [%1], 16;" :: "r"(s), "l"(g));
}
#define CP_COMMIT() asm volatile("cp.async.commit_group;")
#define CP_WAIT(n)  asm volatile("cp.async.wait_group %0;" :: "n"(n))

__device__ __forceinline__ void split2(float a, float b,
    __nv_bfloat162& hi, __nv_bfloat162& lo)
{
    hi.x = __float2bfloat16_rn(a);
    hi.y = __float2bfloat16_rn(b);
    lo.x = __float2bfloat16_rn(a - __bfloat162float(hi.x));
    lo.y = __float2bfloat16_rn(b - __bfloat162float(hi.y));
}
__device__ __forceinline__ float fexp2(float x) {
    float y;
    asm("ex2.approx.f32 %0, %1;" : "=f"(y) : "f"(x));
    return y;
}

// ---------------- split kernels --------------------------------------------
__global__ __launch_bounds__(256) void split_kernel(
    const float4* __restrict__ in, __nv_bfloat162* __restrict__ hi,
    __nv_bfloat162* __restrict__ lo, int n4)
{
    const int i = blockIdx.x * 256 + threadIdx.x;
    if (i >= n4) return;
    const float4 v = in[i];
    __nv_bfloat162 h0, h1, l0, l1;
    split2(v.x, v.y, h0, l0);
    split2(v.z, v.w, h1, l1);
    hi[i * 2]     = h0; hi[i * 2 + 1] = h1;
    lo[i * 2]     = l0; lo[i * 2 + 1] = l1;
}

__global__ __launch_bounds__(256) void split_pack_kernel(
    const float4* __restrict__ in, __nv_bfloat16* __restrict__ hi,
    __nv_bfloat16* __restrict__ lo, int coloff)
{
    const int i = blockIdx.x * 256 + threadIdx.x;
    if (i >= CDIM * CDIM / 4) return;
    const int r = i >> 8;
    const int c = (i & 255) * 4;
    const float4 v = in[i];
    __nv_bfloat162 h0, h1, l0, l1;
    split2(v.x, v.y, h0, l0);
    split2(v.z, v.w, h1, l1);
    const size_t o = (size_t)r * QKVN + coloff + c;
    *(__nv_bfloat162*)(hi + o)     = h0;
    *(__nv_bfloat162*)(hi + o + 2) = h1;
    *(__nv_bfloat162*)(lo + o)     = l0;
    *(__nv_bfloat162*)(lo + o + 2) = l1;
}

// ---------------- LayerNorm: emits bf16 hi/lo -------------------------------
__global__ __launch_bounds__(256) void ln_kernel(
    const float4* __restrict__ x, const float4* __restrict__ g,
    const float4* __restrict__ be,
    __nv_bfloat16* __restrict__ hi, __nv_bfloat16* __restrict__ lo)
{
    const int r = blockIdx.x;
    const int t = threadIdx.x;
    const float4 v = x[(size_t)r * (CDIM / 4) + t];
    float s  = v.x + v.y + v.z + v.w;
    float ss = v.x * v.x + v.y * v.y + v.z * v.z + v.w * v.w;
    #pragma unroll
    for (int o = 16; o > 0; o >>= 1) {
        s  += __shfl_down_sync(0xffffffffu, s,  o);
        ss += __shfl_down_sync(0xffffffffu, ss, o);
    }
    __shared__ float rs[8], rss[8];
    __shared__ float smu, sinv;
    const int w = t >> 5, lane = t & 31;
    if (lane == 0) { rs[w] = s; rss[w] = ss; }
    __syncthreads();
    if (t == 0) {
        float S = 0.f, SS = 0.f;
        #pragma unroll
        for (int i = 0; i < 8; i++) { S += rs[i]; SS += rss[i]; }
        const float mu  = S * (1.0f / CDIM);
        const float var = SS * (1.0f / CDIM) - mu * mu;
        smu = mu; sinv = rsqrtf(var + 1e-5f);
    }
    __syncthreads();
    const float mu = smu, inv = sinv;
    const float4 gv = g[t], bv = be[t];
    float a0 = (v.x - mu) * inv * gv.x + bv.x;
    float a1 = (v.y - mu) * inv * gv.y + bv.y;
    float a2 = (v.z - mu) * inv * gv.z + bv.z;
    float a3 = (v.w - mu) * inv * gv.w + bv.w;
    __nv_bfloat162 h0, h1, l0, l1;
    split2(a0, a1, h0, l0);
    split2(a2, a3, h1, l1);
    const size_t o = (size_t)r * CDIM + t * 4;
    *(__nv_bfloat162*)(hi + o)     = h0;
    *(__nv_bfloat162*)(hi + o + 2) = h1;
    *(__nv_bfloat162*)(lo + o)     = l0;
    *(__nv_bfloat162*)(lo + o + 2) = l1;
}

// ---------------- MMA macros ------------------------------------------------
#define LDMAT_X4(R0,R1,R2,R3,addr) \
    asm volatile("ldmatrix.sync.aligned.m8n8.x4.shared.b16 {%0,%1,%2,%3}, [%4];" \
        : "=r"(R0), "=r"(R1), "=r"(R2), "=r"(R3) : "r"(addr))
#define LDMAT_X4_T(R0,R1,R2,R3,addr) \
    asm volatile("ldmatrix.sync.aligned.m8n8.x4.trans.shared.b16 {%0,%1,%2,%3}, [%4];" \
        : "=r"(R0), "=r"(R1), "=r"(R2), "=r"(R3) : "r"(addr))
#define MMA16816(C, A0,A1,A2,A3, B0,B1) \
    asm volatile("mma.sync.aligned.m16n8k16.row.col.f32.bf16.bf16.f32 " \
        "{%0,%1,%2,%3},{%4,%5,%6,%7},{%8,%9},{%0,%1,%2,%3};" \
        : "+f"(C[0]), "+f"(C[1]), "+f"(C[2]), "+f"(C[3]) \
        : "r"(A0), "r"(A1), "r"(A2), "r"(A3), "r"(B0), "r"(B1))

// ---------------- pipelined bf16x3 tensor-core GEMM (3-stage) ---------------
// Inner MMAs emitted in 3 separate sweeps (hi*hi, lo*hi, hi*lo) so consecutive
// MMAs never share an accumulator -> no RAW serialization on the tensor pipe.
#define A_ST 5120                         // elems per A array per stage: 128*40
#define B_ST 4352                         // elems per B array per stage: 32*136
#define STG_ELEMS (2 * A_ST + 2 * B_ST)   // 18944 elems per stage
#define GEMM_SMEM (3 * STG_ELEMS * 2)     // 113664 bytes

template <int EPI>
__global__ __launch_bounds__(256, 1) void mma_gemm(
    const __nv_bfloat16* __restrict__ Ah, const __nv_bfloat16* __restrict__ Al,
    const __nv_bfloat16* __restrict__ Bh, const __nv_bfloat16* __restrict__ Bl,
    const float* __restrict__ bias, const float* __restrict__ res,
    float* __restrict__ C, __nv_bfloat16* __restrict__ Ch,
    __nv_bfloat16* __restrict__ Cl, int M, int N, int K)
{
    extern __shared__ char dynsmem[];
    __nv_bfloat16* base = (__nv_bfloat16*)dynsmem;

    const int tid  = threadIdx.x;
    const int warp = tid >> 5, lane = tid & 31;
    const int wm = (warp & 1) * 64;
    const int wn = (warp >> 1) * 32;
    const int bm = blockIdx.y * 128, bn = blockIdx.x * 128;

    float c[4][4][4];
    #pragma unroll
    for (int i = 0; i < 4; i++)
        #pragma unroll
        for (int j = 0; j < 4; j++)
            #pragma unroll
            for (int q = 0; q < 4; q++) c[i][j][q] = 0.f;

    const int a_r = tid >> 2, a_c = (tid & 3) * 8;
    const int b_r = tid >> 4, b_c = (tid & 15) * 8;

    auto load_stage = [&](int s, int k0) {
        __nv_bfloat16* st = base + s * STG_ELEMS;
        #pragma unroll
        for (int p = 0; p < 2; p++) {
            const int row = p * 64 + a_r;
            const size_t go = (size_t)(bm + row) * K + k0 + a_c;
            const int so = row * 40 + a_c;
            cp16(st + so,        Ah + go);
            cp16(st + A_ST + so, Al + go);
        }
        #pragma unroll
        for (int p = 0; p < 2; p++) {
            const int row = p * 16 + b_r;
            const size_t go = (size_t)(k0 + row) * N + bn + b_c;
            const int so = 2 * A_ST + row * 136 + b_c;
            cp16(st + so,        Bh + go);
            cp16(st + B_ST + so, Bl + go);
        }
    };

    const int nk = K / 32;
    load_stage(0, 0);
    CP_COMMIT();
    if (nk > 1) load_stage(1, 32);
    CP_COMMIT();

    for (int ki = 0; ki < nk; ki++) {
        CP_WAIT(1);
        __syncthreads();
        if (ki + 2 < nk) load_stage((ki + 2) % 3, (ki + 2) * 32);
        CP_COMMIT();

        const uint32_t st_b = smem_addr32(base + (ki % 3) * STG_ELEMS);
        const uint32_t ah_b = st_b;
        const uint32_t al_b = st_b + A_ST * 2;
        const uint32_t bh_b = st_b + 4 * A_ST;
        const uint32_t bl_b = bh_b + B_ST * 2;

        #pragma unroll
        for (int ks = 0; ks < 32; ks += 16) {
            uint32_t ah[4][4], al[4][4], bh[2][4], bl[2][4];
            #pragma unroll
            for (int mt = 0; mt < 4; mt++) {
                const int r  = wm + mt * 16 + (lane & 15);
                const int cc = ks + 8 * (lane >> 4);
                const uint32_t off = (uint32_t)(r * 40 + cc) * 2;
                LDMAT_X4(ah[mt][0], ah[mt][1], ah[mt][2], ah[mt][3], ah_b + off);
                LDMAT_X4(al[mt][0], al[mt][1], al[mt][2], al[mt][3], al_b + off);
            }
            #pragma unroll
            for (int ng = 0; ng < 2; ng++) {
                const int r  = ks + (lane & 15);
                const int cc = wn + ng * 16 + 8 * (lane >> 4);
                const uint32_t off = (uint32_t)(r * 136 + cc) * 2;
                LDMAT_X4_T(bh[ng][0], bh[ng][1], bh[ng][2], bh[ng][3], bh_b + off);
                LDMAT_X4_T(bl[ng][0], bl[ng][1], bl[ng][2], bl[ng][3], bl_b + off);
            }
            // sweep 1: hi * hi  (16 distinct accumulators back-to-back)
            #pragma unroll
            for (int mt = 0; mt < 4; mt++)
                #pragma unroll
                for (int nt = 0; nt < 4; nt++) {
                    const int ng = nt >> 1, hf = (nt & 1) * 2;
                    MMA16816(c[mt][nt], ah[mt][0], ah[mt][1], ah[mt][2], ah[mt][3],
                             bh[ng][hf], bh[ng][hf + 1]);
                }
            // sweep 2: lo * hi
            #pragma unroll
            for (int mt = 0; mt < 4; mt++)
                #pragma unroll
                for (int nt = 0; nt < 4; nt++) {
                    const int ng = nt >> 1, hf = (nt & 1) * 2;
                    MMA16816(c[mt][nt], al[mt][0], al[mt][1], al[mt][2], al[mt][3],
                             bh[ng][hf], bh[ng][hf + 1]);
                }
            // sweep 3: hi * lo
            #pragma unroll
            for (int mt = 0; mt < 4; mt++)
                #pragma unroll
                for (int nt = 0; nt < 4; nt++) {
                    const int ng = nt >> 1, hf = (nt & 1) * 2;
                    MMA16816(c[mt][nt], ah[mt][0], ah[mt][1], ah[mt][2], ah[mt][3],
                             bl[ng][hf], bl[ng][hf + 1]);
                }
        }
    }

    const int gg = lane >> 2;
    const int qq = (lane & 3) * 2;
    #pragma unroll
    for (int mt = 0; mt < 4; mt++) {
        #pragma unroll
        for (int nt = 0; nt < 4; nt++) {
            const int col = bn + wn + nt * 8 + qq;
            #pragma unroll
            for (int hrow = 0; hrow < 2; hrow++) {
                const int row = bm + wm + mt * 16 + gg + hrow * 8;
                float2 v;
                v.x = c[mt][nt][hrow * 2 + 0];
                v.y = c[mt][nt][hrow * 2 + 1];
                const size_t idx = (size_t)row * N + col;
                if (EPI & 1) {
                    const float2 b2 = *(const float2*)(bias + col);
                    v.x += b2.x; v.y += b2.y;
                }
                if (EPI & 4) { v.x = fmaxf(v.x, 0.f); v.y = fmaxf(v.y, 0.f); }
                if (EPI & 2) {
                    const float2 r2 = *(const float2*)(res + idx);
                    v.x += r2.x; v.y += r2.y;
                }
                if (EPI & 8) {
                    __nv_bfloat162 h2, l2;
                    split2(v.x, v.y, h2, l2);
                    *(__nv_bfloat162*)(Ch + idx) = h2;
                    *(__nv_bfloat162*)(Cl + idx) = l2;
                } else {
                    *(float2*)(C + idx) = v;
                }
            }
        }
    }
}

// ---------------- tensor-core flash attention (causal, bf16x3) --------------
#define FST   72
#define FTILE (64 * FST)
#define FLASH_SMEM (2 * 4 * FTILE * 2)   // 73728 bytes

__global__ __launch_bounds__(128) void flash_mma(
    const __nv_bfloat16* __restrict__ Gh, const __nv_bfloat16* __restrict__ Gl,
    __nv_bfloat16* __restrict__ Ohi, __nv_bfloat16* __restrict__ Olo)
{
    extern __shared__ __nv_bfloat16 fsm[];
    const int qt = 31 - blockIdx.x;
    const int h = blockIdx.y, b = blockIdx.z;
    const int tid = threadIdx.x, warp = tid >> 5, lane = tid & 31;
    const size_t qrow0 = (size_t)(b * TT + qt * 64);
    const float SC = 0.180336880f;

    const int lr = tid >> 1;
    const int lc = (tid & 1) * 4;
    auto load_one = [&](__nv_bfloat16* dst, const __nv_bfloat16* src) {
        #pragma unroll
        for (int i = 0; i < 4; i++)
            cp16(dst + lr * FST + (lc + i) * 8, src + (size_t)lr * QKVN + (lc + i) * 8);
    };
    auto load_kv = [&](int s, int kt) {
        const size_t krow = (size_t)(b * TT + kt * 64);
        load_one(fsm + (s * 4 + 0) * FTILE, Gh + krow * QKVN + CDIM + h * DH);
        load_one(fsm + (s * 4 + 1) * FTILE, Gl + krow * QKVN + CDIM + h * DH);
        load_one(fsm + (s * 4 + 2) * FTILE, Gh + krow * QKVN + 2 * CDIM + h * DH);
        load_one(fsm + (s * 4 + 3) * FTILE, Gl + krow * QKVN + 2 * CDIM + h * DH);
    };

    load_one(fsm + 0 * FTILE, Gh + qrow0 * QKVN + h * DH);
    load_one(fsm + 1 * FTILE, Gl + qrow0 * QKVN + h * DH);
    CP_COMMIT(); CP_WAIT(0);
    __syncthreads();
    uint32_t Qh[4][4], Ql[4][4];
    #pragma unroll
    for (int t = 0; t < 4; t++) {
        const uint32_t off = (uint32_t)((warp * 16 + (lane & 15)) * FST
                                        + t * 16 + 8 * (lane >> 4)) * 2;
        LDMAT_X4(Qh[t][0], Qh[t][1], Qh[t][2], Qh[t][3], smem_addr32(fsm) + off);
        LDMAT_X4(Ql[t][0], Ql[t][1], Ql[t][2], Ql[t][3], smem_addr32(fsm + FTILE) + off);
    }
    __syncthreads();

    float O[8][4];
    #pragma unroll
    for (int i = 0; i < 8; i++)
        #pragma unroll
        for (int j = 0; j < 4; j++) O[i][j] = 0.f;
    float m0 = -1e30f, m1 = -1e30f, l0 = 0.f, l1 = 0.f;

    load_kv(0, 0);
    CP_COMMIT();

    for (int kt = 0; kt <= qt; kt++) {
        const int s = kt & 1;
        if (kt < qt) { load_kv(s ^ 1, kt + 1); CP_COMMIT(); CP_WAIT(1); }
        else         { CP_WAIT(0); }
        __syncthreads();

        const uint32_t kh_b = smem_addr32(fsm + (s * 4 + 0) * FTILE);
        const uint32_t kl_b = smem_addr32(fsm + (s * 4 + 1) * FTILE);
        const uint32_t vh_b = smem_addr32(fsm + (s * 4 + 2) * FTILE);
        const uint32_t vl_b = smem_addr32(fsm + (s * 4 + 3) * FTILE);

        // ---- S = Q K^T (bf16x3, sweep-ordered) ----
        float sv[8][4];
        #pragma unroll
        for (int i = 0; i < 8; i++)
            #pragma unroll
            for (int j = 0; j < 4; j++) sv[i][j] = 0.f;

        #pragma unroll
        for (int t = 0; t < 4; t++) {
            uint32_t kf[4][4];
            #pragma unroll
            for (int g4 = 0; g4 < 4; g4++) {
                const uint32_t off = (uint32_t)((g4 * 16 + (lane & 15)) * FST
                                                + t * 16 + 8 * (lane >> 4)) * 2;
                LDMAT_X4(kf[g4][0], kf[g4][1], kf[g4][2], kf[g4][3], kh_b + off);
            }
            // sweep 1: Qh x Kh over all 8 accumulators
            #pragma unroll
            for (int g4 = 0; g4 < 4; g4++) {
                MMA16816(sv[g4 * 2],     Qh[t][0], Qh[t][1], Qh[t][2], Qh[t][3], kf[g4][0], kf[g4][2]);
                MMA16816(sv[g4 * 2 + 1], Qh[t][0], Qh[t][1], Qh[t][2], Qh[t][3], kf[g4][1], kf[g4][3]);
            }
            // sweep 2: Ql x Kh
            #pragma unroll
            for (int g4 = 0; g4 < 4; g4++) {
                MMA16816(sv[g4 * 2],     Ql[t][0], Ql[t][1], Ql[t][2], Ql[t][3], kf[g4][0], kf[g4][2]);
                MMA16816(sv[g4 * 2 + 1], Ql[t][0], Ql[t][1], Ql[t][2], Ql[t][3], kf[g4][1], kf[g4][3]);
            }
            // reload frags with K-lo, sweep 3: Qh x Kl
            #pragma unroll
            for (int g4 = 0; g4 < 4; g4++) {
                const uint32_t off = (uint32_t)((g4 * 16 + (lane & 15)) * FST
                                                + t * 16 + 8 * (lane >> 4)) * 2;
                LDMAT_X4(kf[g4][0], kf[g4][1], kf[g4][2], kf[g4][3], kl_b + off);
            }
            #pragma unroll
            for (int g4 = 0; g4 < 4; g4++) {
                MMA16816(sv[g4 * 2],     Qh[t][0], Qh[t][1], Qh[t][2], Qh[t][3], kf[g4][0], kf[g4][2]);
                MMA16816(sv[g4 * 2 + 1], Qh[t][0], Qh[t][1], Qh[t][2], Qh[t][3], kf[g4][1], kf[g4][3]);
            }
        }

        // ---- causal mask on diagonal tile ----
        const int rl0 = warp * 16 + (lane >> 2);
        if (kt == qt) {
            #pragma unroll
            for (int nt = 0; nt < 8; nt++) {
                const int cl = nt * 8 + (lane & 3) * 2;
                if (cl     > rl0)     sv[nt][0] = -1e30f;
                if (cl + 1 > rl0)     sv[nt][1] = -1e30f;
                if (cl     > rl0 + 8) sv[nt][2] = -1e30f;
                if (cl + 1 > rl0 + 8) sv[nt][3] = -1e30f;
            }
        }

        // ---- online softmax ----
        float mx0 = -1e30f, mx1 = -1e30f;
        #pragma unroll
        for (int nt = 0; nt < 8; nt++) {
            mx0 = fmaxf(mx0, fmaxf(sv[nt][0], sv[nt][1]));
            mx1 = fmaxf(mx1, fmaxf(sv[nt][2], sv[nt][3]));
        }
        mx0 = fmaxf(mx0, __shfl_xor_sync(0xffffffffu, mx0, 1));
        mx0 = fmaxf(mx0, __shfl_xor_sync(0xffffffffu, mx0, 2));
        mx1 = fmaxf(mx1, __shfl_xor_sync(0xffffffffu, mx1, 1));
        mx1 = fmaxf(mx1, __shfl_xor_sync(0xffffffffu, mx1, 2));
        const float mn0 = fmaxf(m0, mx0), mn1 = fmaxf(m1, mx1);
        const float corr0 = fexp2((m0 - mn0) * SC);
        const float corr1 = fexp2((m1 - mn1) * SC);

        uint32_t pAh[4][4], pAl[4][4];
        float ps0 = 0.f, ps1 = 0.f;
        #pragma unroll
        for (int nt = 0; nt < 8; nt++) {
            const float p0 = fexp2((sv[nt][0] - mn0) * SC);
            const float p1 = fexp2((sv[nt][1] - mn0) * SC);
            const float p2 = fexp2((sv[nt][2] - mn1) * SC);
            const float p3 = fexp2((sv[nt][3] - mn1) * SC);
            ps0 += p0 + p1; ps1 += p2 + p3;
            __nv_bfloat162 h01, l01, h23, l23;
            split2(p0, p1, h01, l01);
            split2(p2, p3, h23, l23);
            const int t = nt >> 1, o = (nt & 1) * 2;
            pAh[t][o]     = *(uint32_t*)&h01;
            pAh[t][o + 1] = *(uint32_t*)&h23;
            pAl[t][o]     = *(uint32_t*)&l01;
            pAl[t][o + 1] = *(uint32_t*)&l23;
        }
        ps0 += __shfl_xor_sync(0xffffffffu, ps0, 1);
        ps0 += __shfl_xor_sync(0xffffffffu, ps0, 2);
        ps1 += __shfl_xor_sync(0xffffffffu, ps1, 1);
        ps1 += __shfl_xor_sync(0xffffffffu, ps1, 2);
        l0 = l0 * corr0 + ps0;
        l1 = l1 * corr1 + ps1;
        m0 = mn0; m1 = mn1;

        #pragma unroll
        for (int dt = 0; dt < 8; dt++) {
            O[dt][0] *= corr0; O[dt][1] *= corr0;
            O[dt][2] *= corr1; O[dt][3] *= corr1;
        }

        // ---- O += P V (bf16x3, sweep-ordered) ----
        #pragma unroll
        for (int t = 0; t < 4; t++) {
            uint32_t vf[4][4];
            #pragma unroll
            for (int g4 = 0; g4 < 4; g4++) {
                const uint32_t off = (uint32_t)((t * 16 + (lane & 15)) * FST
                                                + g4 * 16 + 8 * (lane >> 4)) * 2;
                LDMAT_X4_T(vf[g4][0], vf[g4][1], vf[g4][2], vf[g4][3], vh_b + off);
            }
            // sweep 1: Ph x Vh
            #pragma unroll
            for (int g4 = 0; g4 < 4; g4++) {
                MMA16816(O[g4 * 2],     pAh[t][0], pAh[t][1], pAh[t][2], pAh[t][3], vf[g4][0], vf[g4][1]);
                MMA16816(O[g4 * 2 + 1], pAh[t][0], pAh[t][1], pAh[t][2], pAh[t][3], vf[g4][2], vf[g4][3]);
            }
            // sweep 2: Pl x Vh
            #pragma unroll
            for (int g4 = 0; g4 < 4; g4++) {
                MMA16816(O[g4 * 2],     pAl[t][0], pAl[t][1], pAl[t][2], pAl[t][3], vf[g4][0], vf[g4][1]);
                MMA16816(O[g4 * 2 + 1], pAl[t][0], pAl[t][1], pAl[t][2], pAl[t][3], vf[g4][2], vf[g4][3]);
            }
            // reload frags with V-lo, sweep 3: Ph x Vl
            #pragma unroll
            for (int g4 = 0; g4 < 4; g4++) {
                const uint32_t off = (uint32_t)((t * 16 + (lane & 15)) * FST
                                                + g4 * 16 + 8 * (lane >> 4)) * 2;
                LDMAT_X4_T(vf[g4][0], vf[g4][1], vf[g4][2], vf[g4][3], vl_b + off);
            }
            #pragma unroll
            for (int g4 = 0; g4 < 4; g4++) {
                MMA16816(O[g4 * 2],     pAh[t][0], pAh[t][1], pAh[t][2], pAh[t][3], vf[g4][0], vf[g4][1]);
                MMA16816(O[g4 * 2 + 1], pAh[t][0], pAh[t][1], pAh[t][2], pAh[t][3], vf[g4][2], vf[g4][3]);
            }
        }
        __syncthreads();
    }

    const float inv0 = 1.f / l0, inv1 = 1.f / l1;
    const int rl0 = warp * 16 + (lane >> 2);
    #pragma unroll
    for (int dt = 0; dt < 8; dt++) {
        const int d = h * DH + dt * 8 + (lane & 3) * 2;
        __nv_bfloat162 hh, ll;
        const size_t i0 = (qrow0 + rl0) * CDIM + d;
        split2(O[dt][0] * inv0, O[dt][1] * inv0, hh, ll);
        *(__nv_bfloat162*)(Ohi + i0) = hh;
        *(__nv_bfloat162*)(Olo + i0) = ll;
        const size_t i1 = (qrow0 + rl0 + 8) * CDIM + d;
        split2(O[dt][2] * inv1, O[dt][3] * inv1, hh, ll);
        *(__nv_bfloat162*)(Ohi + i1) = hh;
        *(__nv_bfloat162*)(Olo + i1) = ll;
    }
}

// ---------------- launch ----------------------------------------------------
extern "C" void kernel_launch(void* const* d_in, const int* in_sizes, int n_in,
                              void* d_out, int out_size)
{
    const float* x   = (const float*)d_in[0];
    const float* Wq  = (const float*)d_in[1];
    const float* Wk  = (const float*)d_in[2];
    const float* Wv  = (const float*)d_in[3];
    const float* Wo  = (const float*)d_in[4];
    const float* bo  = (const float*)d_in[5];
    const float* W1  = (const float*)d_in[6];
    const float* b1  = (const float*)d_in[7];
    const float* W2  = (const float*)d_in[8];
    const float* b2  = (const float*)d_in[9];
    const float* g1  = (const float*)d_in[10];
    const float* be1 = (const float*)d_in[11];
    const float* g2  = (const float*)d_in[12];
    const float* be2 = (const float*)d_in[13];
    float* out = (float*)d_out;

    __nv_bfloat16 *h_hi, *h_lo, *qkv_hi, *qkv_lo, *at_hi, *at_lo, *ml_hi, *ml_lo;
    __nv_bfloat16 *wqkv_hi, *wqkv_lo, *wo_hi, *wo_lo, *w1_hi, *w1_lo, *w2_hi, *w2_lo;
    float *x1;
    cudaGetSymbolAddress((void**)&h_hi,   g_h_hi);
    cudaGetSymbolAddress((void**)&h_lo,   g_h_lo);
    cudaGetSymbolAddress((void**)&qkv_hi, g_qkv_hi);
    cudaGetSymbolAddress((void**)&qkv_lo, g_qkv_lo);
    cudaGetSymbolAddress((void**)&at_hi,  g_at_hi);
    cudaGetSymbolAddress((void**)&at_lo,  g_at_lo);
    cudaGetSymbolAddress((void**)&x1,     g_x1);
    cudaGetSymbolAddress((void**)&ml_hi,  g_ml_hi);
    cudaGetSymbolAddress((void**)&ml_lo,  g_ml_lo);
    cudaGetSymbolAddress((void**)&wqkv_hi, g_wqkv_hi);
    cudaGetSymbolAddress((void**)&wqkv_lo, g_wqkv_lo);
    cudaGetSymbolAddress((void**)&wo_hi, g_wo_hi);
    cudaGetSymbolAddress((void**)&wo_lo, g_wo_lo);
    cudaGetSymbolAddress((void**)&w1_hi, g_w1_hi);
    cudaGetSymbolAddress((void**)&w1_lo, g_w1_lo);
    cudaGetSymbolAddress((void**)&w2_hi, g_w2_hi);
    cudaGetSymbolAddress((void**)&w2_lo, g_w2_lo);

    cudaFuncSetAttribute(mma_gemm<3>,  cudaFuncAttributeMaxDynamicSharedMemorySize, GEMM_SMEM);
    cudaFuncSetAttribute(mma_gemm<8>,  cudaFuncAttributeMaxDynamicSharedMemorySize, GEMM_SMEM);
    cudaFuncSetAttribute(mma_gemm<13>, cudaFuncAttributeMaxDynamicSharedMemorySize, GEMM_SMEM);
    cudaFuncSetAttribute(flash_mma,    cudaFuncAttributeMaxDynamicSharedMemorySize, FLASH_SMEM);

    // ---- pre-split weights ----
    const int nW = CDIM * CDIM / 4;
    split_pack_kernel<<<(nW + 255) / 256, 256>>>((const float4*)Wq, wqkv_hi, wqkv_lo, 0);
    split_pack_kernel<<<(nW + 255) / 256, 256>>>((const float4*)Wk, wqkv_hi, wqkv_lo, 1024);
    split_pack_kernel<<<(nW + 255) / 256, 256>>>((const float4*)Wv, wqkv_hi, wqkv_lo, 2048);
    split_kernel<<<(nW + 255) / 256, 256>>>((const float4*)Wo,
        (__nv_bfloat162*)wo_hi, (__nv_bfloat162*)wo_lo, nW);
    const int nW1 = CDIM * FF / 4;
    split_kernel<<<(nW1 + 255) / 256, 256>>>((const float4*)W1,
        (__nv_bfloat162*)w1_hi, (__nv_bfloat162*)w1_lo, nW1);
    split_kernel<<<(nW1 + 255) / 256, 256>>>((const float4*)W2,
        (__nv_bfloat162*)w2_hi, (__nv_bfloat162*)w2_lo, nW1);

    const dim3 gQKV(QKVN / 128, MT / 128);   // (24, 64)
    const dim3 gC(CDIM / 128, MT / 128);     // (8, 64)
    const dim3 gF(FF / 128, MT / 128);       // (32, 64)

    // LN1 -> split h
    ln_kernel<<<MT, 256>>>((const float4*)x, (const float4*)g1,
                           (const float4*)be1, h_hi, h_lo);
    // fused QKV projection -> split qkv
    mma_gemm<8><<<gQKV, 256, GEMM_SMEM>>>(h_hi, h_lo, wqkv_hi, wqkv_lo,
        nullptr, nullptr, nullptr, qkv_hi, qkv_lo, MT, QKVN, CDIM);
    // tensor-core causal flash attention -> split attn
    flash_mma<<<dim3(TT / 64, HH, BB), 128, FLASH_SMEM>>>(qkv_hi, qkv_lo, at_hi, at_lo);
    // x1 = x + attn @ Wo + bo
    mma_gemm<3><<<gC, 256, GEMM_SMEM>>>(at_hi, at_lo, wo_hi, wo_lo,
        bo, x, x1, nullptr, nullptr, MT, CDIM, CDIM);
    // LN2 -> split h
    ln_kernel<<<MT, 256>>>((const float4*)x1, (const float4*)g2,
                           (const float4*)be2, h_hi, h_lo);
    // mlp = relu(h @ W1 + b1) -> split
    mma_gemm<13><<<gF, 256, GEMM_SMEM>>>(h_hi, h_lo, w1_hi, w1_lo,
        b1, nullptr, nullptr, ml_hi, ml_lo, MT, FF, CDIM);
    // out = x1 + mlp @ W2 + b2
    mma_gemm<3><<<gC, 256, GEMM_SMEM>>>(ml_hi, ml_lo, w2_hi, w2_lo,
        b2, x1, out, nullptr, nullptr, MT, CDIM, FF);
}

// round 13
// speedup vs baseline: 3.6254x; 1.1955x over previous
#include <cuda_runtime.h>
#include <cuda_bf16.h>
#include <cuda_fp16.h>
#include <cstdint>
#include <math.h>

// Problem dims
#define BB   4
#define TT   2048
#define MT   8192      // B*T
#define CDIM 1024
#define HH   16
#define DH   64
#define FF   4096
#define QKVN 3072

// ---------------- scratch (device globals; no allocation allowed) ----------
__device__ __nv_bfloat16 g_h_hi [MT * CDIM];   // LN out (bf16 for LN1, reused as f16 for LN2)
__device__ __nv_bfloat16 g_h_lo [MT * CDIM];
__device__ __nv_bfloat16 g_qkv_hi[(size_t)MT * QKVN];
__device__ __nv_bfloat16 g_qkv_lo[(size_t)MT * QKVN];
__device__ __half        g_at_hi[MT * CDIM];
__device__ __half        g_at_lo[MT * CDIM];
__device__ float         g_x1   [MT * CDIM];
__device__ __half        g_ml_hi[(size_t)MT * FF];
__device__ __half        g_ml_lo[(size_t)MT * FF];
// weights: QKV bf16 hi/lo [K][N]; Wo/W1/W2 single f16 [K][N]
__device__ __nv_bfloat16 g_wqkv_hi[CDIM * QKVN];
__device__ __nv_bfloat16 g_wqkv_lo[CDIM * QKVN];
__device__ __half        g_wo_f [CDIM * CDIM];
__device__ __half        g_w1_f [CDIM * FF];
__device__ __half        g_w2_f [FF * CDIM];

// ---------------- helpers ---------------------------------------------------
__device__ __forceinline__ uint32_t smem_addr32(const void* p) {
    return (uint32_t)__cvta_generic_to_shared(p);
}
__device__ __forceinline__ void cp16(void* smem, const void* g) {
    uint32_t s = smem_addr32(smem);
    asm volatile("cp.async.cg.shared.global [%0], [%1], 16;" :: "r"(s), "l"(g));
}
#define CP_COMMIT() asm volatile("cp.async.commit_group;")
#define CP_WAIT(n)  asm volatile("cp.async.wait_group %0;" :: "n"(n))

__device__ __forceinline__ void split2(float a, float b,
    __nv_bfloat162& hi, __nv_bfloat162& lo)
{
    hi.x = __float2bfloat16_rn(a);
    hi.y = __float2bfloat16_rn(b);
    lo.x = __float2bfloat16_rn(a - __bfloat162float(hi.x));
    lo.y = __float2bfloat16_rn(b - __bfloat162float(hi.y));
}
__device__ __forceinline__ void split2(float a, float b,
    __half2& hi, __half2& lo)
{
    hi.x = __float2half_rn(a);
    hi.y = __float2half_rn(b);
    lo.x = __float2half_rn(a - __half2float(hi.x));
    lo.y = __float2half_rn(b - __half2float(hi.y));
}
template <typename T> struct vec2of;
template <> struct vec2of<__nv_bfloat16> { using t = __nv_bfloat162; };
template <> struct vec2of<__half>        { using t = __half2; };

__device__ __forceinline__ float fexp2(float x) {
    float y;
    asm("ex2.approx.f32 %0, %1;" : "=f"(y) : "f"(x));
    return y;
}

// ---------------- weight prep kernels ---------------------------------------
__global__ __launch_bounds__(256) void split_pack_kernel(
    const float4* __restrict__ in, __nv_bfloat16* __restrict__ hi,
    __nv_bfloat16* __restrict__ lo, int coloff)
{
    const int i = blockIdx.x * 256 + threadIdx.x;
    if (i >= CDIM * CDIM / 4) return;
    const int r = i >> 8;
    const int c = (i & 255) * 4;
    const float4 v = in[i];
    __nv_bfloat162 h0, h1, l0, l1;
    split2(v.x, v.y, h0, l0);
    split2(v.z, v.w, h1, l1);
    const size_t o = (size_t)r * QKVN + coloff + c;
    *(__nv_bfloat162*)(hi + o)     = h0;
    *(__nv_bfloat162*)(hi + o + 2) = h1;
    *(__nv_bfloat162*)(lo + o)     = l0;
    *(__nv_bfloat162*)(lo + o + 2) = l1;
}

__global__ __launch_bounds__(256) void tof16_kernel(
    const float4* __restrict__ in, __half2* __restrict__ o, int n4)
{
    const int i = blockIdx.x * 256 + threadIdx.x;
    if (i >= n4) return;
    const float4 v = in[i];
    o[i * 2]     = __floats2half2_rn(v.x, v.y);
    o[i * 2 + 1] = __floats2half2_rn(v.z, v.w);
}

// ---------------- LayerNorm: emits hi/lo in T --------------------------------
template <typename T>
__global__ __launch_bounds__(256) void ln_kernel(
    const float4* __restrict__ x, const float4* __restrict__ g,
    const float4* __restrict__ be, T* __restrict__ hi, T* __restrict__ lo)
{
    using V2 = typename vec2of<T>::t;
    const int r = blockIdx.x;
    const int t = threadIdx.x;
    const float4 v = x[(size_t)r * (CDIM / 4) + t];
    float s  = v.x + v.y + v.z + v.w;
    float ss = v.x * v.x + v.y * v.y + v.z * v.z + v.w * v.w;
    #pragma unroll
    for (int o = 16; o > 0; o >>= 1) {
        s  += __shfl_down_sync(0xffffffffu, s,  o);
        ss += __shfl_down_sync(0xffffffffu, ss, o);
    }
    __shared__ float rs[8], rss[8];
    __shared__ float smu, sinv;
    const int w = t >> 5, lane = t & 31;
    if (lane == 0) { rs[w] = s; rss[w] = ss; }
    __syncthreads();
    if (t == 0) {
        float S = 0.f, SS = 0.f;
        #pragma unroll
        for (int i = 0; i < 8; i++) { S += rs[i]; SS += rss[i]; }
        const float mu  = S * (1.0f / CDIM);
        const float var = SS * (1.0f / CDIM) - mu * mu;
        smu = mu; sinv = rsqrtf(var + 1e-5f);
    }
    __syncthreads();
    const float mu = smu, inv = sinv;
    const float4 gv = g[t], bv = be[t];
    float a0 = (v.x - mu) * inv * gv.x + bv.x;
    float a1 = (v.y - mu) * inv * gv.y + bv.y;
    float a2 = (v.z - mu) * inv * gv.z + bv.z;
    float a3 = (v.w - mu) * inv * gv.w + bv.w;
    V2 h0, h1, l0, l1;
    split2(a0, a1, h0, l0);
    split2(a2, a3, h1, l1);
    const size_t o = (size_t)r * CDIM + t * 4;
    *(V2*)(hi + o)     = h0;
    *(V2*)(hi + o + 2) = h1;
    *(V2*)(lo + o)     = l0;
    *(V2*)(lo + o + 2) = l1;
}

// ---------------- MMA macros ------------------------------------------------
#define LDMAT_X4(R0,R1,R2,R3,addr) \
    asm volatile("ldmatrix.sync.aligned.m8n8.x4.shared.b16 {%0,%1,%2,%3}, [%4];" \
        : "=r"(R0), "=r"(R1), "=r"(R2), "=r"(R3) : "r"(addr))
#define LDMAT_X4_T(R0,R1,R2,R3,addr) \
    asm volatile("ldmatrix.sync.aligned.m8n8.x4.trans.shared.b16 {%0,%1,%2,%3}, [%4];" \
        : "=r"(R0), "=r"(R1), "=r"(R2), "=r"(R3) : "r"(addr))
#define MMA16816(C, A0,A1,A2,A3, B0,B1) \
    asm volatile("mma.sync.aligned.m16n8k16.row.col.f32.bf16.bf16.f32 " \
        "{%0,%1,%2,%3},{%4,%5,%6,%7},{%8,%9},{%0,%1,%2,%3};" \
        : "+f"(C[0]), "+f"(C[1]), "+f"(C[2]), "+f"(C[3]) \
        : "r"(A0), "r"(A1), "r"(A2), "r"(A3), "r"(B0), "r"(B1))
#define MMA16816F(C, A0,A1,A2,A3, B0,B1) \
    asm volatile("mma.sync.aligned.m16n8k16.row.col.f32.f16.f16.f32 " \
        "{%0,%1,%2,%3},{%4,%5,%6,%7},{%8,%9},{%0,%1,%2,%3};" \
        : "+f"(C[0]), "+f"(C[1]), "+f"(C[2]), "+f"(C[3]) \
        : "r"(A0), "r"(A1), "r"(A2), "r"(A3), "r"(B0), "r"(B1))

// ---------------- pipelined split-precision tensor-core GEMM (3-stage) ------
// TERMS==3 (bf16x3): Ah*Bh + Al*Bh + Ah*Bl.  TERMS==2 (f16x2): Ah*B + Al*B.
// EPI bit0:+bias bit1:+residual bit2:relu bit3:split-T out (bias->relu->res)
#define A_ST 5120                         // elems per A array per stage: 128*40
#define B_ST 4352                         // elems per B array per stage: 32*136

template <int TERMS, int EPI, typename AT>
__global__ __launch_bounds__(256, 1) void mma_gemm(
    const AT* __restrict__ Ah, const AT* __restrict__ Al,
    const AT* __restrict__ Bh, const AT* __restrict__ Bl,
    const float* __restrict__ bias, const float* __restrict__ res,
    float* __restrict__ C, AT* __restrict__ Ch,
    AT* __restrict__ Cl, int M, int N, int K)
{
    constexpr bool F16 = (TERMS == 2);
    constexpr int STG_ELEMS = 2 * A_ST + (TERMS == 3 ? 2 : 1) * B_ST;
    extern __shared__ char dynsmem[];
    AT* base = (AT*)dynsmem;

    const int tid  = threadIdx.x;
    const int warp = tid >> 5, lane = tid & 31;
    const int wm = (warp & 1) * 64;
    const int wn = (warp >> 1) * 32;
    const int bm = blockIdx.y * 128, bn = blockIdx.x * 128;

    float c[4][4][4];
    #pragma unroll
    for (int i = 0; i < 4; i++)
        #pragma unroll
        for (int j = 0; j < 4; j++)
            #pragma unroll
            for (int q = 0; q < 4; q++) c[i][j][q] = 0.f;

    const int a_r = tid >> 2, a_c = (tid & 3) * 8;
    const int b_r = tid >> 4, b_c = (tid & 15) * 8;

    auto load_stage = [&](int s, int k0) {
        AT* st = base + s * STG_ELEMS;
        #pragma unroll
        for (int p = 0; p < 2; p++) {
            const int row = p * 64 + a_r;
            const size_t go = (size_t)(bm + row) * K + k0 + a_c;
            const int so = row * 40 + a_c;
            cp16(st + so,        Ah + go);
            cp16(st + A_ST + so, Al + go);
        }
        #pragma unroll
        for (int p = 0; p < 2; p++) {
            const int row = p * 16 + b_r;
            const size_t go = (size_t)(k0 + row) * N + bn + b_c;
            const int so = 2 * A_ST + row * 136 + b_c;
            cp16(st + so, Bh + go);
            if constexpr (TERMS == 3)
                cp16(st + B_ST + so, Bl + go);
        }
    };

    const int nk = K / 32;
    load_stage(0, 0);
    CP_COMMIT();
    if (nk > 1) load_stage(1, 32);
    CP_COMMIT();

    for (int ki = 0; ki < nk; ki++) {
        CP_WAIT(1);
        __syncthreads();
        if (ki + 2 < nk) load_stage((ki + 2) % 3, (ki + 2) * 32);
        CP_COMMIT();

        const uint32_t st_b = smem_addr32(base + (ki % 3) * STG_ELEMS);
        const uint32_t ah_b = st_b;
        const uint32_t al_b = st_b + A_ST * 2;
        const uint32_t bh_b = st_b + 4 * A_ST;
        const uint32_t bl_b = bh_b + B_ST * 2;

        #pragma unroll
        for (int ks = 0; ks < 32; ks += 16) {
            uint32_t ah[4][4], al[4][4], bh[2][4], bl[2][4];
            #pragma unroll
            for (int mt = 0; mt < 4; mt++) {
                const int r  = wm + mt * 16 + (lane & 15);
                const int cc = ks + 8 * (lane >> 4);
                const uint32_t off = (uint32_t)(r * 40 + cc) * 2;
                LDMAT_X4(ah[mt][0], ah[mt][1], ah[mt][2], ah[mt][3], ah_b + off);
                LDMAT_X4(al[mt][0], al[mt][1], al[mt][2], al[mt][3], al_b + off);
            }
            #pragma unroll
            for (int ng = 0; ng < 2; ng++) {
                const int r  = ks + (lane & 15);
                const int cc = wn + ng * 16 + 8 * (lane >> 4);
                const uint32_t off = (uint32_t)(r * 136 + cc) * 2;
                LDMAT_X4_T(bh[ng][0], bh[ng][1], bh[ng][2], bh[ng][3], bh_b + off);
                if constexpr (TERMS == 3)
                    LDMAT_X4_T(bl[ng][0], bl[ng][1], bl[ng][2], bl[ng][3], bl_b + off);
            }
            // sweep 1: Ah x Bh
            #pragma unroll
            for (int mt = 0; mt < 4; mt++)
                #pragma unroll
                for (int nt = 0; nt < 4; nt++) {
                    const int ng = nt >> 1, hf = (nt & 1) * 2;
                    if constexpr (F16) {
                        MMA16816F(c[mt][nt], ah[mt][0], ah[mt][1], ah[mt][2], ah[mt][3],
                                  bh[ng][hf], bh[ng][hf + 1]);
                    } else {
                        MMA16816(c[mt][nt], ah[mt][0], ah[mt][1], ah[mt][2], ah[mt][3],
                                 bh[ng][hf], bh[ng][hf + 1]);
                    }
                }
            // sweep 2: Al x Bh
            #pragma unroll
            for (int mt = 0; mt < 4; mt++)
                #pragma unroll
                for (int nt = 0; nt < 4; nt++) {
                    const int ng = nt >> 1, hf = (nt & 1) * 2;
                    if constexpr (F16) {
                        MMA16816F(c[mt][nt], al[mt][0], al[mt][1], al[mt][2], al[mt][3],
                                  bh[ng][hf], bh[ng][hf + 1]);
                    } else {
                        MMA16816(c[mt][nt], al[mt][0], al[mt][1], al[mt][2], al[mt][3],
                                 bh[ng][hf], bh[ng][hf + 1]);
                    }
                }
            // sweep 3 (bf16x3 only): Ah x Bl
            if constexpr (TERMS == 3) {
                #pragma unroll
                for (int mt = 0; mt < 4; mt++)
                    #pragma unroll
                    for (int nt = 0; nt < 4; nt++) {
                        const int ng = nt >> 1, hf = (nt & 1) * 2;
                        MMA16816(c[mt][nt], ah[mt][0], ah[mt][1], ah[mt][2], ah[mt][3],
                                 bl[ng][hf], bl[ng][hf + 1]);
                    }
            }
        }
    }

    const int gg = lane >> 2;
    const int qq = (lane & 3) * 2;
    #pragma unroll
    for (int mt = 0; mt < 4; mt++) {
        #pragma unroll
        for (int nt = 0; nt < 4; nt++) {
            const int col = bn + wn + nt * 8 + qq;
            #pragma unroll
            for (int hrow = 0; hrow < 2; hrow++) {
                const int row = bm + wm + mt * 16 + gg + hrow * 8;
                float2 v;
                v.x = c[mt][nt][hrow * 2 + 0];
                v.y = c[mt][nt][hrow * 2 + 1];
                const size_t idx = (size_t)row * N + col;
                if (EPI & 1) {
                    const float2 b2 = *(const float2*)(bias + col);
                    v.x += b2.x; v.y += b2.y;
                }
                if (EPI & 4) { v.x = fmaxf(v.x, 0.f); v.y = fmaxf(v.y, 0.f); }
                if (EPI & 2) {
                    const float2 r2 = *(const float2*)(res + idx);
                    v.x += r2.x; v.y += r2.y;
                }
                if (EPI & 8) {
                    typename vec2of<AT>::t h2, l2;
                    split2(v.x, v.y, h2, l2);
                    *(typename vec2of<AT>::t*)(Ch + idx) = h2;
                    *(typename vec2of<AT>::t*)(Cl + idx) = l2;
                } else {
                    *(float2*)(C + idx) = v;
                }
            }
        }
    }
}

#define GEMM_SMEM3 (3 * (2 * A_ST + 2 * B_ST) * 2)   // 113664
#define GEMM_SMEM2 (3 * (2 * A_ST + 1 * B_ST) * 2)   // 87552

// ---------------- tensor-core flash attention (causal, bf16x3) --------------
#define FST   72
#define FTILE (64 * FST)
#define FLASH_SMEM (2 * 4 * FTILE * 2)   // 73728 bytes

__global__ __launch_bounds__(128) void flash_mma(
    const __nv_bfloat16* __restrict__ Gh, const __nv_bfloat16* __restrict__ Gl,
    __half* __restrict__ Ohi, __half* __restrict__ Olo)
{
    extern __shared__ __nv_bfloat16 fsm[];
    const int qt = 31 - blockIdx.x;
    const int h = blockIdx.y, b = blockIdx.z;
    const int tid = threadIdx.x, warp = tid >> 5, lane = tid & 31;
    const size_t qrow0 = (size_t)(b * TT + qt * 64);
    const float SC = 0.180336880f;

    const int lr = tid >> 1;
    const int lc = (tid & 1) * 4;
    auto load_one = [&](__nv_bfloat16* dst, const __nv_bfloat16* src) {
        #pragma unroll
        for (int i = 0; i < 4; i++)
            cp16(dst + lr * FST + (lc + i) * 8, src + (size_t)lr * QKVN + (lc + i) * 8);
    };
    auto load_kv = [&](int s, int kt) {
        const size_t krow = (size_t)(b * TT + kt * 64);
        load_one(fsm + (s * 4 + 0) * FTILE, Gh + krow * QKVN + CDIM + h * DH);
        load_one(fsm + (s * 4 + 1) * FTILE, Gl + krow * QKVN + CDIM + h * DH);
        load_one(fsm + (s * 4 + 2) * FTILE, Gh + krow * QKVN + 2 * CDIM + h * DH);
        load_one(fsm + (s * 4 + 3) * FTILE, Gl + krow * QKVN + 2 * CDIM + h * DH);
    };

    load_one(fsm + 0 * FTILE, Gh + qrow0 * QKVN + h * DH);
    load_one(fsm + 1 * FTILE, Gl + qrow0 * QKVN + h * DH);
    CP_COMMIT(); CP_WAIT(0);
    __syncthreads();
    uint32_t Qh[4][4], Ql[4][4];
    #pragma unroll
    for (int t = 0; t < 4; t++) {
        const uint32_t off = (uint32_t)((warp * 16 + (lane & 15)) * FST
                                        + t * 16 + 8 * (lane >> 4)) * 2;
        LDMAT_X4(Qh[t][0], Qh[t][1], Qh[t][2], Qh[t][3], smem_addr32(fsm) + off);
        LDMAT_X4(Ql[t][0], Ql[t][1], Ql[t][2], Ql[t][3], smem_addr32(fsm + FTILE) + off);
    }
    __syncthreads();

    float O[8][4];
    #pragma unroll
    for (int i = 0; i < 8; i++)
        #pragma unroll
        for (int j = 0; j < 4; j++) O[i][j] = 0.f;
    float m0 = -1e30f, m1 = -1e30f, l0 = 0.f, l1 = 0.f;

    load_kv(0, 0);
    CP_COMMIT();

    for (int kt = 0; kt <= qt; kt++) {
        const int s = kt & 1;
        if (kt < qt) { load_kv(s ^ 1, kt + 1); CP_COMMIT(); CP_WAIT(1); }
        else         { CP_WAIT(0); }
        __syncthreads();

        const uint32_t kh_b = smem_addr32(fsm + (s * 4 + 0) * FTILE);
        const uint32_t kl_b = smem_addr32(fsm + (s * 4 + 1) * FTILE);
        const uint32_t vh_b = smem_addr32(fsm + (s * 4 + 2) * FTILE);
        const uint32_t vl_b = smem_addr32(fsm + (s * 4 + 3) * FTILE);

        // ---- S = Q K^T (bf16x3) ----
        float sv[8][4];
        #pragma unroll
        for (int i = 0; i < 8; i++)
            #pragma unroll
            for (int j = 0; j < 4; j++) sv[i][j] = 0.f;

        #pragma unroll
        for (int t = 0; t < 4; t++) {
            uint32_t kf[4][4];
            #pragma unroll
            for (int g4 = 0; g4 < 4; g4++) {
                const uint32_t off = (uint32_t)((g4 * 16 + (lane & 15)) * FST
                                                + t * 16 + 8 * (lane >> 4)) * 2;
                LDMAT_X4(kf[g4][0], kf[g4][1], kf[g4][2], kf[g4][3], kh_b + off);
            }
            #pragma unroll
            for (int g4 = 0; g4 < 4; g4++) {
                MMA16816(sv[g4 * 2],     Qh[t][0], Qh[t][1], Qh[t][2], Qh[t][3], kf[g4][0], kf[g4][2]);
                MMA16816(sv[g4 * 2 + 1], Qh[t][0], Qh[t][1], Qh[t][2], Qh[t][3], kf[g4][1], kf[g4][3]);
            }
            #pragma unroll
            for (int g4 = 0; g4 < 4; g4++) {
                MMA16816(sv[g4 * 2],     Ql[t][0], Ql[t][1], Ql[t][2], Ql[t][3], kf[g4][0], kf[g4][2]);
                MMA16816(sv[g4 * 2 + 1], Ql[t][0], Ql[t][1], Ql[t][2], Ql[t][3], kf[g4][1], kf[g4][3]);
            }
            #pragma unroll
            for (int g4 = 0; g4 < 4; g4++) {
                const uint32_t off = (uint32_t)((g4 * 16 + (lane & 15)) * FST
                                                + t * 16 + 8 * (lane >> 4)) * 2;
                LDMAT_X4(kf[g4][0], kf[g4][1], kf[g4][2], kf[g4][3], kl_b + off);
            }
            #pragma unroll
            for (int g4 = 0; g4 < 4; g4++) {
                MMA16816(sv[g4 * 2],     Qh[t][0], Qh[t][1], Qh[t][2], Qh[t][3], kf[g4][0], kf[g4][2]);
                MMA16816(sv[g4 * 2 + 1], Qh[t][0], Qh[t][1], Qh[t][2], Qh[t][3], kf[g4][1], kf[g4][3]);
            }
        }

        // ---- causal mask on diagonal tile ----
        const int rl0 = warp * 16 + (lane >> 2);
        if (kt == qt) {
            #pragma unroll
            for (int nt = 0; nt < 8; nt++) {
                const int cl = nt * 8 + (lane & 3) * 2;
                if (cl     > rl0)     sv[nt][0] = -1e30f;
                if (cl + 1 > rl0)     sv[nt][1] = -1e30f;
                if (cl     > rl0 + 8) sv[nt][2] = -1e30f;
                if (cl + 1 > rl0 + 8) sv[nt][3] = -1e30f;
            }
        }

        // ---- online softmax ----
        float mx0 = -1e30f, mx1 = -1e30f;
        #pragma unroll
        for (int nt = 0; nt < 8; nt++) {
            mx0 = fmaxf(mx0, fmaxf(sv[nt][0], sv[nt][1]));
            mx1 = fmaxf(mx1, fmaxf(sv[nt][2], sv[nt][3]));
        }
        mx0 = fmaxf(mx0, __shfl_xor_sync(0xffffffffu, mx0, 1));
        mx0 = fmaxf(mx0, __shfl_xor_sync(0xffffffffu, mx0, 2));
        mx1 = fmaxf(mx1, __shfl_xor_sync(0xffffffffu, mx1, 1));
        mx1 = fmaxf(mx1, __shfl_xor_sync(0xffffffffu, mx1, 2));
        const float mn0 = fmaxf(m0, mx0), mn1 = fmaxf(m1, mx1);
        const float corr0 = fexp2((m0 - mn0) * SC);
        const float corr1 = fexp2((m1 - mn1) * SC);

        uint32_t pAh[4][4], pAl[4][4];
        float ps0 = 0.f, ps1 = 0.f;
        #pragma unroll
        for (int nt = 0; nt < 8; nt++) {
            const float p0 = fexp2((sv[nt][0] - mn0) * SC);
            const float p1 = fexp2((sv[nt][1] - mn0) * SC);
            const float p2 = fexp2((sv[nt][2] - mn1) * SC);
            const float p3 = fexp2((sv[nt][3] - mn1) * SC);
            ps0 += p0 + p1; ps1 += p2 + p3;
            __nv_bfloat162 h01, l01, h23, l23;
            split2(p0, p1, h01, l01);
            split2(p2, p3, h23, l23);
            const int t = nt >> 1, o = (nt & 1) * 2;
            pAh[t][o]     = *(uint32_t*)&h01;
            pAh[t][o + 1] = *(uint32_t*)&h23;
            pAl[t][o]     = *(uint32_t*)&l01;
            pAl[t][o + 1] = *(uint32_t*)&l23;
        }
        ps0 += __shfl_xor_sync(0xffffffffu, ps0, 1);
        ps0 += __shfl_xor_sync(0xffffffffu, ps0, 2);
        ps1 += __shfl_xor_sync(0xffffffffu, ps1, 1);
        ps1 += __shfl_xor_sync(0xffffffffu, ps1, 2);
        l0 = l0 * corr0 + ps0;
        l1 = l1 * corr1 + ps1;
        m0 = mn0; m1 = mn1;

        #pragma unroll
        for (int dt = 0; dt < 8; dt++) {
            O[dt][0] *= corr0; O[dt][1] *= corr0;
            O[dt][2] *= corr1; O[dt][3] *= corr1;
        }

        // ---- O += P V (bf16x3) ----
        #pragma unroll
        for (int t = 0; t < 4; t++) {
            uint32_t vf[4][4];
            #pragma unroll
            for (int g4 = 0; g4 < 4; g4++) {
                const uint32_t off = (uint32_t)((t * 16 + (lane & 15)) * FST
                                                + g4 * 16 + 8 * (lane >> 4)) * 2;
                LDMAT_X4_T(vf[g4][0], vf[g4][1], vf[g4][2], vf[g4][3], vh_b + off);
            }
            #pragma unroll
            for (int g4 = 0; g4 < 4; g4++) {
                MMA16816(O[g4 * 2],     pAh[t][0], pAh[t][1], pAh[t][2], pAh[t][3], vf[g4][0], vf[g4][1]);
                MMA16816(O[g4 * 2 + 1], pAh[t][0], pAh[t][1], pAh[t][2], pAh[t][3], vf[g4][2], vf[g4][3]);
            }
            #pragma unroll
            for (int g4 = 0; g4 < 4; g4++) {
                MMA16816(O[g4 * 2],     pAl[t][0], pAl[t][1], pAl[t][2], pAl[t][3], vf[g4][0], vf[g4][1]);
                MMA16816(O[g4 * 2 + 1], pAl[t][0], pAl[t][1], pAl[t][2], pAl[t][3], vf[g4][2], vf[g4][3]);
            }
            #pragma unroll
            for (int g4 = 0; g4 < 4; g4++) {
                const uint32_t off = (uint32_t)((t * 16 + (lane & 15)) * FST
                                                + g4 * 16 + 8 * (lane >> 4)) * 2;
                LDMAT_X4_T(vf[g4][0], vf[g4][1], vf[g4][2], vf[g4][3], vl_b + off);
            }
            #pragma unroll
            for (int g4 = 0; g4 < 4; g4++) {
                MMA16816(O[g4 * 2],     pAh[t][0], pAh[t][1], pAh[t][2], pAh[t][3], vf[g4][0], vf[g4][1]);
                MMA16816(O[g4 * 2 + 1], pAh[t][0], pAh[t][1], pAh[t][2], pAh[t][3], vf[g4][2], vf[g4][3]);
            }
        }
        __syncthreads();
    }

    // ---- normalize + f16 split-write (for f16x2 Wo GEMM) ----
    const float inv0 = 1.f / l0, inv1 = 1.f / l1;
    const int rl0 = warp * 16 + (lane >> 2);
    #pragma unroll
    for (int dt = 0; dt < 8; dt++) {
        const int d = h * DH + dt * 8 + (lane & 3) * 2;
        __half2 hh, ll;
        const size_t i0 = (qrow0 + rl0) * CDIM + d;
        split2(O[dt][0] * inv0, O[dt][1] * inv0, hh, ll);
        *(__half2*)(Ohi + i0) = hh;
        *(__half2*)(Olo + i0) = ll;
        const size_t i1 = (qrow0 + rl0 + 8) * CDIM + d;
        split2(O[dt][2] * inv1, O[dt][3] * inv1, hh, ll);
        *(__half2*)(Ohi + i1) = hh;
        *(__half2*)(Olo + i1) = ll;
    }
}

// ---------------- launch ----------------------------------------------------
extern "C" void kernel_launch(void* const* d_in, const int* in_sizes, int n_in,
                              void* d_out, int out_size)
{
    const float* x   = (const float*)d_in[0];
    const float* Wq  = (const float*)d_in[1];
    const float* Wk  = (const float*)d_in[2];
    const float* Wv  = (const float*)d_in[3];
    const float* Wo  = (const float*)d_in[4];
    const float* bo  = (const float*)d_in[5];
    const float* W1  = (const float*)d_in[6];
    const float* b1  = (const float*)d_in[7];
    const float* W2  = (const float*)d_in[8];
    const float* b2  = (const float*)d_in[9];
    const float* g1  = (const float*)d_in[10];
    const float* be1 = (const float*)d_in[11];
    const float* g2  = (const float*)d_in[12];
    const float* be2 = (const float*)d_in[13];
    float* out = (float*)d_out;

    __nv_bfloat16 *h_hi, *h_lo, *qkv_hi, *qkv_lo, *wqkv_hi, *wqkv_lo;
    __half *at_hi, *at_lo, *ml_hi, *ml_lo, *wo_f, *w1_f, *w2_f;
    float *x1;
    cudaGetSymbolAddress((void**)&h_hi,   g_h_hi);
    cudaGetSymbolAddress((void**)&h_lo,   g_h_lo);
    cudaGetSymbolAddress((void**)&qkv_hi, g_qkv_hi);
    cudaGetSymbolAddress((void**)&qkv_lo, g_qkv_lo);
    cudaGetSymbolAddress((void**)&at_hi,  g_at_hi);
    cudaGetSymbolAddress((void**)&at_lo,  g_at_lo);
    cudaGetSymbolAddress((void**)&x1,     g_x1);
    cudaGetSymbolAddress((void**)&ml_hi,  g_ml_hi);
    cudaGetSymbolAddress((void**)&ml_lo,  g_ml_lo);
    cudaGetSymbolAddress((void**)&wqkv_hi, g_wqkv_hi);
    cudaGetSymbolAddress((void**)&wqkv_lo, g_wqkv_lo);
    cudaGetSymbolAddress((void**)&wo_f, g_wo_f);
    cudaGetSymbolAddress((void**)&w1_f, g_w1_f);
    cudaGetSymbolAddress((void**)&w2_f, g_w2_f);

    cudaFuncSetAttribute((const void*)mma_gemm<3, 8, __nv_bfloat16>,
        cudaFuncAttributeMaxDynamicSharedMemorySize, GEMM_SMEM3);
    cudaFuncSetAttribute((const void*)mma_gemm<2, 3, __half>,
        cudaFuncAttributeMaxDynamicSharedMemorySize, GEMM_SMEM2);
    cudaFuncSetAttribute((const void*)mma_gemm<2, 13, __half>,
        cudaFuncAttributeMaxDynamicSharedMemorySize, GEMM_SMEM2);
    cudaFuncSetAttribute((const void*)flash_mma,
        cudaFuncAttributeMaxDynamicSharedMemorySize, FLASH_SMEM);

    // ---- weight prep ----
    const int nW = CDIM * CDIM / 4;
    split_pack_kernel<<<(nW + 255) / 256, 256>>>((const float4*)Wq, wqkv_hi, wqkv_lo, 0);
    split_pack_kernel<<<(nW + 255) / 256, 256>>>((const float4*)Wk, wqkv_hi, wqkv_lo, 1024);
    split_pack_kernel<<<(nW + 255) / 256, 256>>>((const float4*)Wv, wqkv_hi, wqkv_lo, 2048);
    tof16_kernel<<<(nW + 255) / 256, 256>>>((const float4*)Wo, (__half2*)wo_f, nW);
    const int nW1 = CDIM * FF / 4;
    tof16_kernel<<<(nW1 + 255) / 256, 256>>>((const float4*)W1, (__half2*)w1_f, nW1);
    tof16_kernel<<<(nW1 + 255) / 256, 256>>>((const float4*)W2, (__half2*)w2_f, nW1);

    const dim3 gQKV(QKVN / 128, MT / 128);   // (24, 64)
    const dim3 gC(CDIM / 128, MT / 128);     // (8, 64)
    const dim3 gF(FF / 128, MT / 128);       // (32, 64)

    // LN1 -> bf16 split h (feeds bf16x3 QKV)
    ln_kernel<__nv_bfloat16><<<MT, 256>>>((const float4*)x, (const float4*)g1,
                                          (const float4*)be1, h_hi, h_lo);
    // fused QKV projection (bf16x3) -> bf16 split qkv
    mma_gemm<3, 8, __nv_bfloat16><<<gQKV, 256, GEMM_SMEM3>>>(
        h_hi, h_lo, wqkv_hi, wqkv_lo,
        nullptr, nullptr, nullptr, qkv_hi, qkv_lo, MT, QKVN, CDIM);
    // tensor-core causal flash attention (bf16x3) -> f16 split attn
    flash_mma<<<dim3(TT / 64, HH, BB), 128, FLASH_SMEM>>>(qkv_hi, qkv_lo, at_hi, at_lo);
    // x1 = x + attn @ Wo + bo   (f16x2)
    mma_gemm<2, 3, __half><<<gC, 256, GEMM_SMEM2>>>(
        at_hi, at_lo, wo_f, nullptr,
        bo, x, x1, nullptr, nullptr, MT, CDIM, CDIM);
    // LN2 -> f16 split h (feeds f16x2 W1)
    ln_kernel<__half><<<MT, 256>>>((const float4*)x1, (const float4*)g2,
                                   (const float4*)be2, (__half*)h_hi, (__half*)h_lo);
    // mlp = relu(h @ W1 + b1) -> f16 split   (f16x2)
    mma_gemm<2, 13, __half><<<gF, 256, GEMM_SMEM2>>>(
        (__half*)h_hi, (__half*)h_lo, w1_f, nullptr,
        b1, nullptr, nullptr, ml_hi, ml_lo, MT, FF, CDIM);
    // out = x1 + mlp @ W2 + b2   (f16x2)
    mma_gemm<2, 3, __half><<<gC, 256, GEMM_SMEM2>>>(
        ml_hi, ml_lo, w2_f, nullptr,
        b2, x1, out, nullptr, nullptr, MT, CDIM, FF);
}

// round 14
// speedup vs baseline: 4.2383x; 1.1691x over previous
#include <cuda_runtime.h>
#include <cuda_bf16.h>
#include <cuda_fp16.h>
#include <cstdint>
#include <math.h>

// Problem dims
#define BB   4
#define TT   2048
#define MT   8192      // B*T
#define CDIM 1024
#define HH   16
#define DH   64
#define FF   4096
#define QKVN 3072

// ---------------- scratch (device globals; no allocation allowed) ----------
__device__ __half g_h_hi [MT * CDIM];
__device__ __half g_h_lo [MT * CDIM];
__device__ __half g_qkv_hi[(size_t)MT * QKVN];
__device__ __half g_qkv_lo[(size_t)MT * QKVN];
__device__ __half g_at_hi[MT * CDIM];
__device__ __half g_at_lo[MT * CDIM];
__device__ float  g_x1   [MT * CDIM];
__device__ __half g_ml_hi[(size_t)MT * FF];
__device__ __half g_ml_lo[(size_t)MT * FF];
// weights: all single f16 [K][N]
__device__ __half g_wqkv_f[CDIM * QKVN];
__device__ __half g_wo_f [CDIM * CDIM];
__device__ __half g_w1_f [CDIM * FF];
__device__ __half g_w2_f [FF * CDIM];

// ---------------- helpers ---------------------------------------------------
__device__ __forceinline__ uint32_t smem_addr32(const void* p) {
    return (uint32_t)__cvta_generic_to_shared(p);
}
__device__ __forceinline__ void cp16(void* smem, const void* g) {
    uint32_t s = smem_addr32(smem);
    asm volatile("cp.async.cg.shared.global [%0], [%1], 16;" :: "r"(s), "l"(g));
}
#define CP_COMMIT() asm volatile("cp.async.commit_group;")
#define CP_WAIT(n)  asm volatile("cp.async.wait_group %0;" :: "n"(n))

__device__ __forceinline__ void split2(float a, float b,
    __half2& hi, __half2& lo)
{
    hi.x = __float2half_rn(a);
    hi.y = __float2half_rn(b);
    lo.x = __float2half_rn(a - __half2float(hi.x));
    lo.y = __float2half_rn(b - __half2float(hi.y));
}
__device__ __forceinline__ float fexp2(float x) {
    float y;
    asm("ex2.approx.f32 %0, %1;" : "=f"(y) : "f"(x));
    return y;
}

// ---------------- weight prep kernels ---------------------------------------
__global__ __launch_bounds__(256) void tof16_kernel(
    const float4* __restrict__ in, __half2* __restrict__ o, int n4)
{
    const int i = blockIdx.x * 256 + threadIdx.x;
    if (i >= n4) return;
    const float4 v = in[i];
    o[i * 2]     = __floats2half2_rn(v.x, v.y);
    o[i * 2 + 1] = __floats2half2_rn(v.z, v.w);
}

// pack W[1024][1024] -> wqkv_f[1024][3072] at column offset, f16
__global__ __launch_bounds__(256) void tof16_pack_kernel(
    const float4* __restrict__ in, __half* __restrict__ o, int coloff)
{
    const int i = blockIdx.x * 256 + threadIdx.x;
    if (i >= CDIM * CDIM / 4) return;
    const int r = i >> 8;
    const int c = (i & 255) * 4;
    const float4 v = in[i];
    const size_t ofs = (size_t)r * QKVN + coloff + c;
    *(__half2*)(o + ofs)     = __floats2half2_rn(v.x, v.y);
    *(__half2*)(o + ofs + 2) = __floats2half2_rn(v.z, v.w);
}

// ---------------- LayerNorm: emits f16 hi/lo ---------------------------------
__global__ __launch_bounds__(256) void ln_kernel(
    const float4* __restrict__ x, const float4* __restrict__ g,
    const float4* __restrict__ be, __half* __restrict__ hi, __half* __restrict__ lo)
{
    const int r = blockIdx.x;
    const int t = threadIdx.x;
    const float4 v = x[(size_t)r * (CDIM / 4) + t];
    float s  = v.x + v.y + v.z + v.w;
    float ss = v.x * v.x + v.y * v.y + v.z * v.z + v.w * v.w;
    #pragma unroll
    for (int o = 16; o > 0; o >>= 1) {
        s  += __shfl_down_sync(0xffffffffu, s,  o);
        ss += __shfl_down_sync(0xffffffffu, ss, o);
    }
    __shared__ float rs[8], rss[8];
    __shared__ float smu, sinv;
    const int w = t >> 5, lane = t & 31;
    if (lane == 0) { rs[w] = s; rss[w] = ss; }
    __syncthreads();
    if (t == 0) {
        float S = 0.f, SS = 0.f;
        #pragma unroll
        for (int i = 0; i < 8; i++) { S += rs[i]; SS += rss[i]; }
        const float mu  = S * (1.0f / CDIM);
        const float var = SS * (1.0f / CDIM) - mu * mu;
        smu = mu; sinv = rsqrtf(var + 1e-5f);
    }
    __syncthreads();
    const float mu = smu, inv = sinv;
    const float4 gv = g[t], bv = be[t];
    float a0 = (v.x - mu) * inv * gv.x + bv.x;
    float a1 = (v.y - mu) * inv * gv.y + bv.y;
    float a2 = (v.z - mu) * inv * gv.z + bv.z;
    float a3 = (v.w - mu) * inv * gv.w + bv.w;
    __half2 h0, h1, l0, l1;
    split2(a0, a1, h0, l0);
    split2(a2, a3, h1, l1);
    const size_t o = (size_t)r * CDIM + t * 4;
    *(__half2*)(hi + o)     = h0;
    *(__half2*)(hi + o + 2) = h1;
    *(__half2*)(lo + o)     = l0;
    *(__half2*)(lo + o + 2) = l1;
}

// ---------------- MMA macros ------------------------------------------------
#define LDMAT_X4(R0,R1,R2,R3,addr) \
    asm volatile("ldmatrix.sync.aligned.m8n8.x4.shared.b16 {%0,%1,%2,%3}, [%4];" \
        : "=r"(R0), "=r"(R1), "=r"(R2), "=r"(R3) : "r"(addr))
#define LDMAT_X4_T(R0,R1,R2,R3,addr) \
    asm volatile("ldmatrix.sync.aligned.m8n8.x4.trans.shared.b16 {%0,%1,%2,%3}, [%4];" \
        : "=r"(R0), "=r"(R1), "=r"(R2), "=r"(R3) : "r"(addr))
#define MMA16816F(C, A0,A1,A2,A3, B0,B1) \
    asm volatile("mma.sync.aligned.m16n8k16.row.col.f32.f16.f16.f32 " \
        "{%0,%1,%2,%3},{%4,%5,%6,%7},{%8,%9},{%0,%1,%2,%3};" \
        : "+f"(C[0]), "+f"(C[1]), "+f"(C[2]), "+f"(C[3]) \
        : "r"(A0), "r"(A1), "r"(A2), "r"(A3), "r"(B0), "r"(B1))

// ---------------- pipelined f16x2 tensor-core GEMM (3-stage) -----------------
// C = (Ah + Al) @ B, all f16, fp32 acc. 2 MMAs per tile-pair per k16.
// EPI bit0:+bias bit1:+residual bit2:relu bit3:split-f16 out (bias->relu->res)
#define A_ST 5120                         // elems per A array per stage: 128*40
#define B_ST 4352                         // elems per B array per stage: 32*136
#define STG_ELEMS (2 * A_ST + B_ST)       // 14592 elems per stage
#define GEMM_SMEM (3 * STG_ELEMS * 2)     // 87552 bytes

template <int EPI>
__global__ __launch_bounds__(256, 1) void mma_gemm(
    const __half* __restrict__ Ah, const __half* __restrict__ Al,
    const __half* __restrict__ Bw,
    const float* __restrict__ bias, const float* __restrict__ res,
    float* __restrict__ C, __half* __restrict__ Ch,
    __half* __restrict__ Cl, int M, int N, int K)
{
    extern __shared__ char dynsmem[];
    __half* base = (__half*)dynsmem;

    const int tid  = threadIdx.x;
    const int warp = tid >> 5, lane = tid & 31;
    const int wm = (warp & 1) * 64;
    const int wn = (warp >> 1) * 32;
    const int bm = blockIdx.y * 128, bn = blockIdx.x * 128;

    float c[4][4][4];
    #pragma unroll
    for (int i = 0; i < 4; i++)
        #pragma unroll
        for (int j = 0; j < 4; j++)
            #pragma unroll
            for (int q = 0; q < 4; q++) c[i][j][q] = 0.f;

    const int a_r = tid >> 2, a_c = (tid & 3) * 8;
    const int b_r = tid >> 4, b_c = (tid & 15) * 8;

    auto load_stage = [&](int s, int k0) {
        __half* st = base + s * STG_ELEMS;
        #pragma unroll
        for (int p = 0; p < 2; p++) {
            const int row = p * 64 + a_r;
            const size_t go = (size_t)(bm + row) * K + k0 + a_c;
            const int so = row * 40 + a_c;
            cp16(st + so,        Ah + go);
            cp16(st + A_ST + so, Al + go);
        }
        #pragma unroll
        for (int p = 0; p < 2; p++) {
            const int row = p * 16 + b_r;
            const size_t go = (size_t)(k0 + row) * N + bn + b_c;
            cp16(st + 2 * A_ST + row * 136 + b_c, Bw + go);
        }
    };

    const int nk = K / 32;
    load_stage(0, 0);
    CP_COMMIT();
    if (nk > 1) load_stage(1, 32);
    CP_COMMIT();

    for (int ki = 0; ki < nk; ki++) {
        CP_WAIT(1);
        __syncthreads();
        if (ki + 2 < nk) load_stage((ki + 2) % 3, (ki + 2) * 32);
        CP_COMMIT();

        const uint32_t st_b = smem_addr32(base + (ki % 3) * STG_ELEMS);
        const uint32_t ah_b = st_b;
        const uint32_t al_b = st_b + A_ST * 2;
        const uint32_t bw_b = st_b + 4 * A_ST;

        #pragma unroll
        for (int ks = 0; ks < 32; ks += 16) {
            uint32_t ah[4][4], al[4][4], bw[2][4];
            #pragma unroll
            for (int mt = 0; mt < 4; mt++) {
                const int r  = wm + mt * 16 + (lane & 15);
                const int cc = ks + 8 * (lane >> 4);
                const uint32_t off = (uint32_t)(r * 40 + cc) * 2;
                LDMAT_X4(ah[mt][0], ah[mt][1], ah[mt][2], ah[mt][3], ah_b + off);
                LDMAT_X4(al[mt][0], al[mt][1], al[mt][2], al[mt][3], al_b + off);
            }
            #pragma unroll
            for (int ng = 0; ng < 2; ng++) {
                const int r  = ks + (lane & 15);
                const int cc = wn + ng * 16 + 8 * (lane >> 4);
                const uint32_t off = (uint32_t)(r * 136 + cc) * 2;
                LDMAT_X4_T(bw[ng][0], bw[ng][1], bw[ng][2], bw[ng][3], bw_b + off);
            }
            // sweep 1: Ah x B
            #pragma unroll
            for (int mt = 0; mt < 4; mt++)
                #pragma unroll
                for (int nt = 0; nt < 4; nt++) {
                    const int ng = nt >> 1, hf = (nt & 1) * 2;
                    MMA16816F(c[mt][nt], ah[mt][0], ah[mt][1], ah[mt][2], ah[mt][3],
                              bw[ng][hf], bw[ng][hf + 1]);
                }
            // sweep 2: Al x B
            #pragma unroll
            for (int mt = 0; mt < 4; mt++)
                #pragma unroll
                for (int nt = 0; nt < 4; nt++) {
                    const int ng = nt >> 1, hf = (nt & 1) * 2;
                    MMA16816F(c[mt][nt], al[mt][0], al[mt][1], al[mt][2], al[mt][3],
                              bw[ng][hf], bw[ng][hf + 1]);
                }
        }
    }

    const int gg = lane >> 2;
    const int qq = (lane & 3) * 2;
    #pragma unroll
    for (int mt = 0; mt < 4; mt++) {
        #pragma unroll
        for (int nt = 0; nt < 4; nt++) {
            const int col = bn + wn + nt * 8 + qq;
            #pragma unroll
            for (int hrow = 0; hrow < 2; hrow++) {
                const int row = bm + wm + mt * 16 + gg + hrow * 8;
                float2 v;
                v.x = c[mt][nt][hrow * 2 + 0];
                v.y = c[mt][nt][hrow * 2 + 1];
                const size_t idx = (size_t)row * N + col;
                if (EPI & 1) {
                    const float2 b2 = *(const float2*)(bias + col);
                    v.x += b2.x; v.y += b2.y;
                }
                if (EPI & 4) { v.x = fmaxf(v.x, 0.f); v.y = fmaxf(v.y, 0.f); }
                if (EPI & 2) {
                    const float2 r2 = *(const float2*)(res + idx);
                    v.x += r2.x; v.y += r2.y;
                }
                if (EPI & 8) {
                    __half2 h2, l2;
                    split2(v.x, v.y, h2, l2);
                    *(__half2*)(Ch + idx) = h2;
                    *(__half2*)(Cl + idx) = l2;
                } else {
                    *(float2*)(C + idx) = v;
                }
            }
        }
    }
}

// ---------------- tensor-core flash attention (causal, f16x2) ----------------
// S = (Qh + Ql) K^T with single-f16 K; O += (Ph + Pl) V with single-f16 V.
#define FST   72
#define FTILE (64 * FST)
#define FLASH_SMEM (2 * 2 * FTILE * 2)   // 36864 bytes (2 stages x [K, V])

__global__ __launch_bounds__(128) void flash_mma(
    const __half* __restrict__ Gh, const __half* __restrict__ Gl,
    __half* __restrict__ Ohi, __half* __restrict__ Olo)
{
    extern __shared__ __half fsm[];
    const int qt = 31 - blockIdx.x;
    const int h = blockIdx.y, b = blockIdx.z;
    const int tid = threadIdx.x, warp = tid >> 5, lane = tid & 31;
    const size_t qrow0 = (size_t)(b * TT + qt * 64);
    const float SC = 0.180336880f;

    const int lr = tid >> 1;
    const int lc = (tid & 1) * 4;
    auto load_one = [&](__half* dst, const __half* src) {
        #pragma unroll
        for (int i = 0; i < 4; i++)
            cp16(dst + lr * FST + (lc + i) * 8, src + (size_t)lr * QKVN + (lc + i) * 8);
    };
    auto load_kv = [&](int s, int kt) {
        const size_t krow = (size_t)(b * TT + kt * 64);
        load_one(fsm + (s * 2 + 0) * FTILE, Gh + krow * QKVN + CDIM + h * DH);
        load_one(fsm + (s * 2 + 1) * FTILE, Gh + krow * QKVN + 2 * CDIM + h * DH);
    };

    // ---- stage Q hi/lo through stage-0 buffers, ldmatrix to registers ----
    load_one(fsm + 0 * FTILE, Gh + qrow0 * QKVN + h * DH);
    load_one(fsm + 1 * FTILE, Gl + qrow0 * QKVN + h * DH);
    CP_COMMIT(); CP_WAIT(0);
    __syncthreads();
    uint32_t Qh[4][4], Ql[4][4];
    #pragma unroll
    for (int t = 0; t < 4; t++) {
        const uint32_t off = (uint32_t)((warp * 16 + (lane & 15)) * FST
                                        + t * 16 + 8 * (lane >> 4)) * 2;
        LDMAT_X4(Qh[t][0], Qh[t][1], Qh[t][2], Qh[t][3], smem_addr32(fsm) + off);
        LDMAT_X4(Ql[t][0], Ql[t][1], Ql[t][2], Ql[t][3], smem_addr32(fsm + FTILE) + off);
    }
    __syncthreads();

    float O[8][4];
    #pragma unroll
    for (int i = 0; i < 8; i++)
        #pragma unroll
        for (int j = 0; j < 4; j++) O[i][j] = 0.f;
    float m0 = -1e30f, m1 = -1e30f, l0 = 0.f, l1 = 0.f;

    load_kv(0, 0);
    CP_COMMIT();

    for (int kt = 0; kt <= qt; kt++) {
        const int s = kt & 1;
        if (kt < qt) { load_kv(s ^ 1, kt + 1); CP_COMMIT(); CP_WAIT(1); }
        else         { CP_WAIT(0); }
        __syncthreads();

        const uint32_t kh_b = smem_addr32(fsm + (s * 2 + 0) * FTILE);
        const uint32_t vh_b = smem_addr32(fsm + (s * 2 + 1) * FTILE);

        // ---- S = (Qh + Ql) K^T ----
        float sv[8][4];
        #pragma unroll
        for (int i = 0; i < 8; i++)
            #pragma unroll
            for (int j = 0; j < 4; j++) sv[i][j] = 0.f;

        #pragma unroll
        for (int t = 0; t < 4; t++) {
            uint32_t kf[4][4];
            #pragma unroll
            for (int g4 = 0; g4 < 4; g4++) {
                const uint32_t off = (uint32_t)((g4 * 16 + (lane & 15)) * FST
                                                + t * 16 + 8 * (lane >> 4)) * 2;
                LDMAT_X4(kf[g4][0], kf[g4][1], kf[g4][2], kf[g4][3], kh_b + off);
            }
            #pragma unroll
            for (int g4 = 0; g4 < 4; g4++) {
                MMA16816F(sv[g4 * 2],     Qh[t][0], Qh[t][1], Qh[t][2], Qh[t][3], kf[g4][0], kf[g4][2]);
                MMA16816F(sv[g4 * 2 + 1], Qh[t][0], Qh[t][1], Qh[t][2], Qh[t][3], kf[g4][1], kf[g4][3]);
            }
            #pragma unroll
            for (int g4 = 0; g4 < 4; g4++) {
                MMA16816F(sv[g4 * 2],     Ql[t][0], Ql[t][1], Ql[t][2], Ql[t][3], kf[g4][0], kf[g4][2]);
                MMA16816F(sv[g4 * 2 + 1], Ql[t][0], Ql[t][1], Ql[t][2], Ql[t][3], kf[g4][1], kf[g4][3]);
            }
        }

        // ---- causal mask on diagonal tile ----
        const int rl0 = warp * 16 + (lane >> 2);
        if (kt == qt) {
            #pragma unroll
            for (int nt = 0; nt < 8; nt++) {
                const int cl = nt * 8 + (lane & 3) * 2;
                if (cl     > rl0)     sv[nt][0] = -1e30f;
                if (cl + 1 > rl0)     sv[nt][1] = -1e30f;
                if (cl     > rl0 + 8) sv[nt][2] = -1e30f;
                if (cl + 1 > rl0 + 8) sv[nt][3] = -1e30f;
            }
        }

        // ---- online softmax ----
        float mx0 = -1e30f, mx1 = -1e30f;
        #pragma unroll
        for (int nt = 0; nt < 8; nt++) {
            mx0 = fmaxf(mx0, fmaxf(sv[nt][0], sv[nt][1]));
            mx1 = fmaxf(mx1, fmaxf(sv[nt][2], sv[nt][3]));
        }
        mx0 = fmaxf(mx0, __shfl_xor_sync(0xffffffffu, mx0, 1));
        mx0 = fmaxf(mx0, __shfl_xor_sync(0xffffffffu, mx0, 2));
        mx1 = fmaxf(mx1, __shfl_xor_sync(0xffffffffu, mx1, 1));
        mx1 = fmaxf(mx1, __shfl_xor_sync(0xffffffffu, mx1, 2));
        const float mn0 = fmaxf(m0, mx0), mn1 = fmaxf(m1, mx1);
        const float corr0 = fexp2((m0 - mn0) * SC);
        const float corr1 = fexp2((m1 - mn1) * SC);

        uint32_t pAh[4][4], pAl[4][4];
        float ps0 = 0.f, ps1 = 0.f;
        #pragma unroll
        for (int nt = 0; nt < 8; nt++) {
            const float p0 = fexp2((sv[nt][0] - mn0) * SC);
            const float p1 = fexp2((sv[nt][1] - mn0) * SC);
            const float p2 = fexp2((sv[nt][2] - mn1) * SC);
            const float p3 = fexp2((sv[nt][3] - mn1) * SC);
            ps0 += p0 + p1; ps1 += p2 + p3;
            __half2 h01, l01, h23, l23;
            split2(p0, p1, h01, l01);
            split2(p2, p3, h23, l23);
            const int t = nt >> 1, o = (nt & 1) * 2;
            pAh[t][o]     = *(uint32_t*)&h01;
            pAh[t][o + 1] = *(uint32_t*)&h23;
            pAl[t][o]     = *(uint32_t*)&l01;
            pAl[t][o + 1] = *(uint32_t*)&l23;
        }
        ps0 += __shfl_xor_sync(0xffffffffu, ps0, 1);
        ps0 += __shfl_xor_sync(0xffffffffu, ps0, 2);
        ps1 += __shfl_xor_sync(0xffffffffu, ps1, 1);
        ps1 += __shfl_xor_sync(0xffffffffu, ps1, 2);
        l0 = l0 * corr0 + ps0;
        l1 = l1 * corr1 + ps1;
        m0 = mn0; m1 = mn1;

        #pragma unroll
        for (int dt = 0; dt < 8; dt++) {
            O[dt][0] *= corr0; O[dt][1] *= corr0;
            O[dt][2] *= corr1; O[dt][3] *= corr1;
        }

        // ---- O += (Ph + Pl) V ----
        #pragma unroll
        for (int t = 0; t < 4; t++) {
            uint32_t vf[4][4];
            #pragma unroll
            for (int g4 = 0; g4 < 4; g4++) {
                const uint32_t off = (uint32_t)((t * 16 + (lane & 15)) * FST
                                                + g4 * 16 + 8 * (lane >> 4)) * 2;
                LDMAT_X4_T(vf[g4][0], vf[g4][1], vf[g4][2], vf[g4][3], vh_b + off);
            }
            #pragma unroll
            for (int g4 = 0; g4 < 4; g4++) {
                MMA16816F(O[g4 * 2],     pAh[t][0], pAh[t][1], pAh[t][2], pAh[t][3], vf[g4][0], vf[g4][1]);
                MMA16816F(O[g4 * 2 + 1], pAh[t][0], pAh[t][1], pAh[t][2], pAh[t][3], vf[g4][2], vf[g4][3]);
            }
            #pragma unroll
            for (int g4 = 0; g4 < 4; g4++) {
                MMA16816F(O[g4 * 2],     pAl[t][0], pAl[t][1], pAl[t][2], pAl[t][3], vf[g4][0], vf[g4][1]);
                MMA16816F(O[g4 * 2 + 1], pAl[t][0], pAl[t][1], pAl[t][2], pAl[t][3], vf[g4][2], vf[g4][3]);
            }
        }
        __syncthreads();
    }

    // ---- normalize + f16 split-write ----
    const float inv0 = 1.f / l0, inv1 = 1.f / l1;
    const int rl0 = warp * 16 + (lane >> 2);
    #pragma unroll
    for (int dt = 0; dt < 8; dt++) {
        const int d = h * DH + dt * 8 + (lane & 3) * 2;
        __half2 hh, ll;
        const size_t i0 = (qrow0 + rl0) * CDIM + d;
        split2(O[dt][0] * inv0, O[dt][1] * inv0, hh, ll);
        *(__half2*)(Ohi + i0) = hh;
        *(__half2*)(Olo + i0) = ll;
        const size_t i1 = (qrow0 + rl0 + 8) * CDIM + d;
        split2(O[dt][2] * inv1, O[dt][3] * inv1, hh, ll);
        *(__half2*)(Ohi + i1) = hh;
        *(__half2*)(Olo + i1) = ll;
    }
}

// ---------------- launch ----------------------------------------------------
extern "C" void kernel_launch(void* const* d_in, const int* in_sizes, int n_in,
                              void* d_out, int out_size)
{
    const float* x   = (const float*)d_in[0];
    const float* Wq  = (const float*)d_in[1];
    const float* Wk  = (const float*)d_in[2];
    const float* Wv  = (const float*)d_in[3];
    const float* Wo  = (const float*)d_in[4];
    const float* bo  = (const float*)d_in[5];
    const float* W1  = (const float*)d_in[6];
    const float* b1  = (const float*)d_in[7];
    const float* W2  = (const float*)d_in[8];
    const float* b2  = (const float*)d_in[9];
    const float* g1  = (const float*)d_in[10];
    const float* be1 = (const float*)d_in[11];
    const float* g2  = (const float*)d_in[12];
    const float* be2 = (const float*)d_in[13];
    float* out = (float*)d_out;

    __half *h_hi, *h_lo, *qkv_hi, *qkv_lo, *at_hi, *at_lo, *ml_hi, *ml_lo;
    __half *wqkv_f, *wo_f, *w1_f, *w2_f;
    float *x1;
    cudaGetSymbolAddress((void**)&h_hi,   g_h_hi);
    cudaGetSymbolAddress((void**)&h_lo,   g_h_lo);
    cudaGetSymbolAddress((void**)&qkv_hi, g_qkv_hi);
    cudaGetSymbolAddress((void**)&qkv_lo, g_qkv_lo);
    cudaGetSymbolAddress((void**)&at_hi,  g_at_hi);
    cudaGetSymbolAddress((void**)&at_lo,  g_at_lo);
    cudaGetSymbolAddress((void**)&x1,     g_x1);
    cudaGetSymbolAddress((void**)&ml_hi,  g_ml_hi);
    cudaGetSymbolAddress((void**)&ml_lo,  g_ml_lo);
    cudaGetSymbolAddress((void**)&wqkv_f, g_wqkv_f);
    cudaGetSymbolAddress((void**)&wo_f, g_wo_f);
    cudaGetSymbolAddress((void**)&w1_f, g_w1_f);
    cudaGetSymbolAddress((void**)&w2_f, g_w2_f);

    cudaFuncSetAttribute((const void*)mma_gemm<3>,
        cudaFuncAttributeMaxDynamicSharedMemorySize, GEMM_SMEM);
    cudaFuncSetAttribute((const void*)mma_gemm<8>,
        cudaFuncAttributeMaxDynamicSharedMemorySize, GEMM_SMEM);
    cudaFuncSetAttribute((const void*)mma_gemm<13>,
        cudaFuncAttributeMaxDynamicSharedMemorySize, GEMM_SMEM);
    cudaFuncSetAttribute((const void*)flash_mma,
        cudaFuncAttributeMaxDynamicSharedMemorySize, FLASH_SMEM);

    // ---- weight prep (all single f16) ----
    const int nW = CDIM * CDIM / 4;
    tof16_pack_kernel<<<(nW + 255) / 256, 256>>>((const float4*)Wq, wqkv_f, 0);
    tof16_pack_kernel<<<(nW + 255) / 256, 256>>>((const float4*)Wk, wqkv_f, 1024);
    tof16_pack_kernel<<<(nW + 255) / 256, 256>>>((const float4*)Wv, wqkv_f, 2048);
    tof16_kernel<<<(nW + 255) / 256, 256>>>((const float4*)Wo, (__half2*)wo_f, nW);
    const int nW1 = CDIM * FF / 4;
    tof16_kernel<<<(nW1 + 255) / 256, 256>>>((const float4*)W1, (__half2*)w1_f, nW1);
    tof16_kernel<<<(nW1 + 255) / 256, 256>>>((const float4*)W2, (__half2*)w2_f, nW1);

    const dim3 gQKV(QKVN / 128, MT / 128);   // (24, 64)
    const dim3 gC(CDIM / 128, MT / 128);     // (8, 64)
    const dim3 gF(FF / 128, MT / 128);       // (32, 64)

    // LN1 -> f16 split h
    ln_kernel<<<MT, 256>>>((const float4*)x, (const float4*)g1,
                           (const float4*)be1, h_hi, h_lo);
    // fused QKV projection (f16x2) -> f16 split qkv
    mma_gemm<8><<<gQKV, 256, GEMM_SMEM>>>(h_hi, h_lo, wqkv_f,
        nullptr, nullptr, nullptr, qkv_hi, qkv_lo, MT, QKVN, CDIM);
    // tensor-core causal flash attention (f16x2) -> f16 split attn
    flash_mma<<<dim3(TT / 64, HH, BB), 128, FLASH_SMEM>>>(qkv_hi, qkv_lo, at_hi, at_lo);
    // x1 = x + attn @ Wo + bo   (f16x2)
    mma_gemm<3><<<gC, 256, GEMM_SMEM>>>(at_hi, at_lo, wo_f,
        bo, x, x1, nullptr, nullptr, MT, CDIM, CDIM);
    // LN2 -> f16 split h
    ln_kernel<<<MT, 256>>>((const float4*)x1, (const float4*)g2,
                           (const float4*)be2, h_hi, h_lo);
    // mlp = relu(h @ W1 + b1) -> f16 split   (f16x2)
    mma_gemm<13><<<gF, 256, GEMM_SMEM>>>(h_hi, h_lo, w1_f,
        b1, nullptr, nullptr, ml_hi, ml_lo, MT, FF, CDIM);
    // out = x1 + mlp @ W2 + b2   (f16x2)
    mma_gemm<3><<<gC, 256, GEMM_SMEM>>>(ml_hi, ml_lo, w2_f,
        b2, x1, out, nullptr, nullptr, MT, CDIM, FF);
}

// round 16
// speedup vs baseline: 5.2444x; 1.2374x over previous
#include <cuda_runtime.h>
#include <cuda_fp16.h>
#include <cstdint>
#include <math.h>

// Problem dims
#define BB   4
#define TT   2048
#define MT   8192      // B*T
#define CDIM 1024
#define HH   16
#define DH   64
#define FF   4096
#define QKVN 3072

// ---------------- scratch (device globals; no allocation allowed) ----------
__device__ __half g_h  [MT * CDIM];
__device__ __half g_qkv[(size_t)MT * QKVN];
__device__ __half g_at [MT * CDIM];
__device__ float  g_x1 [MT * CDIM];
__device__ __half g_ml [(size_t)MT * FF];
// weights: all single f16 [K][N]
__device__ __half g_wqkv_f[CDIM * QKVN];
__device__ __half g_wo_f [CDIM * CDIM];
__device__ __half g_w1_f [CDIM * FF];
__device__ __half g_w2_f [FF * CDIM];

// ---------------- helpers ---------------------------------------------------
__device__ __forceinline__ uint32_t smem_addr32(const void* p) {
    return (uint32_t)__cvta_generic_to_shared(p);
}
__device__ __forceinline__ void cp16(void* smem, const void* g) {
    uint32_t s = smem_addr32(smem);
    asm volatile("cp.async.cg.shared.global [%0], [%1], 16;" :: "r"(s), "l"(g));
}
#define CP_COMMIT() asm volatile("cp.async.commit_group;")
#define CP_WAIT(n)  asm volatile("cp.async.wait_group %0;" :: "n"(n))

__device__ __forceinline__ float fexp2(float x) {
    float y;
    asm("ex2.approx.f32 %0, %1;" : "=f"(y) : "f"(x));
    return y;
}

// ---------------- weight prep kernels ---------------------------------------
__global__ __launch_bounds__(256) void tof16_kernel(
    const float4* __restrict__ in, __half2* __restrict__ o, int n4)
{
    const int i = blockIdx.x * 256 + threadIdx.x;
    if (i >= n4) return;
    const float4 v = in[i];
    o[i * 2]     = __floats2half2_rn(v.x, v.y);
    o[i * 2 + 1] = __floats2half2_rn(v.z, v.w);
}

// pack W[1024][1024] -> wqkv_f[1024][3072] at column offset, f16
__global__ __launch_bounds__(256) void tof16_pack_kernel(
    const float4* __restrict__ in, __half* __restrict__ o, int coloff)
{
    const int i = blockIdx.x * 256 + threadIdx.x;
    if (i >= CDIM * CDIM / 4) return;
    const int r = i >> 8;
    const int c = (i & 255) * 4;
    const float4 v = in[i];
    const size_t ofs = (size_t)r * QKVN + coloff + c;
    *(__half2*)(o + ofs)     = __floats2half2_rn(v.x, v.y);
    *(__half2*)(o + ofs + 2) = __floats2half2_rn(v.z, v.w);
}

// ---------------- LayerNorm: emits single f16 --------------------------------
__global__ __launch_bounds__(256) void ln_kernel(
    const float4* __restrict__ x, const float4* __restrict__ g,
    const float4* __restrict__ be, __half* __restrict__ o)
{
    const int r = blockIdx.x;
    const int t = threadIdx.x;
    const float4 v = x[(size_t)r * (CDIM / 4) + t];
    float s  = v.x + v.y + v.z + v.w;
    float ss = v.x * v.x + v.y * v.y + v.z * v.z + v.w * v.w;
    #pragma unroll
    for (int oo = 16; oo > 0; oo >>= 1) {
        s  += __shfl_down_sync(0xffffffffu, s,  oo);
        ss += __shfl_down_sync(0xffffffffu, ss, oo);
    }
    __shared__ float rs[8], rss[8];
    __shared__ float smu, sinv;
    const int w = t >> 5, lane = t & 31;
    if (lane == 0) { rs[w] = s; rss[w] = ss; }
    __syncthreads();
    if (t == 0) {
        float S = 0.f, SS = 0.f;
        #pragma unroll
        for (int i = 0; i < 8; i++) { S += rs[i]; SS += rss[i]; }
        const float mu  = S * (1.0f / CDIM);
        const float var = SS * (1.0f / CDIM) - mu * mu;
        smu = mu; sinv = rsqrtf(var + 1e-5f);
    }
    __syncthreads();
    const float mu = smu, inv = sinv;
    const float4 gv = g[t], bv = be[t];
    const float a0 = (v.x - mu) * inv * gv.x + bv.x;
    const float a1 = (v.y - mu) * inv * gv.y + bv.y;
    const float a2 = (v.z - mu) * inv * gv.z + bv.z;
    const float a3 = (v.w - mu) * inv * gv.w + bv.w;
    const size_t ofs = (size_t)r * CDIM + t * 4;
    *(__half2*)(o + ofs)     = __floats2half2_rn(a0, a1);
    *(__half2*)(o + ofs + 2) = __floats2half2_rn(a2, a3);
}

// ---------------- MMA macros ------------------------------------------------
#define LDMAT_X4(R0,R1,R2,R3,addr) \
    asm volatile("ldmatrix.sync.aligned.m8n8.x4.shared.b16 {%0,%1,%2,%3}, [%4];" \
        : "=r"(R0), "=r"(R1), "=r"(R2), "=r"(R3) : "r"(addr))
#define LDMAT_X4_T(R0,R1,R2,R3,addr) \
    asm volatile("ldmatrix.sync.aligned.m8n8.x4.trans.shared.b16 {%0,%1,%2,%3}, [%4];" \
        : "=r"(R0), "=r"(R1), "=r"(R2), "=r"(R3) : "r"(addr))
#define MMA16816F(C, A0,A1,A2,A3, B0,B1) \
    asm volatile("mma.sync.aligned.m16n8k16.row.col.f32.f16.f16.f32 " \
        "{%0,%1,%2,%3},{%4,%5,%6,%7},{%8,%9},{%0,%1,%2,%3};" \
        : "+f"(C[0]), "+f"(C[1]), "+f"(C[2]), "+f"(C[3]) \
        : "r"(A0), "r"(A1), "r"(A2), "r"(A3), "r"(B0), "r"(B1))

// ---------------- pipelined f16 tensor-core GEMM (3-stage) -------------------
// C = A @ B, all single f16, fp32 acc. 1 MMA per tile-pair per k16.
// EPI bit0:+bias bit1:+residual bit2:relu bit3:f16 out (bias->relu->res)
#define A_ST 5120                         // elems per A stage: 128*40
#define B_ST 4352                         // elems per B stage: 32*136
#define STG_ELEMS (A_ST + B_ST)           // 9472 elems per stage
#define GEMM_SMEM (3 * STG_ELEMS * 2)     // 56832 bytes

template <int EPI>
__global__ __launch_bounds__(256) void mma_gemm(
    const __half* __restrict__ A, const __half* __restrict__ Bw,
    const float* __restrict__ bias, const float* __restrict__ res,
    float* __restrict__ C, __half* __restrict__ Ch, int M, int N, int K)
{
    extern __shared__ char dynsmem[];
    __half* base = (__half*)dynsmem;

    const int tid  = threadIdx.x;
    const int warp = tid >> 5, lane = tid & 31;
    const int wm = (warp & 1) * 64;
    const int wn = (warp >> 1) * 32;
    const int bm = blockIdx.y * 128, bn = blockIdx.x * 128;

    float c[4][4][4];
    #pragma unroll
    for (int i = 0; i < 4; i++)
        #pragma unroll
        for (int j = 0; j < 4; j++)
            #pragma unroll
            for (int q = 0; q < 4; q++) c[i][j][q] = 0.f;

    const int a_r = tid >> 2, a_c = (tid & 3) * 8;
    const int b_r = tid >> 4, b_c = (tid & 15) * 8;

    auto load_stage = [&](int s, int k0) {
        __half* st = base + s * STG_ELEMS;
        #pragma unroll
        for (int p = 0; p < 2; p++) {
            const int row = p * 64 + a_r;
            cp16(st + row * 40 + a_c, A + (size_t)(bm + row) * K + k0 + a_c);
        }
        #pragma unroll
        for (int p = 0; p < 2; p++) {
            const int row = p * 16 + b_r;
            cp16(st + A_ST + row * 136 + b_c, Bw + (size_t)(k0 + row) * N + bn + b_c);
        }
    };

    const int nk = K / 32;
    load_stage(0, 0);
    CP_COMMIT();
    if (nk > 1) load_stage(1, 32);
    CP_COMMIT();

    for (int ki = 0; ki < nk; ki++) {
        CP_WAIT(1);
        __syncthreads();
        if (ki + 2 < nk) load_stage((ki + 2) % 3, (ki + 2) * 32);
        CP_COMMIT();

        const uint32_t st_b = smem_addr32(base + (ki % 3) * STG_ELEMS);
        const uint32_t a_b  = st_b;
        const uint32_t b_b  = st_b + A_ST * 2;

        #pragma unroll
        for (int ks = 0; ks < 32; ks += 16) {
            uint32_t af[4][4], bw[2][4];
            #pragma unroll
            for (int mt = 0; mt < 4; mt++) {
                const int r  = wm + mt * 16 + (lane & 15);
                const int cc = ks + 8 * (lane >> 4);
                LDMAT_X4(af[mt][0], af[mt][1], af[mt][2], af[mt][3],
                         a_b + (uint32_t)(r * 40 + cc) * 2);
            }
            #pragma unroll
            for (int ng = 0; ng < 2; ng++) {
                const int r  = ks + (lane & 15);
                const int cc = wn + ng * 16 + 8 * (lane >> 4);
                LDMAT_X4_T(bw[ng][0], bw[ng][1], bw[ng][2], bw[ng][3],
                           b_b + (uint32_t)(r * 136 + cc) * 2);
            }
            #pragma unroll
            for (int mt = 0; mt < 4; mt++)
                #pragma unroll
                for (int nt = 0; nt < 4; nt++) {
                    const int ng = nt >> 1, hf = (nt & 1) * 2;
                    MMA16816F(c[mt][nt], af[mt][0], af[mt][1], af[mt][2], af[mt][3],
                              bw[ng][hf], bw[ng][hf + 1]);
                }
        }
    }

    const int gg = lane >> 2;
    const int qq = (lane & 3) * 2;
    #pragma unroll
    for (int mt = 0; mt < 4; mt++) {
        #pragma unroll
        for (int nt = 0; nt < 4; nt++) {
            const int col = bn + wn + nt * 8 + qq;
            #pragma unroll
            for (int hrow = 0; hrow < 2; hrow++) {
                const int row = bm + wm + mt * 16 + gg + hrow * 8;
                float2 v;
                v.x = c[mt][nt][hrow * 2 + 0];
                v.y = c[mt][nt][hrow * 2 + 1];
                const size_t idx = (size_t)row * N + col;
                if (EPI & 1) {
                    const float2 b2 = *(const float2*)(bias + col);
                    v.x += b2.x; v.y += b2.y;
                }
                if (EPI & 4) { v.x = fmaxf(v.x, 0.f); v.y = fmaxf(v.y, 0.f); }
                if (EPI & 2) {
                    const float2 r2 = *(const float2*)(res + idx);
                    v.x += r2.x; v.y += r2.y;
                }
                if (EPI & 8) {
                    *(__half2*)(Ch + idx) = __floats2half2_rn(v.x, v.y);
                } else {
                    *(float2*)(C + idx) = v;
                }
            }
        }
    }
}

// ---------------- tensor-core flash attention (causal, f16) ------------------
// S = Q K^T; O += P V; all operands single f16, fp32 acc.
#define FST   72
#define FTILE (64 * FST)
#define FLASH_SMEM (2 * 2 * FTILE * 2)   // 36864 bytes (2 stages x [K, V])

__global__ __launch_bounds__(128) void flash_mma(
    const __half* __restrict__ G, __half* __restrict__ O_out)
{
    extern __shared__ __half fsm[];
    const int qt = 31 - blockIdx.x;
    const int h = blockIdx.y, b = blockIdx.z;
    const int tid = threadIdx.x, warp = tid >> 5, lane = tid & 31;
    const size_t qrow0 = (size_t)(b * TT + qt * 64);
    const float SC = 0.180336880f;           // 0.125 * log2(e)

    const int lr = tid >> 1;
    const int lc = (tid & 1) * 4;
    auto load_one = [&](__half* dst, const __half* src) {
        #pragma unroll
        for (int i = 0; i < 4; i++)
            cp16(dst + lr * FST + (lc + i) * 8, src + (size_t)lr * QKVN + (lc + i) * 8);
    };
    auto load_kv = [&](int s, int kt) {
        const size_t krow = (size_t)(b * TT + kt * 64);
        load_one(fsm + (s * 2 + 0) * FTILE, G + krow * QKVN + CDIM + h * DH);
        load_one(fsm + (s * 2 + 1) * FTILE, G + krow * QKVN + 2 * CDIM + h * DH);
    };

    // ---- stage Q through stage-0 buffer, ldmatrix to registers ----
    load_one(fsm, G + qrow0 * QKVN + h * DH);
    CP_COMMIT(); CP_WAIT(0);
    __syncthreads();
    uint32_t Q[4][4];
    #pragma unroll
    for (int t = 0; t < 4; t++) {
        const uint32_t off = (uint32_t)((warp * 16 + (lane & 15)) * FST
                                        + t * 16 + 8 * (lane >> 4)) * 2;
        LDMAT_X4(Q[t][0], Q[t][1], Q[t][2], Q[t][3], smem_addr32(fsm) + off);
    }
    __syncthreads();

    float O[8][4];
    #pragma unroll
    for (int i = 0; i < 8; i++)
        #pragma unroll
        for (int j = 0; j < 4; j++) O[i][j] = 0.f;
    float m0 = -1e30f, m1 = -1e30f, l0 = 0.f, l1 = 0.f;

    load_kv(0, 0);
    CP_COMMIT();

    for (int kt = 0; kt <= qt; kt++) {
        const int s = kt & 1;
        if (kt < qt) { load_kv(s ^ 1, kt + 1); CP_COMMIT(); CP_WAIT(1); }
        else         { CP_WAIT(0); }
        __syncthreads();

        const uint32_t k_b = smem_addr32(fsm + (s * 2 + 0) * FTILE);
        const uint32_t v_b = smem_addr32(fsm + (s * 2 + 1) * FTILE);

        // ---- S = Q K^T ----
        float sv[8][4];
        #pragma unroll
        for (int i = 0; i < 8; i++)
            #pragma unroll
            for (int j = 0; j < 4; j++) sv[i][j] = 0.f;

        #pragma unroll
        for (int t = 0; t < 4; t++) {
            uint32_t kf[4][4];
            #pragma unroll
            for (int g4 = 0; g4 < 4; g4++) {
                const uint32_t off = (uint32_t)((g4 * 16 + (lane & 15)) * FST
                                                + t * 16 + 8 * (lane >> 4)) * 2;
                LDMAT_X4(kf[g4][0], kf[g4][1], kf[g4][2], kf[g4][3], k_b + off);
            }
            #pragma unroll
            for (int g4 = 0; g4 < 4; g4++) {
                MMA16816F(sv[g4 * 2],     Q[t][0], Q[t][1], Q[t][2], Q[t][3], kf[g4][0], kf[g4][2]);
                MMA16816F(sv[g4 * 2 + 1], Q[t][0], Q[t][1], Q[t][2], Q[t][3], kf[g4][1], kf[g4][3]);
            }
        }

        // ---- causal mask on diagonal tile ----
        const int rl0 = warp * 16 + (lane >> 2);
        if (kt == qt) {
            #pragma unroll
            for (int nt = 0; nt < 8; nt++) {
                const int cl = nt * 8 + (lane & 3) * 2;
                if (cl     > rl0)     sv[nt][0] = -1e30f;
                if (cl + 1 > rl0)     sv[nt][1] = -1e30f;
                if (cl     > rl0 + 8) sv[nt][2] = -1e30f;
                if (cl + 1 > rl0 + 8) sv[nt][3] = -1e30f;
            }
        }

        // ---- online softmax ----
        float mx0 = -1e30f, mx1 = -1e30f;
        #pragma unroll
        for (int nt = 0; nt < 8; nt++) {
            mx0 = fmaxf(mx0, fmaxf(sv[nt][0], sv[nt][1]));
            mx1 = fmaxf(mx1, fmaxf(sv[nt][2], sv[nt][3]));
        }
        mx0 = fmaxf(mx0, __shfl_xor_sync(0xffffffffu, mx0, 1));
        mx0 = fmaxf(mx0, __shfl_xor_sync(0xffffffffu, mx0, 2));
        mx1 = fmaxf(mx1, __shfl_xor_sync(0xffffffffu, mx1, 1));
        mx1 = fmaxf(mx1, __shfl_xor_sync(0xffffffffu, mx1, 2));
        const float mn0 = fmaxf(m0, mx0), mn1 = fmaxf(m1, mx1);
        const float corr0 = fexp2((m0 - mn0) * SC);
        const float corr1 = fexp2((m1 - mn1) * SC);

        uint32_t pA[4][4];
        float ps0 = 0.f, ps1 = 0.f;
        #pragma unroll
        for (int nt = 0; nt < 8; nt++) {
            const float p0 = fexp2((sv[nt][0] - mn0) * SC);
            const float p1 = fexp2((sv[nt][1] - mn0) * SC);
            const float p2 = fexp2((sv[nt][2] - mn1) * SC);
            const float p3 = fexp2((sv[nt][3] - mn1) * SC);
            ps0 += p0 + p1; ps1 += p2 + p3;
            const __half2 h01 = __floats2half2_rn(p0, p1);
            const __half2 h23 = __floats2half2_rn(p2, p3);
            const int t = nt >> 1, o = (nt & 1) * 2;
            pA[t][o]     = *(uint32_t*)&h01;
            pA[t][o + 1] = *(uint32_t*)&h23;
        }
        ps0 += __shfl_xor_sync(0xffffffffu, ps0, 1);
        ps0 += __shfl_xor_sync(0xffffffffu, ps0, 2);
        ps1 += __shfl_xor_sync(0xffffffffu, ps1, 1);
        ps1 += __shfl_xor_sync(0xffffffffu, ps1, 2);
        l0 = l0 * corr0 + ps0;
        l1 = l1 * corr1 + ps1;
        m0 = mn0; m1 = mn1;

        #pragma unroll
        for (int dt = 0; dt < 8; dt++) {
            O[dt][0] *= corr0; O[dt][1] *= corr0;
            O[dt][2] *= corr1; O[dt][3] *= corr1;
        }

        // ---- O += P V ----
        #pragma unroll
        for (int t = 0; t < 4; t++) {
            uint32_t vf[4][4];
            #pragma unroll
            for (int g4 = 0; g4 < 4; g4++) {
                const uint32_t off = (uint32_t)((t * 16 + (lane & 15)) * FST
                                                + g4 * 16 + 8 * (lane >> 4)) * 2;
                LDMAT_X4_T(vf[g4][0], vf[g4][1], vf[g4][2], vf[g4][3], v_b + off);
            }
            #pragma unroll
            for (int g4 = 0; g4 < 4; g4++) {
                MMA16816F(O[g4 * 2],     pA[t][0], pA[t][1], pA[t][2], pA[t][3], vf[g4][0], vf[g4][1]);
                MMA16816F(O[g4 * 2 + 1], pA[t][0], pA[t][1], pA[t][2], pA[t][3], vf[g4][2], vf[g4][3]);
            }
        }
        __syncthreads();
    }

    // ---- normalize + f16 write ----
    const float inv0 = 1.f / l0, inv1 = 1.f / l1;
    const int rl0 = warp * 16 + (lane >> 2);
    #pragma unroll
    for (int dt = 0; dt < 8; dt++) {
        const int d = h * DH + dt * 8 + (lane & 3) * 2;
        const size_t i0 = (qrow0 + rl0) * CDIM + d;
        *(__half2*)(O_out + i0) = __floats2half2_rn(O[dt][0] * inv0, O[dt][1] * inv0);
        const size_t i1 = (qrow0 + rl0 + 8) * CDIM + d;
        *(__half2*)(O_out + i1) = __floats2half2_rn(O[dt][2] * inv1, O[dt][3] * inv1);
    }
}

// ---------------- launch ----------------------------------------------------
extern "C" void kernel_launch(void* const* d_in, const int* in_sizes, int n_in,
                              void* d_out, int out_size)
{
    const float* x   = (const float*)d_in[0];
    const float* Wq  = (const float*)d_in[1];
    const float* Wk  = (const float*)d_in[2];
    const float* Wv  = (const float*)d_in[3];
    const float* Wo  = (const float*)d_in[4];
    const float* bo  = (const float*)d_in[5];
    const float* W1  = (const float*)d_in[6];
    const float* b1  = (const float*)d_in[7];
    const float* W2  = (const float*)d_in[8];
    const float* b2  = (const float*)d_in[9];
    const float* g1  = (const float*)d_in[10];
    const float* be1 = (const float*)d_in[11];
    const float* g2  = (const float*)d_in[12];
    const float* be2 = (const float*)d_in[13];
    float* out = (float*)d_out;

    __half *h, *qkv, *at, *ml, *wqkv_f, *wo_f, *w1_f, *w2_f;
    float *x1;
    cudaGetSymbolAddress((void**)&h,   g_h);
    cudaGetSymbolAddress((void**)&qkv, g_qkv);
    cudaGetSymbolAddress((void**)&at,  g_at);
    cudaGetSymbolAddress((void**)&x1,  g_x1);
    cudaGetSymbolAddress((void**)&ml,  g_ml);
    cudaGetSymbolAddress((void**)&wqkv_f, g_wqkv_f);
    cudaGetSymbolAddress((void**)&wo_f, g_wo_f);
    cudaGetSymbolAddress((void**)&w1_f, g_w1_f);
    cudaGetSymbolAddress((void**)&w2_f, g_w2_f);

    cudaFuncSetAttribute((const void*)mma_gemm<3>,
        cudaFuncAttributeMaxDynamicSharedMemorySize, GEMM_SMEM);
    cudaFuncSetAttribute((const void*)mma_gemm<8>,
        cudaFuncAttributeMaxDynamicSharedMemorySize, GEMM_SMEM);
    cudaFuncSetAttribute((const void*)mma_gemm<13>,
        cudaFuncAttributeMaxDynamicSharedMemorySize, GEMM_SMEM);
    cudaFuncSetAttribute((const void*)flash_mma,
        cudaFuncAttributeMaxDynamicSharedMemorySize, FLASH_SMEM);

    // ---- weight prep (all single f16) ----
    const int nW = CDIM * CDIM / 4;
    tof16_pack_kernel<<<(nW + 255) / 256, 256>>>((const float4*)Wq, wqkv_f, 0);
    tof16_pack_kernel<<<(nW + 255) / 256, 256>>>((const float4*)Wk, wqkv_f, 1024);
    tof16_pack_kernel<<<(nW + 255) / 256, 256>>>((const float4*)Wv, wqkv_f, 2048);
    tof16_kernel<<<(nW + 255) / 256, 256>>>((const float4*)Wo, (__half2*)wo_f, nW);
    const int nW1 = CDIM * FF / 4;
    tof16_kernel<<<(nW1 + 255) / 256, 256>>>((const float4*)W1, (__half2*)w1_f, nW1);
    tof16_kernel<<<(nW1 + 255) / 256, 256>>>((const float4*)W2, (__half2*)w2_f, nW1);

    const dim3 gQKV(QKVN / 128, MT / 128);   // (24, 64)
    const dim3 gC(CDIM / 128, MT / 128);     // (8, 64)
    const dim3 gF(FF / 128, MT / 128);       // (32, 64)

    // LN1 -> f16 h
    ln_kernel<<<MT, 256>>>((const float4*)x, (const float4*)g1,
                           (const float4*)be1, h);
    // fused QKV projection -> f16 qkv
    mma_gemm<8><<<gQKV, 256, GEMM_SMEM>>>(h, wqkv_f,
        nullptr, nullptr, nullptr, qkv, MT, QKVN, CDIM);
    // tensor-core causal flash attention -> f16 attn
    flash_mma<<<dim3(TT / 64, HH, BB), 128, FLASH_SMEM>>>(qkv, at);
    // x1 = x + attn @ Wo + bo
    mma_gemm<3><<<gC, 256, GEMM_SMEM>>>(at, wo_f,
        bo, x, x1, nullptr, MT, CDIM, CDIM);
    // LN2 -> f16 h
    ln_kernel<<<MT, 256>>>((const float4*)x1, (const float4*)g2,
                           (const float4*)be2, h);
    // mlp = relu(h @ W1 + b1) -> f16 ml
    mma_gemm<13><<<gF, 256, GEMM_SMEM>>>(h, w1_f,
        b1, nullptr, nullptr, ml, MT, FF, CDIM);
    // out = x1 + mlp @ W2 + b2
    mma_gemm<3><<<gC, 256, GEMM_SMEM>>>(ml, w2_f,
        b2, x1, out, nullptr, MT, CDIM, FF);
}

// round 17
// speedup vs baseline: 7.9384x; 1.5137x over previous
#include <cuda_runtime.h>
#include <cuda_fp16.h>
#include <cstdint>
#include <math.h>

// Problem dims
#define BB   4
#define TT   2048
#define MT   8192      // B*T
#define CDIM 1024
#define HH   16
#define DH   64
#define FF   4096
#define QKVN 3072

// ---------------- scratch (device globals; no allocation allowed) ----------
__device__ __half g_h  [MT * CDIM];
__device__ __half g_qkv[(size_t)MT * QKVN];
__device__ __half g_at [MT * CDIM];
__device__ float  g_x1 [MT * CDIM];
__device__ __half g_ml [(size_t)MT * FF];
// weights: all single f16 [K][N]
__device__ __half g_wqkv_f[CDIM * QKVN];
__device__ __half g_wo_f [CDIM * CDIM];
__device__ __half g_w1_f [CDIM * FF];
__device__ __half g_w2_f [FF * CDIM];

// ---------------- helpers ---------------------------------------------------
__device__ __forceinline__ uint32_t smem_addr32(const void* p) {
    return (uint32_t)__cvta_generic_to_shared(p);
}
__device__ __forceinline__ void cp16(void* smem, const void* g) {
    uint32_t s = smem_addr32(smem);
    asm volatile("cp.async.cg.shared.global [%0], [%1], 16;" :: "r"(s), "l"(g));
}
#define CP_COMMIT() asm volatile("cp.async.commit_group;")
#define CP_WAIT(n)  asm volatile("cp.async.wait_group %0;" :: "n"(n))

__device__ __forceinline__ float fexp2(float x) {
    float y;
    asm("ex2.approx.f32 %0, %1;" : "=f"(y) : "f"(x));
    return y;
}

// ---------------- weight prep kernels ---------------------------------------
__global__ __launch_bounds__(256) void tof16_kernel(
    const float4* __restrict__ in, __half2* __restrict__ o, int n4)
{
    const int i = blockIdx.x * 256 + threadIdx.x;
    if (i >= n4) return;
    const float4 v = in[i];
    o[i * 2]     = __floats2half2_rn(v.x, v.y);
    o[i * 2 + 1] = __floats2half2_rn(v.z, v.w);
}

// pack W[1024][1024] -> wqkv_f[1024][3072] at column offset, f16
__global__ __launch_bounds__(256) void tof16_pack_kernel(
    const float4* __restrict__ in, __half* __restrict__ o, int coloff)
{
    const int i = blockIdx.x * 256 + threadIdx.x;
    if (i >= CDIM * CDIM / 4) return;
    const int r = i >> 8;
    const int c = (i & 255) * 4;
    const float4 v = in[i];
    const size_t ofs = (size_t)r * QKVN + coloff + c;
    *(__half2*)(o + ofs)     = __floats2half2_rn(v.x, v.y);
    *(__half2*)(o + ofs + 2) = __floats2half2_rn(v.z, v.w);
}

// ---------------- LayerNorm: emits single f16 --------------------------------
__global__ __launch_bounds__(256) void ln_kernel(
    const float4* __restrict__ x, const float4* __restrict__ g,
    const float4* __restrict__ be, __half* __restrict__ o)
{
    const int r = blockIdx.x;
    const int t = threadIdx.x;
    const float4 v = x[(size_t)r * (CDIM / 4) + t];
    float s  = v.x + v.y + v.z + v.w;
    float ss = v.x * v.x + v.y * v.y + v.z * v.z + v.w * v.w;
    #pragma unroll
    for (int oo = 16; oo > 0; oo >>= 1) {
        s  += __shfl_down_sync(0xffffffffu, s,  oo);
        ss += __shfl_down_sync(0xffffffffu, ss, oo);
    }
    __shared__ float rs[8], rss[8];
    __shared__ float smu, sinv;
    const int w = t >> 5, lane = t & 31;
    if (lane == 0) { rs[w] = s; rss[w] = ss; }
    __syncthreads();
    if (t == 0) {
        float S = 0.f, SS = 0.f;
        #pragma unroll
        for (int i = 0; i < 8; i++) { S += rs[i]; SS += rss[i]; }
        const float mu  = S * (1.0f / CDIM);
        const float var = SS * (1.0f / CDIM) - mu * mu;
        smu = mu; sinv = rsqrtf(var + 1e-5f);
    }
    __syncthreads();
    const float mu = smu, inv = sinv;
    const float4 gv = g[t], bv = be[t];
    const float a0 = (v.x - mu) * inv * gv.x + bv.x;
    const float a1 = (v.y - mu) * inv * gv.y + bv.y;
    const float a2 = (v.z - mu) * inv * gv.z + bv.z;
    const float a3 = (v.w - mu) * inv * gv.w + bv.w;
    const size_t ofs = (size_t)r * CDIM + t * 4;
    *(__half2*)(o + ofs)     = __floats2half2_rn(a0, a1);
    *(__half2*)(o + ofs + 2) = __floats2half2_rn(a2, a3);
}

// ---------------- MMA macros ------------------------------------------------
#define LDMAT_X4(R0,R1,R2,R3,addr) \
    asm volatile("ldmatrix.sync.aligned.m8n8.x4.shared.b16 {%0,%1,%2,%3}, [%4];" \
        : "=r"(R0), "=r"(R1), "=r"(R2), "=r"(R3) : "r"(addr))
#define LDMAT_X4_T(R0,R1,R2,R3,addr) \
    asm volatile("ldmatrix.sync.aligned.m8n8.x4.trans.shared.b16 {%0,%1,%2,%3}, [%4];" \
        : "=r"(R0), "=r"(R1), "=r"(R2), "=r"(R3) : "r"(addr))
#define MMA16816F(C, A0,A1,A2,A3, B0,B1) \
    asm volatile("mma.sync.aligned.m16n8k16.row.col.f32.f16.f16.f32 " \
        "{%0,%1,%2,%3},{%4,%5,%6,%7},{%8,%9},{%0,%1,%2,%3};" \
        : "+f"(C[0]), "+f"(C[1]), "+f"(C[2]), "+f"(C[3]) \
        : "r"(A0), "r"(A1), "r"(A2), "r"(A3), "r"(B0), "r"(B1))

// ---------------- pipelined f16 tensor-core GEMM (3-stage) -------------------
// Block tile 128x256, warp tile 64x64 (8 warps, 2x4). 32 MMA : 8 LDSM per k16.
// EPI bit0:+bias bit1:+residual bit2:relu bit3:f16 out (bias->relu->res)
#define A_ST 5120                         // elems per A stage: 128*40
#define B_ST 8448                         // elems per B stage: 32*264
#define STG_ELEMS (A_ST + B_ST)           // 13568 elems per stage
#define GEMM_SMEM (3 * STG_ELEMS * 2)     // 81408 bytes

template <int EPI>
__global__ __launch_bounds__(256) void mma_gemm(
    const __half* __restrict__ A, const __half* __restrict__ Bw,
    const float* __restrict__ bias, const float* __restrict__ res,
    float* __restrict__ C, __half* __restrict__ Ch, int M, int N, int K)
{
    extern __shared__ char dynsmem[];
    __half* base = (__half*)dynsmem;

    const int tid  = threadIdx.x;
    const int warp = tid >> 5, lane = tid & 31;
    const int wm = (warp & 1) * 64;
    const int wn = (warp >> 1) * 64;
    const int bm = blockIdx.y * 128, bn = blockIdx.x * 256;

    float c[4][8][4];
    #pragma unroll
    for (int i = 0; i < 4; i++)
        #pragma unroll
        for (int j = 0; j < 8; j++)
            #pragma unroll
            for (int q = 0; q < 4; q++) c[i][j][q] = 0.f;

    const int a_r = tid >> 2, a_c = (tid & 3) * 8;     // A: 64 rows/pass, 2 passes
    const int b_r = tid >> 5, b_c = (tid & 31) * 8;    // B: 8 rows/pass, 4 passes

    auto load_stage = [&](int s, int k0) {
        __half* st = base + s * STG_ELEMS;
        #pragma unroll
        for (int p = 0; p < 2; p++) {
            const int row = p * 64 + a_r;
            cp16(st + row * 40 + a_c, A + (size_t)(bm + row) * K + k0 + a_c);
        }
        #pragma unroll
        for (int p = 0; p < 4; p++) {
            const int row = p * 8 + b_r;
            cp16(st + A_ST + row * 264 + b_c, Bw + (size_t)(k0 + row) * N + bn + b_c);
        }
    };

    const int nk = K / 32;
    load_stage(0, 0);
    CP_COMMIT();
    if (nk > 1) load_stage(1, 32);
    CP_COMMIT();

    for (int ki = 0; ki < nk; ki++) {
        CP_WAIT(1);
        __syncthreads();
        if (ki + 2 < nk) load_stage((ki + 2) % 3, (ki + 2) * 32);
        CP_COMMIT();

        const uint32_t st_b = smem_addr32(base + (ki % 3) * STG_ELEMS);
        const uint32_t a_b  = st_b;
        const uint32_t b_b  = st_b + A_ST * 2;

        #pragma unroll
        for (int ks = 0; ks < 32; ks += 16) {
            uint32_t af[4][4], bw[4][4];
            #pragma unroll
            for (int mt = 0; mt < 4; mt++) {
                const int r  = wm + mt * 16 + (lane & 15);
                const int cc = ks + 8 * (lane >> 4);
                LDMAT_X4(af[mt][0], af[mt][1], af[mt][2], af[mt][3],
                         a_b + (uint32_t)(r * 40 + cc) * 2);
            }
            #pragma unroll
            for (int ng = 0; ng < 4; ng++) {
                const int r  = ks + (lane & 15);
                const int cc = wn + ng * 16 + 8 * (lane >> 4);
                LDMAT_X4_T(bw[ng][0], bw[ng][1], bw[ng][2], bw[ng][3],
                           b_b + (uint32_t)(r * 264 + cc) * 2);
            }
            #pragma unroll
            for (int mt = 0; mt < 4; mt++)
                #pragma unroll
                for (int nt = 0; nt < 8; nt++) {
                    const int ng = nt >> 1, hf = (nt & 1) * 2;
                    MMA16816F(c[mt][nt], af[mt][0], af[mt][1], af[mt][2], af[mt][3],
                              bw[ng][hf], bw[ng][hf + 1]);
                }
        }
    }

    const int gg = lane >> 2;
    const int qq = (lane & 3) * 2;
    #pragma unroll
    for (int mt = 0; mt < 4; mt++) {
        #pragma unroll
        for (int nt = 0; nt < 8; nt++) {
            const int col = bn + wn + nt * 8 + qq;
            #pragma unroll
            for (int hrow = 0; hrow < 2; hrow++) {
                const int row = bm + wm + mt * 16 + gg + hrow * 8;
                float2 v;
                v.x = c[mt][nt][hrow * 2 + 0];
                v.y = c[mt][nt][hrow * 2 + 1];
                const size_t idx = (size_t)row * N + col;
                if (EPI & 1) {
                    const float2 b2 = *(const float2*)(bias + col);
                    v.x += b2.x; v.y += b2.y;
                }
                if (EPI & 4) { v.x = fmaxf(v.x, 0.f); v.y = fmaxf(v.y, 0.f); }
                if (EPI & 2) {
                    const float2 r2 = *(const float2*)(res + idx);
                    v.x += r2.x; v.y += r2.y;
                }
                if (EPI & 8) {
                    *(__half2*)(Ch + idx) = __floats2half2_rn(v.x, v.y);
                } else {
                    *(float2*)(C + idx) = v;
                }
            }
        }
    }
}

// ---------------- tensor-core flash attention (causal, f16) ------------------
// S = Q K^T; O += P V; all operands single f16, fp32 acc.
#define FST   72
#define FTILE (64 * FST)
#define FLASH_SMEM (2 * 2 * FTILE * 2)   // 36864 bytes (2 stages x [K, V])

__global__ __launch_bounds__(128) void flash_mma(
    const __half* __restrict__ G, __half* __restrict__ O_out)
{
    extern __shared__ __half fsm[];
    const int qt = 31 - blockIdx.x;
    const int h = blockIdx.y, b = blockIdx.z;
    const int tid = threadIdx.x, warp = tid >> 5, lane = tid & 31;
    const size_t qrow0 = (size_t)(b * TT + qt * 64);
    const float SC = 0.180336880f;           // 0.125 * log2(e)

    const int lr = tid >> 1;
    const int lc = (tid & 1) * 4;
    auto load_one = [&](__half* dst, const __half* src) {
        #pragma unroll
        for (int i = 0; i < 4; i++)
            cp16(dst + lr * FST + (lc + i) * 8, src + (size_t)lr * QKVN + (lc + i) * 8);
    };
    auto load_kv = [&](int s, int kt) {
        const size_t krow = (size_t)(b * TT + kt * 64);
        load_one(fsm + (s * 2 + 0) * FTILE, G + krow * QKVN + CDIM + h * DH);
        load_one(fsm + (s * 2 + 1) * FTILE, G + krow * QKVN + 2 * CDIM + h * DH);
    };

    // ---- stage Q through stage-0 buffer, ldmatrix to registers ----
    load_one(fsm, G + qrow0 * QKVN + h * DH);
    CP_COMMIT(); CP_WAIT(0);
    __syncthreads();
    uint32_t Q[4][4];
    #pragma unroll
    for (int t = 0; t < 4; t++) {
        const uint32_t off = (uint32_t)((warp * 16 + (lane & 15)) * FST
                                        + t * 16 + 8 * (lane >> 4)) * 2;
        LDMAT_X4(Q[t][0], Q[t][1], Q[t][2], Q[t][3], smem_addr32(fsm) + off);
    }
    __syncthreads();

    float O[8][4];
    #pragma unroll
    for (int i = 0; i < 8; i++)
        #pragma unroll
        for (int j = 0; j < 4; j++) O[i][j] = 0.f;
    float m0 = -1e30f, m1 = -1e30f, l0 = 0.f, l1 = 0.f;

    load_kv(0, 0);
    CP_COMMIT();

    for (int kt = 0; kt <= qt; kt++) {
        const int s = kt & 1;
        if (kt < qt) { load_kv(s ^ 1, kt + 1); CP_COMMIT(); CP_WAIT(1); }
        else         { CP_WAIT(0); }
        __syncthreads();

        const uint32_t k_b = smem_addr32(fsm + (s * 2 + 0) * FTILE);
        const uint32_t v_b = smem_addr32(fsm + (s * 2 + 1) * FTILE);

        // ---- S = Q K^T ----
        float sv[8][4];
        #pragma unroll
        for (int i = 0; i < 8; i++)
            #pragma unroll
            for (int j = 0; j < 4; j++) sv[i][j] = 0.f;

        #pragma unroll
        for (int t = 0; t < 4; t++) {
            uint32_t kf[4][4];
            #pragma unroll
            for (int g4 = 0; g4 < 4; g4++) {
                const uint32_t off = (uint32_t)((g4 * 16 + (lane & 15)) * FST
                                                + t * 16 + 8 * (lane >> 4)) * 2;
                LDMAT_X4(kf[g4][0], kf[g4][1], kf[g4][2], kf[g4][3], k_b + off);
            }
            #pragma unroll
            for (int g4 = 0; g4 < 4; g4++) {
                MMA16816F(sv[g4 * 2],     Q[t][0], Q[t][1], Q[t][2], Q[t][3], kf[g4][0], kf[g4][2]);
                MMA16816F(sv[g4 * 2 + 1], Q[t][0], Q[t][1], Q[t][2], Q[t][3], kf[g4][1], kf[g4][3]);
            }
        }

        // ---- causal mask on diagonal tile ----
        const int rl0 = warp * 16 + (lane >> 2);
        if (kt == qt) {
            #pragma unroll
            for (int nt = 0; nt < 8; nt++) {
                const int cl = nt * 8 + (lane & 3) * 2;
                if (cl     > rl0)     sv[nt][0] = -1e30f;
                if (cl + 1 > rl0)     sv[nt][1] = -1e30f;
                if (cl     > rl0 + 8) sv[nt][2] = -1e30f;
                if (cl + 1 > rl0 + 8) sv[nt][3] = -1e30f;
            }
        }

        // ---- online softmax ----
        float mx0 = -1e30f, mx1 = -1e30f;
        #pragma unroll
        for (int nt = 0; nt < 8; nt++) {
            mx0 = fmaxf(mx0, fmaxf(sv[nt][0], sv[nt][1]));
            mx1 = fmaxf(mx1, fmaxf(sv[nt][2], sv[nt][3]));
        }
        mx0 = fmaxf(mx0, __shfl_xor_sync(0xffffffffu, mx0, 1));
        mx0 = fmaxf(mx0, __shfl_xor_sync(0xffffffffu, mx0, 2));
        mx1 = fmaxf(mx1, __shfl_xor_sync(0xffffffffu, mx1, 1));
        mx1 = fmaxf(mx1, __shfl_xor_sync(0xffffffffu, mx1, 2));
        const float mn0 = fmaxf(m0, mx0), mn1 = fmaxf(m1, mx1);
        const float corr0 = fexp2((m0 - mn0) * SC);
        const float corr1 = fexp2((m1 - mn1) * SC);

        uint32_t pA[4][4];
        float ps0 = 0.f, ps1 = 0.f;
        #pragma unroll
        for (int nt = 0; nt < 8; nt++) {
            const float p0 = fexp2((sv[nt][0] - mn0) * SC);
            const float p1 = fexp2((sv[nt][1] - mn0) * SC);
            const float p2 = fexp2((sv[nt][2] - mn1) * SC);
            const float p3 = fexp2((sv[nt][3] - mn1) * SC);
            ps0 += p0 + p1; ps1 += p2 + p3;
            const __half2 h01 = __floats2half2_rn(p0, p1);
            const __half2 h23 = __floats2half2_rn(p2, p3);
            const int t = nt >> 1, o = (nt & 1) * 2;
            pA[t][o]     = *(uint32_t*)&h01;
            pA[t][o + 1] = *(uint32_t*)&h23;
        }
        ps0 += __shfl_xor_sync(0xffffffffu, ps0, 1);
        ps0 += __shfl_xor_sync(0xffffffffu, ps0, 2);
        ps1 += __shfl_xor_sync(0xffffffffu, ps1, 1);
        ps1 += __shfl_xor_sync(0xffffffffu, ps1, 2);
        l0 = l0 * corr0 + ps0;
        l1 = l1 * corr1 + ps1;
        m0 = mn0; m1 = mn1;

        #pragma unroll
        for (int dt = 0; dt < 8; dt++) {
            O[dt][0] *= corr0; O[dt][1] *= corr0;
            O[dt][2] *= corr1; O[dt][3] *= corr1;
        }

        // ---- O += P V ----
        #pragma unroll
        for (int t = 0; t < 4; t++) {
            uint32_t vf[4][4];
            #pragma unroll
            for (int g4 = 0; g4 < 4; g4++) {
                const uint32_t off = (uint32_t)((t * 16 + (lane & 15)) * FST
                                                + g4 * 16 + 8 * (lane >> 4)) * 2;
                LDMAT_X4_T(vf[g4][0], vf[g4][1], vf[g4][2], vf[g4][3], v_b + off);
            }
            #pragma unroll
            for (int g4 = 0; g4 < 4; g4++) {
                MMA16816F(O[g4 * 2],     pA[t][0], pA[t][1], pA[t][2], pA[t][3], vf[g4][0], vf[g4][1]);
                MMA16816F(O[g4 * 2 + 1], pA[t][0], pA[t][1], pA[t][2], pA[t][3], vf[g4][2], vf[g4][3]);
            }
        }
        __syncthreads();
    }

    // ---- normalize + f16 write ----
    const float inv0 = 1.f / l0, inv1 = 1.f / l1;
    const int rl0 = warp * 16 + (lane >> 2);
    #pragma unroll
    for (int dt = 0; dt < 8; dt++) {
        const int d = h * DH + dt * 8 + (lane & 3) * 2;
        const size_t i0 = (qrow0 + rl0) * CDIM + d;
        *(__half2*)(O_out + i0) = __floats2half2_rn(O[dt][0] * inv0, O[dt][1] * inv0);
        const size_t i1 = (qrow0 + rl0 + 8) * CDIM + d;
        *(__half2*)(O_out + i1) = __floats2half2_rn(O[dt][2] * inv1, O[dt][3] * inv1);
    }
}

// ---------------- launch ----------------------------------------------------
extern "C" void kernel_launch(void* const* d_in, const int* in_sizes, int n_in,
                              void* d_out, int out_size)
{
    const float* x   = (const float*)d_in[0];
    const float* Wq  = (const float*)d_in[1];
    const float* Wk  = (const float*)d_in[2];
    const float* Wv  = (const float*)d_in[3];
    const float* Wo  = (const float*)d_in[4];
    const float* bo  = (const float*)d_in[5];
    const float* W1  = (const float*)d_in[6];
    const float* b1  = (const float*)d_in[7];
    const float* W2  = (const float*)d_in[8];
    const float* b2  = (const float*)d_in[9];
    const float* g1  = (const float*)d_in[10];
    const float* be1 = (const float*)d_in[11];
    const float* g2  = (const float*)d_in[12];
    const float* be2 = (const float*)d_in[13];
    float* out = (float*)d_out;

    __half *h, *qkv, *at, *ml, *wqkv_f, *wo_f, *w1_f, *w2_f;
    float *x1;
    cudaGetSymbolAddress((void**)&h,   g_h);
    cudaGetSymbolAddress((void**)&qkv, g_qkv);
    cudaGetSymbolAddress((void**)&at,  g_at);
    cudaGetSymbolAddress((void**)&x1,  g_x1);
    cudaGetSymbolAddress((void**)&ml,  g_ml);
    cudaGetSymbolAddress((void**)&wqkv_f, g_wqkv_f);
    cudaGetSymbolAddress((void**)&wo_f, g_wo_f);
    cudaGetSymbolAddress((void**)&w1_f, g_w1_f);
    cudaGetSymbolAddress((void**)&w2_f, g_w2_f);

    cudaFuncSetAttribute((const void*)mma_gemm<3>,
        cudaFuncAttributeMaxDynamicSharedMemorySize, GEMM_SMEM);
    cudaFuncSetAttribute((const void*)mma_gemm<8>,
        cudaFuncAttributeMaxDynamicSharedMemorySize, GEMM_SMEM);
    cudaFuncSetAttribute((const void*)mma_gemm<13>,
        cudaFuncAttributeMaxDynamicSharedMemorySize, GEMM_SMEM);
    cudaFuncSetAttribute((const void*)flash_mma,
        cudaFuncAttributeMaxDynamicSharedMemorySize, FLASH_SMEM);

    // ---- weight prep (all single f16) ----
    const int nW = CDIM * CDIM / 4;
    tof16_pack_kernel<<<(nW + 255) / 256, 256>>>((const float4*)Wq, wqkv_f, 0);
    tof16_pack_kernel<<<(nW + 255) / 256, 256>>>((const float4*)Wk, wqkv_f, 1024);
    tof16_pack_kernel<<<(nW + 255) / 256, 256>>>((const float4*)Wv, wqkv_f, 2048);
    tof16_kernel<<<(nW + 255) / 256, 256>>>((const float4*)Wo, (__half2*)wo_f, nW);
    const int nW1 = CDIM * FF / 4;
    tof16_kernel<<<(nW1 + 255) / 256, 256>>>((const float4*)W1, (__half2*)w1_f, nW1);
    tof16_kernel<<<(nW1 + 255) / 256, 256>>>((const float4*)W2, (__half2*)w2_f, nW1);

    const dim3 gQKV(QKVN / 256, MT / 128);   // (12, 64)
    const dim3 gC(CDIM / 256, MT / 128);     // (4, 64)
    const dim3 gF(FF / 256, MT / 128);       // (16, 64)

    // LN1 -> f16 h
    ln_kernel<<<MT, 256>>>((const float4*)x, (const float4*)g1,
                           (const float4*)be1, h);
    // fused QKV projection -> f16 qkv
    mma_gemm<8><<<gQKV, 256, GEMM_SMEM>>>(h, wqkv_f,
        nullptr, nullptr, nullptr, qkv, MT, QKVN, CDIM);
    // tensor-core causal flash attention -> f16 attn
    flash_mma<<<dim3(TT / 64, HH, BB), 128, FLASH_SMEM>>>(qkv, at);
    // x1 = x + attn @ Wo + bo
    mma_gemm<3><<<gC, 256, GEMM_SMEM>>>(at, wo_f,
        bo, x, x1, nullptr, MT, CDIM, CDIM);
    // LN2 -> f16 h
    ln_kernel<<<MT, 256>>>((const float4*)x1, (const float4*)g2,
                           (const float4*)be2, h);
    // mlp = relu(h @ W1 + b1) -> f16 ml
    mma_gemm<13><<<gF, 256, GEMM_SMEM>>>(h, w1_f,
        b1, nullptr, nullptr, ml, MT, FF, CDIM);
    // out = x1 + mlp @ W2 + b2
    mma_gemm<3><<<gC, 256, GEMM_SMEM>>>(ml, w2_f,
        b2, x1, out, nullptr, MT, CDIM, FF);
}